// round 9
// baseline (speedup 1.0000x reference)
#include <cuda_runtime.h>
#include <cuda_bf16.h>
#include <math.h>
#include <stdint.h>

#define NN 4096
#define DD 64
#define OMA 0.8f   // 1 - alpha(0.2)
#define NH 4

// ---------------- scratch (device globals; allocation-free) ----------------
__device__ __nv_bfloat16 g_Whi[(size_t)NH * NN * NN];
__device__ __nv_bfloat16 g_Wlo[(size_t)NH * NN * NN];
__device__ __nv_bfloat16 g_ahi[(size_t)NN * NN];
__device__ __nv_bfloat16 g_alo[(size_t)NN * NN];
__device__ __nv_bfloat16 g_xhi[(size_t)NN * NN];
__device__ __nv_bfloat16 g_xlo[(size_t)NN * NN];
__device__ __nv_bfloat16 g_bhi[NH * 64 * NN];
__device__ __nv_bfloat16 g_blo[NH * 64 * NN];
__device__ float g_cat[NN * NH * DD];
__device__ float g_x1[NN * DD];
__device__ float g_tb[NN * DD];
__device__ float g_h1[NN * DD];
__device__ float g_part[(size_t)32 * NN * DD];   // up to 32 split slabs
__device__ float g_f1[NH * NN], g_f2[NH * NN], g_f1s[NH * NN], g_rinv[NH * NN];
__device__ int   g_pi[NH * NN];
__device__ float2 g_pk[NH * NN];

// ================= portable (sm_80+) PTX helpers =================
__device__ __forceinline__ uint32_t smem_u32(const void* p) {
    uint32_t a;
    asm("{ .reg .u64 t; cvta.to.shared.u64 t, %1; cvt.u32.u64 %0, t; }"
        : "=r"(a) : "l"(p));
    return a;
}

#define CP16(dst, src) \
    asm volatile("cp.async.cg.shared.global [%0], [%1], 16;" :: "r"(dst), "l"(src))
#define CP_COMMIT() asm volatile("cp.async.commit_group;" ::: "memory")
#define CP_WAIT0() asm volatile("cp.async.wait_group 0;" ::: "memory")
#define CP_WAIT1() asm volatile("cp.async.wait_group 1;" ::: "memory")

__device__ __forceinline__ void ldm4(uint32_t* r, uint32_t addr) {
    asm volatile("ldmatrix.sync.aligned.m8n8.x4.shared.b16 {%0,%1,%2,%3}, [%4];"
        : "=r"(r[0]), "=r"(r[1]), "=r"(r[2]), "=r"(r[3]) : "r"(addr));
}

__device__ __forceinline__ void mma16816(float* d, const uint32_t* a, const uint32_t* b) {
    asm volatile("mma.sync.aligned.m16n8k16.row.col.f32.bf16.bf16.f32 "
        "{%0,%1,%2,%3}, {%4,%5,%6,%7}, {%8,%9}, {%0,%1,%2,%3};"
        : "+f"(d[0]), "+f"(d[1]), "+f"(d[2]), "+f"(d[3])
        : "r"(a[0]), "r"(a[1]), "r"(a[2]), "r"(a[3]), "r"(b[0]), "r"(b[1]));
}

__device__ __forceinline__ uint32_t swz(uint32_t bo) { return bo ^ ((bo >> 3) & 0x70); }

// ================= tensor-core big matmul (mma.sync bf16 pair-split) =================
#define O_AH 0
#define O_AL 16384
#define O_BH 32768
#define O_BL 40960
#define STG  49152
#define MMSMEM (2 * STG)

__global__ void __launch_bounds__(256, 2) mm_mma(
        const __nv_bfloat16* __restrict__ Ahi, const __nv_bfloat16* __restrict__ Alo,
        const __nv_bfloat16* __restrict__ Bhi, const __nv_bfloat16* __restrict__ Blo,
        float* __restrict__ part, size_t aStr, size_t bStr, int m0Off) {
    extern __shared__ char smem[];
    uint32_t sb = smem_u32(smem);
    int tid = threadIdx.x, wid = tid >> 5, lane = tid & 31;
    int m0 = (blockIdx.x + m0Off) * 128;
    int klen = NN / gridDim.y;
    int kbeg = blockIdx.y * klen;
    int nch = klen / 64;
    int wm = wid >> 1, wn = wid & 1;
    size_t zo = (size_t)blockIdx.z;
    const __nv_bfloat16* AhiZ = Ahi + zo * aStr;
    const __nv_bfloat16* AloZ = Alo + zo * aStr;
    const __nv_bfloat16* BhiZ = Bhi + zo * bStr;
    const __nv_bfloat16* BloZ = Blo + zo * bStr;

    auto load_chunk = [&](int ch) {
        uint32_t base = sb + (uint32_t)(ch & 1) * STG;
        int kc = kbeg + ch * 64;
        int r = tid >> 3, c = tid & 7;
        uint32_t sw = swz((uint32_t)(r * 128 + c * 16));
        #pragma unroll
        for (int pl = 0; pl < 2; pl++) {
            const __nv_bfloat16* src = pl ? AloZ : AhiZ;
            uint32_t off = pl ? O_AL : O_AH;
            #pragma unroll
            for (int i = 0; i < 4; i++)
                CP16(base + off + sw + (uint32_t)i * 4096,
                     src + (size_t)(m0 + r + i * 32) * NN + kc + c * 8);
        }
        #pragma unroll
        for (int pl = 0; pl < 2; pl++) {
            const __nv_bfloat16* src = pl ? BloZ : BhiZ;
            uint32_t off = pl ? O_BL : O_BH;
            #pragma unroll
            for (int i = 0; i < 2; i++)
                CP16(base + off + sw + (uint32_t)i * 4096,
                     src + (size_t)(r + i * 32) * NN + kc + c * 8);
        }
        CP_COMMIT();
    };

    float acc[2][4][4] = {};
    load_chunk(0);
    for (int ch = 0; ch < nch; ch++) {
        if (ch + 1 < nch) { load_chunk(ch + 1); CP_WAIT1(); }
        else               { CP_WAIT0(); }
        __syncthreads();
        uint32_t base = sb + (uint32_t)(ch & 1) * STG;
        #pragma unroll
        for (int ks = 0; ks < 4; ks++) {
            uint32_t ah[2][4], al[2][4], bh[8], bl[8];
            #pragma unroll
            for (int mt = 0; mt < 2; mt++) {
                int row = wm * 32 + mt * 16 + (lane & 7) + ((lane >> 3) & 1) * 8;
                int koff = ks * 32 + (lane >> 4) * 16;
                uint32_t sw = swz((uint32_t)(row * 128 + koff));
                ldm4(ah[mt], base + O_AH + sw);
                ldm4(al[mt], base + O_AL + sw);
            }
            #pragma unroll
            for (int half = 0; half < 2; half++) {
                int g = lane >> 3;
                int n = wn * 32 + half * 16 + (g >> 1) * 8 + (lane & 7);
                int koff = ks * 32 + (g & 1) * 16;
                uint32_t sw = swz((uint32_t)(n * 128 + koff));
                ldm4(bh + half * 4, base + O_BH + sw);
                ldm4(bl + half * 4, base + O_BL + sw);
            }
            #pragma unroll
            for (int mt = 0; mt < 2; mt++)
                #pragma unroll
                for (int nt = 0; nt < 4; nt++) {
                    mma16816(acc[mt][nt], ah[mt], bh + nt * 2);
                    mma16816(acc[mt][nt], ah[mt], bl + nt * 2);
                    mma16816(acc[mt][nt], al[mt], bh + nt * 2);
                }
        }
        __syncthreads();
    }

    float* cp = part + ((size_t)blockIdx.z * gridDim.y + blockIdx.y) * (NN * 64);
    #pragma unroll
    for (int mt = 0; mt < 2; mt++)
        #pragma unroll
        for (int nt = 0; nt < 4; nt++) {
            int row = m0 + wm * 32 + mt * 16 + (lane >> 2);
            int col = wn * 32 + nt * 8 + (lane & 3) * 2;
            *(float2*)&cp[(size_t)row * 64 + col] =
                make_float2(acc[mt][nt][0], acc[mt][nt][1]);
            *(float2*)&cp[(size_t)(row + 8) * 64 + col] =
                make_float2(acc[mt][nt][2], acc[mt][nt][3]);
        }
}

// ---------------- fp32 -> bf16 pair planes (big matrices) ----------------
__global__ void cpair(const float4* __restrict__ in, __nv_bfloat16* __restrict__ hi,
                      __nv_bfloat16* __restrict__ lo) {
    size_t n4 = (size_t)NN * NN / 4;
    for (size_t i = (size_t)blockIdx.x * 256 + threadIdx.x; i < n4;
         i += (size_t)gridDim.x * 256) {
        float4 v = in[i];
        __nv_bfloat16 h0 = __float2bfloat16_rn(v.x);
        __nv_bfloat16 h1 = __float2bfloat16_rn(v.y);
        __nv_bfloat16 h2 = __float2bfloat16_rn(v.z);
        __nv_bfloat16 h3 = __float2bfloat16_rn(v.w);
        __nv_bfloat162* H = (__nv_bfloat162*)hi;
        __nv_bfloat162* L = (__nv_bfloat162*)lo;
        H[2 * i]     = __nv_bfloat162(h0, h1);
        H[2 * i + 1] = __nv_bfloat162(h2, h3);
        L[2 * i]     = __nv_bfloat162(__float2bfloat16_rn(v.x - __bfloat162float(h0)),
                                      __float2bfloat16_rn(v.y - __bfloat162float(h1)));
        L[2 * i + 1] = __nv_bfloat162(__float2bfloat16_rn(v.z - __bfloat162float(h2)),
                                      __float2bfloat16_rn(v.w - __bfloat162float(h3)));
    }
}

// ---------------- prep: h = A@B (16-row tiles), f1/f2, coalesced bf16 pair planes ----------------
template<int K, int NC, bool FV>
__global__ void prep(const float* __restrict__ A, const float* __restrict__ B, int bStr,
                     const float* __restrict__ av, int aStr,
                     __nv_bfloat16* __restrict__ phi, __nv_bfloat16* __restrict__ plo,
                     float* __restrict__ f1, float* __restrict__ f2) {
    constexpr int NOUT = 16 * NC / 256;
    __shared__ float As[16 * 64];
    __shared__ float Bs[64 * NC];
    __shared__ float to[16 * 68];
    size_t z = blockIdx.y;
    const float* Bh = B + z * (size_t)bStr;
    int tid = threadIdx.x;
    int col = tid % NC, rgrp = tid / NC;
    int row0 = blockIdx.x * 16;
    float acc[NOUT];
    #pragma unroll
    for (int i = 0; i < NOUT; i++) acc[i] = 0.f;

    for (int kc = 0; kc < K; kc += 64) {
        for (int e = tid; e < 64 * NC; e += 256)
            Bs[e] = Bh[(size_t)(kc + e / NC) * NC + (e % NC)];
        for (int e = tid; e < 16 * 64; e += 256)
            As[e] = A[(size_t)(row0 + (e >> 6)) * K + kc + (e & 63)];
        __syncthreads();
        #pragma unroll 16
        for (int k = 0; k < 64; k++) {
            float bv = Bs[k * NC + col];
            #pragma unroll
            for (int i = 0; i < NOUT; i++)
                acc[i] += As[(rgrp * NOUT + i) * 64 + k] * bv;
        }
        __syncthreads();
    }
    #pragma unroll
    for (int i = 0; i < NOUT; i++)
        to[(rgrp * NOUT + i) * 68 + col] = acc[i];
    __syncthreads();

    {
        int pcol = tid >> 2, q = tid & 3;
        __nv_bfloat16 hv[4], lv[4];
        #pragma unroll
        for (int i = 0; i < 4; i++) {
            float v = (pcol < NC) ? to[(q * 4 + i) * 68 + pcol] : 0.f;
            hv[i] = __float2bfloat16_rn(v);
            lv[i] = __float2bfloat16_rn(v - __bfloat162float(hv[i]));
        }
        size_t off = z * (size_t)64 * NN + (size_t)pcol * NN + row0 + q * 4;
        *(__nv_bfloat162*)&phi[off]     = __nv_bfloat162(hv[0], hv[1]);
        *(__nv_bfloat162*)&phi[off + 2] = __nv_bfloat162(hv[2], hv[3]);
        *(__nv_bfloat162*)&plo[off]     = __nv_bfloat162(lv[0], lv[1]);
        *(__nv_bfloat162*)&plo[off + 2] = __nv_bfloat162(lv[2], lv[3]);
    }

    if (FV) {
        const float* az = av + z * (size_t)aStr;
        int w = tid >> 5, lane = tid & 31;
        #pragma unroll
        for (int rr = 0; rr < 2; rr++) {
            int r = w * 2 + rr;
            float h0 = to[r * 68 + lane], h1 = to[r * 68 + lane + 32];
            float v1 = h0 * az[lane] + h1 * az[lane + 32];
            float v2 = h0 * az[64 + lane] + h1 * az[96 + lane];
            #pragma unroll
            for (int o = 16; o; o >>= 1) {
                v1 += __shfl_down_sync(0xffffffffu, v1, o);
                v2 += __shfl_down_sync(0xffffffffu, v2, o);
            }
            if (lane == 0) {
                f1[z * NN + row0 + r] = v1;
                f2[z * NN + row0 + r] = v2;
            }
        }
    }
}

// ---------------- radix sort: 3x8-bit passes over top-24 key bits + fused search ----------------
// misordering only among keys equal in top 24 bits; contribution to S is O(1e-9) — negligible.
#define RDXS (16384 + 16384 + 8192 + 8192 + 65536 + 4096 + 1024)

__global__ void __launch_bounds__(1024, 1) sortk(
        const float* __restrict__ f1, const float* __restrict__ f2g,
        float* __restrict__ f1s, int* __restrict__ piout, float2* __restrict__ pk) {
    extern __shared__ char rs[];
    uint32_t* keyA = (uint32_t*)rs;
    uint32_t* keyB = (uint32_t*)(rs + 16384);
    uint16_t* valA = (uint16_t*)(rs + 32768);
    uint16_t* valB = (uint16_t*)(rs + 40960);
    uint16_t* cnt  = (uint16_t*)(rs + 49152);               // [128][256]
    uint32_t* psum = (uint32_t*)(rs + 49152 + 65536);        // [4][256]
    uint32_t* ebase = psum + 1024;                           // [256]
    __shared__ uint32_t wsum[8];

    int tid = threadIdx.x;
    int lane = tid & 31, wid = tid >> 5;
    size_t hz = blockIdx.x;
    const float* src = f1 + hz * NN;

    for (int i = tid; i < NN; i += 1024) {
        uint32_t b = __float_as_uint(src[i]);
        keyA[i] = b ^ ((b & 0x80000000u) ? 0xFFFFFFFFu : 0x80000000u);
        valA[i] = (uint16_t)i;
    }
    __syncthreads();

    uint32_t* KA = keyA; uint32_t* KB = keyB;
    uint16_t* VA = valA; uint16_t* VB = valB;
    int dg = tid & 255, q = tid >> 8;

    #pragma unroll
    for (int shift = 8; shift < 32; shift += 8) {
        uint32_t k[4], d[4]; uint16_t v[4];
        #pragma unroll
        for (int s = 0; s < 4; s++) {
            k[s] = KA[s * 1024 + tid];
            v[s] = VA[s * 1024 + tid];
            d[s] = (k[s] >> shift) & 255u;
        }
        uint32_t* cz = (uint32_t*)cnt;
        #pragma unroll
        for (int i = 0; i < 16; i++) cz[i * 1024 + tid] = 0;
        __syncthreads();
        #pragma unroll
        for (int s = 0; s < 4; s++) {
            uint32_t mask = __match_any_sync(0xffffffffu, d[s]);
            if ((mask & ((1u << lane) - 1)) == 0)
                cnt[(s * 32 + wid) * 256 + d[s]] = (uint16_t)__popc(mask);
        }
        __syncthreads();
        // quarter sums: 4 threads per digit, 32 groups each (independent loads)
        {
            uint32_t part_ = 0;
            #pragma unroll
            for (int g = 0; g < 32; g++)
                part_ += (uint32_t)cnt[(q * 32 + g) * 256 + dg];
            psum[q * 256 + dg] = part_;
        }
        __syncthreads();
        // 256-wide scan via warp shuffles (3 barriers)
        uint32_t tot = 0, inc = 0;
        if (tid < 256) {
            tot = psum[tid] + psum[256 + tid] + psum[512 + tid] + psum[768 + tid];
            inc = tot;
            #pragma unroll
            for (int o = 1; o < 32; o <<= 1) {
                uint32_t t = __shfl_up_sync(0xffffffffu, inc, o);
                if (lane >= o) inc += t;
            }
            if (lane == 31) wsum[wid] = inc;
        }
        __syncthreads();
        if (tid < 256) {
            uint32_t off = 0;
            #pragma unroll
            for (int w = 0; w < 8; w++) if (w < wid) off += wsum[w];
            ebase[tid] = off + inc - tot;
        }
        __syncthreads();
        // write back per-group exclusive offsets (batched prefetch)
        {
            uint32_t run = ebase[dg];
            #pragma unroll
            for (int qq = 0; qq < 3; qq++) if (qq < q) run += psum[qq * 256 + dg];
            #pragma unroll
            for (int b8 = 0; b8 < 4; b8++) {
                uint32_t c[8];
                #pragma unroll
                for (int g = 0; g < 8; g++)
                    c[g] = cnt[(q * 32 + b8 * 8 + g) * 256 + dg];
                #pragma unroll
                for (int g = 0; g < 8; g++) {
                    cnt[(q * 32 + b8 * 8 + g) * 256 + dg] = (uint16_t)run;
                    run += c[g];
                }
            }
        }
        __syncthreads();
        #pragma unroll
        for (int s = 0; s < 4; s++) {
            uint32_t mask = __match_any_sync(0xffffffffu, d[s]);
            uint32_t rank = __popc(mask & ((1u << lane) - 1));
            uint32_t pos = (uint32_t)cnt[(s * 32 + wid) * 256 + d[s]] + rank;
            KB[pos] = k[s];
            VB[pos] = v[s];
        }
        __syncthreads();
        uint32_t* tk = KA; KA = KB; KB = tk;
        uint16_t* tv = VA; VA = VB; VB = tv;
    }
    float* dk = f1s + hz * NN;
    int* di = piout + hz * NN;
    for (int i = tid; i < NN; i += 1024) {
        uint32_t u = KA[i];
        uint32_t b = (u & 0x80000000u) ? (u ^ 0x80000000u) : ~u;
        dk[i] = __uint_as_float(b);
        di[i] = (int)VA[i];
    }
    // fused tvec: truncated-comparison binary search (consistent with sort order)
    for (int j = tid; j < NN; j += 1024) {
        float f2j = f2g[hz * NN + j];
        uint32_t tb = __float_as_uint(-f2j);
        uint32_t tk24 = (tb ^ ((tb & 0x80000000u) ? 0xFFFFFFFFu : 0x80000000u)) >> 8;
        int lo = 0, hi = NN;
        while (lo < hi) {
            int mid = (lo + hi) >> 1;
            if ((KA[mid] >> 8) <= tk24) lo = mid + 1; else hi = mid;
        }
        int pidx = 16;
        if (lo > 0) pidx = ((lo - 1) >> 4) * 17 + ((lo - 1) & 15);
        pk[hz * NN + j] = make_float2(f2j, __int_as_float(pidx));
    }
}

// ---------------- phase A: all heads per block, S cached in smem, row-chunked ----------------
#define PASMEM (16896 * 4)

__global__ void phaseA(const float* __restrict__ adj, const int* __restrict__ pi,
                       const float* __restrict__ f1s, const float2* __restrict__ pk,
                       __nv_bfloat16* __restrict__ Whi, __nv_bfloat16* __restrict__ Wlo,
                       float* __restrict__ rinv, int nheads, int rowOff) {
    extern __shared__ float sm[];
    float* arow = sm;
    float* sP = sm + 4096;
    float* sQ = sP + 4352;
    float* sS = sQ + 4352;
    __shared__ float wsp[8], wsq[8];

    int i = blockIdx.x + rowOff, tid = threadIdx.x;
    unsigned lane = tid & 31, wid = tid >> 5;

    const float* Arow = adj + (size_t)i * NN;
    for (int r = tid; r < NN; r += 256) arow[r] = Arow[r];
    if (tid == 0) { sP[16] = 0.f; sQ[16] = 0.f; }
    __syncthreads();

    for (int hz = 0; hz < nheads; hz++) {
        const int* piz = pi + (size_t)hz * NN;
        const float* f1z = f1s + (size_t)hz * NN;
        const float2* pkz = pk + (size_t)hz * NN;

        for (int r = tid; r < NN; r += 256) {
            float a = arow[piz[r]];
            int pr = ((r >> 4) * 17) + (r & 15);
            sP[pr] = a;
            sQ[pr] = a * f1z[r];
        }
        __syncthreads();
        int base = tid * 17;
        float p = 0.f, q = 0.f;
        #pragma unroll
        for (int u = 0; u < 16; u++) {
            p += sP[base + u]; sP[base + u] = p;
            q += sQ[base + u]; sQ[base + u] = q;
        }
        float ip = p, iq = q;
        #pragma unroll
        for (int o = 1; o < 32; o <<= 1) {
            float tp = __shfl_up_sync(0xffffffffu, ip, o);
            float tq = __shfl_up_sync(0xffffffffu, iq, o);
            if (lane >= o) { ip += tp; iq += tq; }
        }
        if (lane == 31) { wsp[wid] = ip; wsq[wid] = iq; }
        __syncthreads();
        float offp = 0.f, offq = 0.f;
        for (int w = 0; w < 8; w++)
            if (w < (int)wid) { offp += wsp[w]; offq += wsq[w]; }
        float ep = offp + ip - p;
        float eq = offq + iq - q;
        #pragma unroll
        for (int u = 0; u < 16; u++) { sP[base + u] += ep; sQ[base + u] += eq; }
        __syncthreads();
        float A0 = sP[255 * 17 + 15];
        float A1 = sQ[255 * 17 + 15];

        float m = -3.0e38f;
        for (int j = tid; j < NN; j += 256) {
            float2 pj = pkz[j];
            float f2j = pj.x;
            int pidx = __float_as_int(pj.y);
            float S = A1 + A0 * f2j - OMA * (sQ[pidx] + f2j * sP[pidx]);
            sS[j] = S;
            m = fmaxf(m, S);
        }
        #pragma unroll
        for (int o = 16; o; o >>= 1) m = fmaxf(m, __shfl_xor_sync(0xffffffffu, m, o));
        __syncthreads();
        if (lane == 0) wsp[wid] = m;
        __syncthreads();
        float mall = wsp[0];
        #pragma unroll
        for (int w = 1; w < 8; w++) mall = fmaxf(mall, wsp[w]);

        float z = 0.f;
        __nv_bfloat162* Wh = (__nv_bfloat162*)(Whi + (size_t)hz * NN * NN + (size_t)i * NN);
        __nv_bfloat162* Wl = (__nv_bfloat162*)(Wlo + (size_t)hz * NN * NN + (size_t)i * NN);
        for (int j0 = tid * 2; j0 < NN; j0 += 512) {
            float w0 = __expf(sS[j0] - mall);
            float w1 = __expf(sS[j0 + 1] - mall);
            z += w0 + w1;
            __nv_bfloat16 h0 = __float2bfloat16_rn(w0);
            __nv_bfloat16 h1 = __float2bfloat16_rn(w1);
            Wh[j0 >> 1] = __nv_bfloat162(h0, h1);
            Wl[j0 >> 1] = __nv_bfloat162(
                __float2bfloat16_rn(w0 - __bfloat162float(h0)),
                __float2bfloat16_rn(w1 - __bfloat162float(h1)));
        }
        #pragma unroll
        for (int o = 16; o; o >>= 1) z += __shfl_xor_sync(0xffffffffu, z, o);
        __syncthreads();
        if (lane == 0) wsq[wid] = z;
        __syncthreads();
        if (tid == 0) {
            float zt = 0.f;
            #pragma unroll
            for (int w = 0; w < 8; w++) zt += wsq[w];
            rinv[(size_t)hz * NN + i] = 1.0f / zt;
        }
        __syncthreads();
    }
}

// ---------------- epilogue: 16-row tiles, coalesced optional plane emission ----------------
__global__ void epilogue_k(const float* __restrict__ part, int splits,
                           const float* __restrict__ rinv, float* __restrict__ dst,
                           int ldc, int dstHeadOff, int mode,
                           __nv_bfloat16* __restrict__ phi, __nv_bfloat16* __restrict__ plo) {
    __shared__ float to[16 * 68];
    size_t z = blockIdx.y;
    const float* pz = part + z * (size_t)splits * NN * 64;
    int tid = threadIdx.x;
    int col = tid & 63, rg = tid >> 6;
    int row0 = blockIdx.x * 16;
    #pragma unroll
    for (int i = 0; i < 4; i++) {
        int rl = rg * 4 + i;
        int row = row0 + rl;
        int idx = row * 64 + col;
        float v = 0.f;
        for (int s = 0; s < splits; s++) v += pz[(size_t)s * NN * 64 + idx];
        if (rinv) v *= rinv[z * NN + row];
        if (mode == 1) v = fmaxf(v, 0.f);
        else if (mode == 2) v = (v > 0.f) ? v : expm1f(v);
        dst[(size_t)row * ldc + z * dstHeadOff + col] = v;
        to[rl * 68 + col] = v;
    }
    if (phi) {
        __syncthreads();
        int pcol = tid >> 2, q = tid & 3;
        __nv_bfloat16 hv[4], lv[4];
        #pragma unroll
        for (int i = 0; i < 4; i++) {
            float v = to[(q * 4 + i) * 68 + pcol];
            hv[i] = __float2bfloat16_rn(v);
            lv[i] = __float2bfloat16_rn(v - __bfloat162float(hv[i]));
        }
        size_t off = (size_t)pcol * NN + row0 + q * 4;
        *(__nv_bfloat162*)&phi[off]     = __nv_bfloat162(hv[0], hv[1]);
        *(__nv_bfloat162*)&phi[off + 2] = __nv_bfloat162(hv[2], hv[3]);
        *(__nv_bfloat162*)&plo[off]     = __nv_bfloat162(lv[0], lv[1]);
        *(__nv_bfloat162*)&plo[off + 2] = __nv_bfloat162(lv[2], lv[3]);
    }
}

__global__ void epi32(const float* __restrict__ part, float* __restrict__ dst) {
    int idx = blockIdx.x * 256 + threadIdx.x;
    int row = idx >> 5, col = idx & 31;
    float v = 0.f;
    for (int s = 0; s < 8; s++) v += part[(size_t)s * NN * 64 + (size_t)row * 64 + col];
    dst[idx] = v;
}

// ---------------- host orchestration ----------------
struct Bufs {
    __nv_bfloat16 *Whi, *Wlo, *ahi, *alo, *xhi, *xlo, *bhi, *blo;
    float *cat, *x1, *tb, *h1, *part, *f1, *f2, *f1s, *rinv;
    int *pi;
    float2 *pk;
};

static void run_gat_single(const float* adjc, const float* F,
                           const float* Hm, const float* av,
                           float* dst, const Bufs& b, bool planes) {
    prep<256, 64, true><<<dim3(NN / 16, 1), 256>>>(F, Hm, 0, av, 0,
                                                   b.bhi, b.blo, b.f1, b.f2);
    sortk<<<1, 1024, RDXS>>>(b.f1, b.f2, b.f1s, b.pi, b.pk);
    // chunked: W chunk stays in L2 between phaseA and mm_mma
    for (int c = 0; c < 2; c++) {
        phaseA<<<2048, 256, PASMEM>>>(adjc, b.pi, b.f1s, b.pk, b.Whi, b.Wlo,
                                      b.rinv, 1, c * 2048);
        mm_mma<<<dim3(16, 16, 1), 256, MMSMEM>>>(b.Whi, b.Wlo, b.bhi, b.blo, b.part,
                                                 0, 0, c * 16);
    }
    epilogue_k<<<dim3(NN / 16, 1), 256>>>(b.part, 16, b.rinv, dst, 64, 0, 2,
                                          planes ? b.bhi : nullptr,
                                          planes ? b.blo : nullptr);
}

static void run_heads(const float* adjc, const float* prev,
                      const float* HmBase, const float* avBase, const Bufs& b) {
    prep<64, 64, true><<<dim3(NN / 16, NH), 256>>>(prev, HmBase, 64 * 64, avBase, 128,
                                                   b.bhi, b.blo, b.f1, b.f2);
    sortk<<<NH, 1024, RDXS>>>(b.f1, b.f2, b.f1s, b.pi, b.pk);
    for (int c = 0; c < 4; c++) {
        phaseA<<<1024, 256, PASMEM>>>(adjc, b.pi, b.f1s, b.pk, b.Whi, b.Wlo,
                                      b.rinv, NH, c * 1024);
        mm_mma<<<dim3(8, 8, NH), 256, MMSMEM>>>(b.Whi, b.Wlo, b.bhi, b.blo, b.part,
                                                (size_t)NN * NN, (size_t)64 * NN, c * 8);
    }
    epilogue_k<<<dim3(NN / 16, NH), 256>>>(b.part, 8, b.rinv, b.cat, 256, 64, 2,
                                           nullptr, nullptr);
}

extern "C" void kernel_launch(void* const* d_in, const int* in_sizes, int n_in,
                              void* d_out, int out_size) {
    const float* x      = (const float*)d_in[0];
    const float* adj    = (const float*)d_in[1];
    const float* w_init = (const float*)d_in[2];
    const float* head_H = (const float*)d_in[3];
    const float* head_a = (const float*)d_in[4];
    const float* out_H  = (const float*)d_in[5];
    const float* out_a  = (const float*)d_in[6];
    const float* l2_w   = (const float*)d_in[7];
    float* out = (float*)d_out;

    cudaFuncSetAttribute(phaseA, cudaFuncAttributeMaxDynamicSharedMemorySize, PASMEM);
    cudaFuncSetAttribute(mm_mma, cudaFuncAttributeMaxDynamicSharedMemorySize, MMSMEM);
    cudaFuncSetAttribute(sortk, cudaFuncAttributeMaxDynamicSharedMemorySize, RDXS);

    static cudaStream_t s2 = nullptr;
    static cudaEvent_t evF = nullptr, evJ = nullptr;
    if (!s2) {
        cudaStreamCreateWithFlags(&s2, cudaStreamNonBlocking);
        cudaEventCreateWithFlags(&evF, cudaEventDisableTiming);
        cudaEventCreateWithFlags(&evJ, cudaEventDisableTiming);
    }

    Bufs b;
    cudaGetSymbolAddress((void**)&b.Whi, g_Whi);
    cudaGetSymbolAddress((void**)&b.Wlo, g_Wlo);
    cudaGetSymbolAddress((void**)&b.ahi, g_ahi);
    cudaGetSymbolAddress((void**)&b.alo, g_alo);
    cudaGetSymbolAddress((void**)&b.xhi, g_xhi);
    cudaGetSymbolAddress((void**)&b.xlo, g_xlo);
    cudaGetSymbolAddress((void**)&b.bhi, g_bhi);
    cudaGetSymbolAddress((void**)&b.blo, g_blo);
    cudaGetSymbolAddress((void**)&b.cat, g_cat);
    cudaGetSymbolAddress((void**)&b.x1, g_x1);
    cudaGetSymbolAddress((void**)&b.tb, g_tb);
    cudaGetSymbolAddress((void**)&b.h1, g_h1);
    cudaGetSymbolAddress((void**)&b.part, g_part);
    cudaGetSymbolAddress((void**)&b.f1, g_f1);
    cudaGetSymbolAddress((void**)&b.f2, g_f2);
    cudaGetSymbolAddress((void**)&b.f1s, g_f1s);
    cudaGetSymbolAddress((void**)&b.rinv, g_rinv);
    cudaGetSymbolAddress((void**)&b.pi, g_pi);
    cudaGetSymbolAddress((void**)&b.pk, g_pk);

    // fork: input-only pair conversions overlap with cell-0/1 GAT chain
    cudaEventRecord(evF, 0);
    cudaStreamWaitEvent(s2, evF, 0);
    cpair<<<4096, 256, 0, s2>>>((const float4*)(x + (size_t)NN * NN), b.xhi, b.xlo);
    cpair<<<4096, 256, 0, s2>>>((const float4*)(adj + (size_t)NN * NN), b.ahi, b.alo);
    cudaEventRecord(evJ, s2);

    const float* prev = w_init;
    for (int i = 0; i < 2; i++) {
        const float* adjc = adj + (size_t)i * NN * NN;
        run_heads(adjc, prev, head_H + (size_t)i * NH * 64 * 64,
                  head_a + (size_t)i * NH * 128, b);
        run_gat_single(adjc, b.cat, out_H + (size_t)i * 256 * 64,
                       out_a + (size_t)i * 128, b.x1, b, i == 1);
        prev = b.x1;

        if (i == 1) {
            cudaStreamWaitEvent(0, evJ, 0);
            // tb = x @ x1 (x1 planes already in bhi/blo); emit tb planes
            mm_mma<<<dim3(32, 8, 1), 256, MMSMEM>>>(b.xhi, b.xlo, b.bhi, b.blo,
                                                    b.part, 0, 0, 0);
            epilogue_k<<<dim3(NN / 16, 1), 256>>>(b.part, 8, nullptr, b.tb, 64, 0, 0,
                                                  b.bhi, b.blo);
            // h1 = relu(adj @ tb)
            mm_mma<<<dim3(32, 8, 1), 256, MMSMEM>>>(b.ahi, b.alo, b.bhi, b.blo,
                                                    b.part, 0, 0, 0);
            epilogue_k<<<dim3(NN / 16, 1), 256>>>(b.part, 8, nullptr, b.h1, 64, 0, 1,
                                                  nullptr, nullptr);
            // u = h1 @ l2_w -> planes directly (zero-padded to 64)
            prep<64, 32, false><<<dim3(NN / 16, 1), 256>>>(b.h1, l2_w + (size_t)i * 64 * 32,
                                                           0, nullptr, 0,
                                                           b.bhi, b.blo, nullptr, nullptr);
            // out = adj @ u
            mm_mma<<<dim3(32, 8, 1), 256, MMSMEM>>>(b.ahi, b.alo, b.bhi, b.blo,
                                                    b.part, 0, 0, 0);
            epi32<<<NN * 32 / 256, 256>>>(b.part, out);
        }
    }
}

// round 11
// speedup vs baseline: 1.2199x; 1.2199x over previous
#include <cuda_runtime.h>
#include <cuda_bf16.h>
#include <math.h>
#include <stdint.h>

#define NN 4096
#define DD 64
#define OMA 0.8f   // 1 - alpha(0.2)
#define NH 4

// ---------------- scratch (device globals; allocation-free) ----------------
__device__ __nv_bfloat16 g_Whi[(size_t)NH * NN * NN];
__device__ __nv_bfloat16 g_ahi[(size_t)NN * NN];
__device__ __nv_bfloat16 g_alo[(size_t)NN * NN];
__device__ __nv_bfloat16 g_xhi[(size_t)NN * NN];
__device__ __nv_bfloat16 g_xlo[(size_t)NN * NN];
__device__ __nv_bfloat16 g_bhi[NH * 64 * NN];
__device__ __nv_bfloat16 g_blo[NH * 64 * NN];
__device__ float g_cat[NN * NH * DD];
__device__ float g_x1[NN * DD];
__device__ float g_tb[NN * DD];
__device__ float g_h1[NN * DD];
__device__ float g_part[8 * NN * DD];
__device__ float g_f1[NH * NN], g_f2[NH * NN], g_f1s[NH * NN], g_rinv[NH * NN];
__device__ int   g_pi[NH * NN];
__device__ float2 g_pk[NH * NN];

// ================= portable (sm_80+) PTX helpers =================
__device__ __forceinline__ uint32_t smem_u32(const void* p) {
    uint32_t a;
    asm("{ .reg .u64 t; cvta.to.shared.u64 t, %1; cvt.u32.u64 %0, t; }"
        : "=r"(a) : "l"(p));
    return a;
}

#define CP16(dst, src) \
    asm volatile("cp.async.cg.shared.global [%0], [%1], 16;" :: "r"(dst), "l"(src))
#define CP_COMMIT() asm volatile("cp.async.commit_group;" ::: "memory")
#define CP_WAIT0() asm volatile("cp.async.wait_group 0;" ::: "memory")
#define CP_WAIT1() asm volatile("cp.async.wait_group 1;" ::: "memory")

__device__ __forceinline__ void ldm4(uint32_t* r, uint32_t addr) {
    asm volatile("ldmatrix.sync.aligned.m8n8.x4.shared.b16 {%0,%1,%2,%3}, [%4];"
        : "=r"(r[0]), "=r"(r[1]), "=r"(r[2]), "=r"(r[3]) : "r"(addr));
}

__device__ __forceinline__ void mma16816(float* d, const uint32_t* a, const uint32_t* b) {
    asm volatile("mma.sync.aligned.m16n8k16.row.col.f32.bf16.bf16.f32 "
        "{%0,%1,%2,%3}, {%4,%5,%6,%7}, {%8,%9}, {%0,%1,%2,%3};"
        : "+f"(d[0]), "+f"(d[1]), "+f"(d[2]), "+f"(d[3])
        : "r"(a[0]), "r"(a[1]), "r"(a[2]), "r"(a[3]), "r"(b[0]), "r"(b[1]));
}

__device__ __forceinline__ uint32_t swz(uint32_t bo) { return bo ^ ((bo >> 3) & 0x70); }

// ================= tensor-core big matmul (mma.sync bf16 pair-split) =================
// combos==3: (AhBh + AhBl + AlBh)  — A pair-split
// combos==2: (AhBh + AhBl)        — A single plane (skip Alo loads & MMAs)
#define O_AH 0
#define O_AL 16384
#define O_BH 32768
#define O_BL 40960
#define STG  49152
#define MMSMEM (2 * STG)

__global__ void __launch_bounds__(256, 2) mm_mma(
        const __nv_bfloat16* __restrict__ Ahi, const __nv_bfloat16* __restrict__ Alo,
        const __nv_bfloat16* __restrict__ Bhi, const __nv_bfloat16* __restrict__ Blo,
        float* __restrict__ part, size_t aStr, size_t bStr, int combos) {
    extern __shared__ char smem[];
    uint32_t sb = smem_u32(smem);
    int tid = threadIdx.x, wid = tid >> 5, lane = tid & 31;
    int m0 = blockIdx.x * 128;
    int klen = NN / gridDim.y;
    int kbeg = blockIdx.y * klen;
    int nch = klen / 64;
    int wm = wid >> 1, wn = wid & 1;
    size_t zo = (size_t)blockIdx.z;
    const __nv_bfloat16* AhiZ = Ahi + zo * aStr;
    const __nv_bfloat16* AloZ = Alo ? Alo + zo * aStr : nullptr;
    const __nv_bfloat16* BhiZ = Bhi + zo * bStr;
    const __nv_bfloat16* BloZ = Blo + zo * bStr;

    auto load_chunk = [&](int ch) {
        uint32_t base = sb + (uint32_t)(ch & 1) * STG;
        int kc = kbeg + ch * 64;
        int r = tid >> 3, c = tid & 7;
        uint32_t sw = swz((uint32_t)(r * 128 + c * 16));
        #pragma unroll
        for (int i = 0; i < 4; i++)
            CP16(base + O_AH + sw + (uint32_t)i * 4096,
                 AhiZ + (size_t)(m0 + r + i * 32) * NN + kc + c * 8);
        if (combos == 3) {
            #pragma unroll
            for (int i = 0; i < 4; i++)
                CP16(base + O_AL + sw + (uint32_t)i * 4096,
                     AloZ + (size_t)(m0 + r + i * 32) * NN + kc + c * 8);
        }
        #pragma unroll
        for (int pl = 0; pl < 2; pl++) {
            const __nv_bfloat16* src = pl ? BloZ : BhiZ;
            uint32_t off = pl ? O_BL : O_BH;
            #pragma unroll
            for (int i = 0; i < 2; i++)
                CP16(base + off + sw + (uint32_t)i * 4096,
                     src + (size_t)(r + i * 32) * NN + kc + c * 8);
        }
        CP_COMMIT();
    };

    float acc[2][4][4] = {};
    load_chunk(0);
    for (int ch = 0; ch < nch; ch++) {
        if (ch + 1 < nch) { load_chunk(ch + 1); CP_WAIT1(); }
        else               { CP_WAIT0(); }
        __syncthreads();
        uint32_t base = sb + (uint32_t)(ch & 1) * STG;
        #pragma unroll
        for (int ks = 0; ks < 4; ks++) {
            uint32_t ah[2][4], al[2][4], bh[8], bl[8];
            #pragma unroll
            for (int mt = 0; mt < 2; mt++) {
                int row = wm * 32 + mt * 16 + (lane & 7) + ((lane >> 3) & 1) * 8;
                int koff = ks * 32 + (lane >> 4) * 16;
                uint32_t sw = swz((uint32_t)(row * 128 + koff));
                ldm4(ah[mt], base + O_AH + sw);
                if (combos == 3) ldm4(al[mt], base + O_AL + sw);
            }
            #pragma unroll
            for (int half = 0; half < 2; half++) {
                int g = lane >> 3;
                int n = wn * 32 + half * 16 + (g >> 1) * 8 + (lane & 7);
                int koff = ks * 32 + (g & 1) * 16;
                uint32_t sw = swz((uint32_t)(n * 128 + koff));
                ldm4(bh + half * 4, base + O_BH + sw);
                ldm4(bl + half * 4, base + O_BL + sw);
            }
            #pragma unroll
            for (int mt = 0; mt < 2; mt++)
                #pragma unroll
                for (int nt = 0; nt < 4; nt++) {
                    mma16816(acc[mt][nt], ah[mt], bh + nt * 2);
                    mma16816(acc[mt][nt], ah[mt], bl + nt * 2);
                    if (combos == 3) mma16816(acc[mt][nt], al[mt], bh + nt * 2);
                }
        }
        __syncthreads();
    }

    float* cp = part + ((size_t)blockIdx.z * gridDim.y + blockIdx.y) * (NN * 64);
    #pragma unroll
    for (int mt = 0; mt < 2; mt++)
        #pragma unroll
        for (int nt = 0; nt < 4; nt++) {
            int row = m0 + wm * 32 + mt * 16 + (lane >> 2);
            int col = wn * 32 + nt * 8 + (lane & 3) * 2;
            *(float2*)&cp[(size_t)row * 64 + col] =
                make_float2(acc[mt][nt][0], acc[mt][nt][1]);
            *(float2*)&cp[(size_t)(row + 8) * 64 + col] =
                make_float2(acc[mt][nt][2], acc[mt][nt][3]);
        }
}

// ---------------- fp32 -> bf16 pair planes (big matrices) ----------------
__global__ void cpair(const float4* __restrict__ in, __nv_bfloat16* __restrict__ hi,
                      __nv_bfloat16* __restrict__ lo) {
    size_t n4 = (size_t)NN * NN / 4;
    for (size_t i = (size_t)blockIdx.x * 256 + threadIdx.x; i < n4;
         i += (size_t)gridDim.x * 256) {
        float4 v = in[i];
        __nv_bfloat16 h0 = __float2bfloat16_rn(v.x);
        __nv_bfloat16 h1 = __float2bfloat16_rn(v.y);
        __nv_bfloat16 h2 = __float2bfloat16_rn(v.z);
        __nv_bfloat16 h3 = __float2bfloat16_rn(v.w);
        __nv_bfloat162* H = (__nv_bfloat162*)hi;
        __nv_bfloat162* L = (__nv_bfloat162*)lo;
        H[2 * i]     = __nv_bfloat162(h0, h1);
        H[2 * i + 1] = __nv_bfloat162(h2, h3);
        L[2 * i]     = __nv_bfloat162(__float2bfloat16_rn(v.x - __bfloat162float(h0)),
                                      __float2bfloat16_rn(v.y - __bfloat162float(h1)));
        L[2 * i + 1] = __nv_bfloat162(__float2bfloat16_rn(v.z - __bfloat162float(h2)),
                                      __float2bfloat16_rn(v.w - __bfloat162float(h3)));
    }
}

// ---------------- prep: h = A@B (16-row tiles), f1/f2, coalesced bf16 pair planes ----------------
template<int K, int NC, bool FV>
__global__ void prep(const float* __restrict__ A, const float* __restrict__ B, int bStr,
                     const float* __restrict__ av, int aStr,
                     __nv_bfloat16* __restrict__ phi, __nv_bfloat16* __restrict__ plo,
                     float* __restrict__ f1, float* __restrict__ f2) {
    constexpr int NOUT = 16 * NC / 256;
    __shared__ float As[16 * 64];
    __shared__ float Bs[64 * NC];
    __shared__ float to[16 * 68];
    size_t z = blockIdx.y;
    const float* Bh = B + z * (size_t)bStr;
    int tid = threadIdx.x;
    int col = tid % NC, rgrp = tid / NC;
    int row0 = blockIdx.x * 16;
    float acc[NOUT];
    #pragma unroll
    for (int i = 0; i < NOUT; i++) acc[i] = 0.f;

    for (int kc = 0; kc < K; kc += 64) {
        for (int e = tid; e < 64 * NC; e += 256)
            Bs[e] = Bh[(size_t)(kc + e / NC) * NC + (e % NC)];
        for (int e = tid; e < 16 * 64; e += 256)
            As[e] = A[(size_t)(row0 + (e >> 6)) * K + kc + (e & 63)];
        __syncthreads();
        #pragma unroll 16
        for (int k = 0; k < 64; k++) {
            float bv = Bs[k * NC + col];
            #pragma unroll
            for (int i = 0; i < NOUT; i++)
                acc[i] += As[(rgrp * NOUT + i) * 64 + k] * bv;
        }
        __syncthreads();
    }
    #pragma unroll
    for (int i = 0; i < NOUT; i++)
        to[(rgrp * NOUT + i) * 68 + col] = acc[i];
    __syncthreads();

    {
        int pcol = tid >> 2, q = tid & 3;
        __nv_bfloat16 hv[4], lv[4];
        #pragma unroll
        for (int i = 0; i < 4; i++) {
            float v = (pcol < NC) ? to[(q * 4 + i) * 68 + pcol] : 0.f;
            hv[i] = __float2bfloat16_rn(v);
            lv[i] = __float2bfloat16_rn(v - __bfloat162float(hv[i]));
        }
        size_t off = z * (size_t)64 * NN + (size_t)pcol * NN + row0 + q * 4;
        *(__nv_bfloat162*)&phi[off]     = __nv_bfloat162(hv[0], hv[1]);
        *(__nv_bfloat162*)&phi[off + 2] = __nv_bfloat162(hv[2], hv[3]);
        *(__nv_bfloat162*)&plo[off]     = __nv_bfloat162(lv[0], lv[1]);
        *(__nv_bfloat162*)&plo[off + 2] = __nv_bfloat162(lv[2], lv[3]);
    }

    if (FV) {
        const float* az = av + z * (size_t)aStr;
        int w = tid >> 5, lane = tid & 31;
        #pragma unroll
        for (int rr = 0; rr < 2; rr++) {
            int r = w * 2 + rr;
            float h0 = to[r * 68 + lane], h1 = to[r * 68 + lane + 32];
            float v1 = h0 * az[lane] + h1 * az[lane + 32];
            float v2 = h0 * az[64 + lane] + h1 * az[96 + lane];
            #pragma unroll
            for (int o = 16; o; o >>= 1) {
                v1 += __shfl_down_sync(0xffffffffu, v1, o);
                v2 += __shfl_down_sync(0xffffffffu, v2, o);
            }
            if (lane == 0) {
                f1[z * NN + row0 + r] = v1;
                f2[z * NN + row0 + r] = v2;
            }
        }
    }
}

// ---------------- radix sort: 3x8-bit passes over top-24 key bits + fused search ----------------
#define RDXS (16384 + 16384 + 8192 + 8192 + 65536 + 4096 + 1024)

__global__ void __launch_bounds__(1024, 1) sortk(
        const float* __restrict__ f1, const float* __restrict__ f2g,
        float* __restrict__ f1s, int* __restrict__ piout, float2* __restrict__ pk) {
    extern __shared__ char rs[];
    uint32_t* keyA = (uint32_t*)rs;
    uint32_t* keyB = (uint32_t*)(rs + 16384);
    uint16_t* valA = (uint16_t*)(rs + 32768);
    uint16_t* valB = (uint16_t*)(rs + 40960);
    uint16_t* cnt  = (uint16_t*)(rs + 49152);
    uint32_t* psum = (uint32_t*)(rs + 49152 + 65536);
    uint32_t* ebase = psum + 1024;
    __shared__ uint32_t wsum[8];

    int tid = threadIdx.x;
    int lane = tid & 31, wid = tid >> 5;
    size_t hz = blockIdx.x;
    const float* src = f1 + hz * NN;

    for (int i = tid; i < NN; i += 1024) {
        uint32_t b = __float_as_uint(src[i]);
        keyA[i] = b ^ ((b & 0x80000000u) ? 0xFFFFFFFFu : 0x80000000u);
        valA[i] = (uint16_t)i;
    }
    __syncthreads();

    uint32_t* KA = keyA; uint32_t* KB = keyB;
    uint16_t* VA = valA; uint16_t* VB = valB;
    int dg = tid & 255, q = tid >> 8;

    #pragma unroll
    for (int shift = 8; shift < 32; shift += 8) {
        uint32_t k[4], d[4]; uint16_t v[4];
        #pragma unroll
        for (int s = 0; s < 4; s++) {
            k[s] = KA[s * 1024 + tid];
            v[s] = VA[s * 1024 + tid];
            d[s] = (k[s] >> shift) & 255u;
        }
        uint32_t* cz = (uint32_t*)cnt;
        #pragma unroll
        for (int i = 0; i < 16; i++) cz[i * 1024 + tid] = 0;
        __syncthreads();
        #pragma unroll
        for (int s = 0; s < 4; s++) {
            uint32_t mask = __match_any_sync(0xffffffffu, d[s]);
            if ((mask & ((1u << lane) - 1)) == 0)
                cnt[(s * 32 + wid) * 256 + d[s]] = (uint16_t)__popc(mask);
        }
        __syncthreads();
        {
            uint32_t part_ = 0;
            #pragma unroll
            for (int g = 0; g < 32; g++)
                part_ += (uint32_t)cnt[(q * 32 + g) * 256 + dg];
            psum[q * 256 + dg] = part_;
        }
        __syncthreads();
        uint32_t tot = 0, inc = 0;
        if (tid < 256) {
            tot = psum[tid] + psum[256 + tid] + psum[512 + tid] + psum[768 + tid];
            inc = tot;
            #pragma unroll
            for (int o = 1; o < 32; o <<= 1) {
                uint32_t t = __shfl_up_sync(0xffffffffu, inc, o);
                if (lane >= o) inc += t;
            }
            if (lane == 31) wsum[wid] = inc;
        }
        __syncthreads();
        if (tid < 256) {
            uint32_t off = 0;
            #pragma unroll
            for (int w = 0; w < 8; w++) if (w < wid) off += wsum[w];
            ebase[tid] = off + inc - tot;
        }
        __syncthreads();
        {
            uint32_t run = ebase[dg];
            #pragma unroll
            for (int qq = 0; qq < 3; qq++) if (qq < q) run += psum[qq * 256 + dg];
            #pragma unroll
            for (int b8 = 0; b8 < 4; b8++) {
                uint32_t c[8];
                #pragma unroll
                for (int g = 0; g < 8; g++)
                    c[g] = cnt[(q * 32 + b8 * 8 + g) * 256 + dg];
                #pragma unroll
                for (int g = 0; g < 8; g++) {
                    cnt[(q * 32 + b8 * 8 + g) * 256 + dg] = (uint16_t)run;
                    run += c[g];
                }
            }
        }
        __syncthreads();
        #pragma unroll
        for (int s = 0; s < 4; s++) {
            uint32_t mask = __match_any_sync(0xffffffffu, d[s]);
            uint32_t rank = __popc(mask & ((1u << lane) - 1));
            uint32_t pos = (uint32_t)cnt[(s * 32 + wid) * 256 + d[s]] + rank;
            KB[pos] = k[s];
            VB[pos] = v[s];
        }
        __syncthreads();
        uint32_t* tk = KA; KA = KB; KB = tk;
        uint16_t* tv = VA; VA = VB; VB = tv;
    }
    float* dk = f1s + hz * NN;
    int* di = piout + hz * NN;
    for (int i = tid; i < NN; i += 1024) {
        uint32_t u = KA[i];
        uint32_t b = (u & 0x80000000u) ? (u ^ 0x80000000u) : ~u;
        dk[i] = __uint_as_float(b);
        di[i] = (int)VA[i];
    }
    for (int j = tid; j < NN; j += 1024) {
        float f2j = f2g[hz * NN + j];
        uint32_t tb = __float_as_uint(-f2j);
        uint32_t tk24 = (tb ^ ((tb & 0x80000000u) ? 0xFFFFFFFFu : 0x80000000u)) >> 8;
        int lo = 0, hi = NN;
        while (lo < hi) {
            int mid = (lo + hi) >> 1;
            if ((KA[mid] >> 8) <= tk24) lo = mid + 1; else hi = mid;
        }
        int pidx = 16;
        if (lo > 0) pidx = ((lo - 1) >> 4) * 17 + ((lo - 1) & 15);
        pk[hz * NN + j] = make_float2(f2j, __int_as_float(pidx));
    }
}

// ---------------- phase A: all heads per block (internal loop), single-plane W ----------------
#define PASMEM (16896 * 4)

__global__ void phaseA(const float* __restrict__ adj, const int* __restrict__ pi,
                       const float* __restrict__ f1s, const float2* __restrict__ pk,
                       __nv_bfloat16* __restrict__ Whi,
                       float* __restrict__ rinv, int nheads) {
    extern __shared__ float sm[];
    float* arow = sm;
    float* sP = sm + 4096;
    float* sQ = sP + 4352;
    float* sS = sQ + 4352;
    __shared__ float wsp[8], wsq[8];

    int i = blockIdx.x, tid = threadIdx.x;
    unsigned lane = tid & 31, wid = tid >> 5;

    const float* Arow = adj + (size_t)i * NN;
    for (int r = tid; r < NN; r += 256) arow[r] = Arow[r];
    if (tid == 0) { sP[16] = 0.f; sQ[16] = 0.f; }
    __syncthreads();

    for (int hz = 0; hz < nheads; hz++) {
        const int* piz = pi + (size_t)hz * NN;
        const float* f1z = f1s + (size_t)hz * NN;
        const float2* pkz = pk + (size_t)hz * NN;

        for (int r = tid; r < NN; r += 256) {
            float a = arow[piz[r]];
            int pr = ((r >> 4) * 17) + (r & 15);
            sP[pr] = a;
            sQ[pr] = a * f1z[r];
        }
        __syncthreads();
        int base = tid * 17;
        float p = 0.f, q = 0.f;
        #pragma unroll
        for (int u = 0; u < 16; u++) {
            p += sP[base + u]; sP[base + u] = p;
            q += sQ[base + u]; sQ[base + u] = q;
        }
        float ip = p, iq = q;
        #pragma unroll
        for (int o = 1; o < 32; o <<= 1) {
            float tp = __shfl_up_sync(0xffffffffu, ip, o);
            float tq = __shfl_up_sync(0xffffffffu, iq, o);
            if (lane >= o) { ip += tp; iq += tq; }
        }
        if (lane == 31) { wsp[wid] = ip; wsq[wid] = iq; }
        __syncthreads();
        float offp = 0.f, offq = 0.f;
        for (int w = 0; w < 8; w++)
            if (w < (int)wid) { offp += wsp[w]; offq += wsq[w]; }
        float ep = offp + ip - p;
        float eq = offq + iq - q;
        #pragma unroll
        for (int u = 0; u < 16; u++) { sP[base + u] += ep; sQ[base + u] += eq; }
        __syncthreads();
        float A0 = sP[255 * 17 + 15];
        float A1 = sQ[255 * 17 + 15];

        float m = -3.0e38f;
        for (int j = tid; j < NN; j += 256) {
            float2 pj = pkz[j];
            float f2j = pj.x;
            int pidx = __float_as_int(pj.y);
            float S = A1 + A0 * f2j - OMA * (sQ[pidx] + f2j * sP[pidx]);
            sS[j] = S;
            m = fmaxf(m, S);
        }
        #pragma unroll
        for (int o = 16; o; o >>= 1) m = fmaxf(m, __shfl_xor_sync(0xffffffffu, m, o));
        __syncthreads();
        if (lane == 0) wsp[wid] = m;
        __syncthreads();
        float mall = wsp[0];
        #pragma unroll
        for (int w = 1; w < 8; w++) mall = fmaxf(mall, wsp[w]);

        float z = 0.f;
        __nv_bfloat162* Wh = (__nv_bfloat162*)(Whi + (size_t)hz * NN * NN + (size_t)i * NN);
        for (int j0 = tid * 2; j0 < NN; j0 += 512) {
            float w0 = __expf(sS[j0] - mall);
            float w1 = __expf(sS[j0 + 1] - mall);
            z += w0 + w1;
            Wh[j0 >> 1] = __nv_bfloat162(__float2bfloat16_rn(w0), __float2bfloat16_rn(w1));
        }
        #pragma unroll
        for (int o = 16; o; o >>= 1) z += __shfl_xor_sync(0xffffffffu, z, o);
        __syncthreads();
        if (lane == 0) wsq[wid] = z;
        __syncthreads();
        if (tid == 0) {
            float zt = 0.f;
            #pragma unroll
            for (int w = 0; w < 8; w++) zt += wsq[w];
            rinv[(size_t)hz * NN + i] = 1.0f / zt;
        }
        __syncthreads();
    }
}

// ---------------- epilogue: 16-row tiles, coalesced optional plane emission ----------------
__global__ void epilogue_k(const float* __restrict__ part, int splits,
                           const float* __restrict__ rinv, float* __restrict__ dst,
                           int ldc, int dstHeadOff, int mode,
                           __nv_bfloat16* __restrict__ phi, __nv_bfloat16* __restrict__ plo) {
    __shared__ float to[16 * 68];
    size_t z = blockIdx.y;
    const float* pz = part + z * (size_t)splits * NN * 64;
    int tid = threadIdx.x;
    int col = tid & 63, rg = tid >> 6;
    int row0 = blockIdx.x * 16;
    #pragma unroll
    for (int i = 0; i < 4; i++) {
        int rl = rg * 4 + i;
        int row = row0 + rl;
        int idx = row * 64 + col;
        float v = 0.f;
        for (int s = 0; s < splits; s++) v += pz[(size_t)s * NN * 64 + idx];
        if (rinv) v *= rinv[z * NN + row];
        if (mode == 1) v = fmaxf(v, 0.f);
        else if (mode == 2) v = (v > 0.f) ? v : expm1f(v);
        dst[(size_t)row * ldc + z * dstHeadOff + col] = v;
        to[rl * 68 + col] = v;
    }
    if (phi) {
        __syncthreads();
        int pcol = tid >> 2, q = tid & 3;
        __nv_bfloat16 hv[4], lv[4];
        #pragma unroll
        for (int i = 0; i < 4; i++) {
            float v = to[(q * 4 + i) * 68 + pcol];
            hv[i] = __float2bfloat16_rn(v);
            lv[i] = __float2bfloat16_rn(v - __bfloat162float(hv[i]));
        }
        size_t off = (size_t)pcol * NN + row0 + q * 4;
        *(__nv_bfloat162*)&phi[off]     = __nv_bfloat162(hv[0], hv[1]);
        *(__nv_bfloat162*)&phi[off + 2] = __nv_bfloat162(hv[2], hv[3]);
        *(__nv_bfloat162*)&plo[off]     = __nv_bfloat162(lv[0], lv[1]);
        *(__nv_bfloat162*)&plo[off + 2] = __nv_bfloat162(lv[2], lv[3]);
    }
}

__global__ void epi32(const float* __restrict__ part, float* __restrict__ dst) {
    int idx = blockIdx.x * 256 + threadIdx.x;
    int row = idx >> 5, col = idx & 31;
    float v = 0.f;
    for (int s = 0; s < 8; s++) v += part[(size_t)s * NN * 64 + (size_t)row * 64 + col];
    dst[idx] = v;
}

// ---------------- host orchestration ----------------
struct Bufs {
    __nv_bfloat16 *Whi, *ahi, *alo, *xhi, *xlo, *bhi, *blo;
    float *cat, *x1, *tb, *h1, *part, *f1, *f2, *f1s, *rinv;
    int *pi;
    float2 *pk;
};

static void run_gat_single(const float* adjc, const float* F,
                           const float* Hm, const float* av,
                           float* dst, const Bufs& b, bool planes) {
    prep<256, 64, true><<<dim3(NN / 16, 1), 256>>>(F, Hm, 0, av, 0,
                                                   b.bhi, b.blo, b.f1, b.f2);
    sortk<<<1, 1024, RDXS>>>(b.f1, b.f2, b.f1s, b.pi, b.pk);
    phaseA<<<NN, 256, PASMEM>>>(adjc, b.pi, b.f1s, b.pk, b.Whi, b.rinv, 1);
    mm_mma<<<dim3(32, 8, 1), 256, MMSMEM>>>(b.Whi, nullptr, b.bhi, b.blo, b.part,
                                            0, 0, 2);
    epilogue_k<<<dim3(NN / 16, 1), 256>>>(b.part, 8, b.rinv, dst, 64, 0, 2,
                                          planes ? b.bhi : nullptr,
                                          planes ? b.blo : nullptr);
}

static void run_heads(const float* adjc, const float* prev,
                      const float* HmBase, const float* avBase, const Bufs& b) {
    prep<64, 64, true><<<dim3(NN / 16, NH), 256>>>(prev, HmBase, 64 * 64, avBase, 128,
                                                   b.bhi, b.blo, b.f1, b.f2);
    sortk<<<NH, 1024, RDXS>>>(b.f1, b.f2, b.f1s, b.pi, b.pk);
    // internal head loop: one block per row, adj row loaded once for all 4 heads
    phaseA<<<NN, 256, PASMEM>>>(adjc, b.pi, b.f1s, b.pk, b.Whi, b.rinv, NH);
    mm_mma<<<dim3(32, 2, NH), 256, MMSMEM>>>(b.Whi, nullptr, b.bhi, b.blo, b.part,
                                             (size_t)NN * NN, (size_t)64 * NN, 2);
    epilogue_k<<<dim3(NN / 16, NH), 256>>>(b.part, 2, b.rinv, b.cat, 256, 64, 2,
                                           nullptr, nullptr);
}

extern "C" void kernel_launch(void* const* d_in, const int* in_sizes, int n_in,
                              void* d_out, int out_size) {
    const float* x      = (const float*)d_in[0];
    const float* adj    = (const float*)d_in[1];
    const float* w_init = (const float*)d_in[2];
    const float* head_H = (const float*)d_in[3];
    const float* head_a = (const float*)d_in[4];
    const float* out_H  = (const float*)d_in[5];
    const float* out_a  = (const float*)d_in[6];
    const float* l2_w   = (const float*)d_in[7];
    float* out = (float*)d_out;

    cudaFuncSetAttribute(phaseA, cudaFuncAttributeMaxDynamicSharedMemorySize, PASMEM);
    cudaFuncSetAttribute(mm_mma, cudaFuncAttributeMaxDynamicSharedMemorySize, MMSMEM);
    cudaFuncSetAttribute(sortk, cudaFuncAttributeMaxDynamicSharedMemorySize, RDXS);

    static cudaStream_t s2 = nullptr;
    static cudaEvent_t evF = nullptr, evJ = nullptr;
    if (!s2) {
        cudaStreamCreateWithFlags(&s2, cudaStreamNonBlocking);
        cudaEventCreateWithFlags(&evF, cudaEventDisableTiming);
        cudaEventCreateWithFlags(&evJ, cudaEventDisableTiming);
    }

    Bufs b;
    cudaGetSymbolAddress((void**)&b.Whi, g_Whi);
    cudaGetSymbolAddress((void**)&b.ahi, g_ahi);
    cudaGetSymbolAddress((void**)&b.alo, g_alo);
    cudaGetSymbolAddress((void**)&b.xhi, g_xhi);
    cudaGetSymbolAddress((void**)&b.xlo, g_xlo);
    cudaGetSymbolAddress((void**)&b.bhi, g_bhi);
    cudaGetSymbolAddress((void**)&b.blo, g_blo);
    cudaGetSymbolAddress((void**)&b.cat, g_cat);
    cudaGetSymbolAddress((void**)&b.x1, g_x1);
    cudaGetSymbolAddress((void**)&b.tb, g_tb);
    cudaGetSymbolAddress((void**)&b.h1, g_h1);
    cudaGetSymbolAddress((void**)&b.part, g_part);
    cudaGetSymbolAddress((void**)&b.f1, g_f1);
    cudaGetSymbolAddress((void**)&b.f2, g_f2);
    cudaGetSymbolAddress((void**)&b.f1s, g_f1s);
    cudaGetSymbolAddress((void**)&b.rinv, g_rinv);
    cudaGetSymbolAddress((void**)&b.pi, g_pi);
    cudaGetSymbolAddress((void**)&b.pk, g_pk);

    // fork: input-only pair conversions overlap with cell-0/1 GAT chain
    cudaEventRecord(evF, 0);
    cudaStreamWaitEvent(s2, evF, 0);
    cpair<<<4096, 256, 0, s2>>>((const float4*)(x + (size_t)NN * NN), b.xhi, b.xlo);
    cpair<<<4096, 256, 0, s2>>>((const float4*)(adj + (size_t)NN * NN), b.ahi, b.alo);
    cudaEventRecord(evJ, s2);

    const float* prev = w_init;
    for (int i = 0; i < 2; i++) {
        const float* adjc = adj + (size_t)i * NN * NN;
        run_heads(adjc, prev, head_H + (size_t)i * NH * 64 * 64,
                  head_a + (size_t)i * NH * 128, b);
        run_gat_single(adjc, b.cat, out_H + (size_t)i * 256 * 64,
                       out_a + (size_t)i * 128, b.x1, b, i == 1);
        prev = b.x1;

        if (i == 1) {
            cudaStreamWaitEvent(0, evJ, 0);
            // tb = x @ x1 (x1 planes already in bhi/blo); emit tb planes
            mm_mma<<<dim3(32, 8, 1), 256, MMSMEM>>>(b.xhi, b.xlo, b.bhi, b.blo,
                                                    b.part, 0, 0, 3);
            epilogue_k<<<dim3(NN / 16, 1), 256>>>(b.part, 8, nullptr, b.tb, 64, 0, 0,
                                                  b.bhi, b.blo);
            // h1 = relu(adj @ tb)
            mm_mma<<<dim3(32, 8, 1), 256, MMSMEM>>>(b.ahi, b.alo, b.bhi, b.blo,
                                                    b.part, 0, 0, 3);
            epilogue_k<<<dim3(NN / 16, 1), 256>>>(b.part, 8, nullptr, b.h1, 64, 0, 1,
                                                  nullptr, nullptr);
            // u = h1 @ l2_w -> planes directly (zero-padded to 64)
            prep<64, 32, false><<<dim3(NN / 16, 1), 256>>>(b.h1, l2_w + (size_t)i * 64 * 32,
                                                           0, nullptr, 0,
                                                           b.bhi, b.blo, nullptr, nullptr);
            // out = adj @ u
            mm_mma<<<dim3(32, 8, 1), 256, MMSMEM>>>(b.ahi, b.alo, b.bhi, b.blo,
                                                    b.part, 0, 0, 3);
            epi32<<<NN * 32 / 256, 256>>>(b.part, out);
        }
    }
}

// round 12
// speedup vs baseline: 1.2967x; 1.0630x over previous
#include <cuda_runtime.h>
#include <cuda_bf16.h>
#include <cuda_fp16.h>
#include <math.h>
#include <stdint.h>

#define NN 4096
#define DD 64
#define OMA 0.8f   // 1 - alpha(0.2)
#define NH 4

// ---------------- scratch (device globals; allocation-free) ----------------
__device__ __half g_Whi[(size_t)NH * NN * NN];          // attention weights (fp16)
__device__ __nv_bfloat16 g_ahi[(size_t)NN * NN];
__device__ __nv_bfloat16 g_alo[(size_t)NN * NN];
__device__ __nv_bfloat16 g_xhi[(size_t)NN * NN];
__device__ __nv_bfloat16 g_xlo[(size_t)NN * NN];
__device__ __half g_bh16[NH * 64 * NN];                 // h planes (fp16, attention B)
__device__ __nv_bfloat16 g_bhi[64 * NN];                // tail B planes (bf16 pair)
__device__ __nv_bfloat16 g_blo[64 * NN];
__device__ float g_cat[NN * NH * DD];
__device__ float g_x1[NN * DD];
__device__ float g_tb[NN * DD];
__device__ float g_h1[NN * DD];
__device__ float g_part[8 * NN * DD];
__device__ float g_f1[NH * NN], g_f2[NH * NN], g_f1s[NH * NN], g_rinv[NH * NN];
__device__ int   g_pi[NH * NN];
__device__ float2 g_pk[NH * NN];

// ================= portable (sm_80+) PTX helpers =================
__device__ __forceinline__ uint32_t smem_u32(const void* p) {
    uint32_t a;
    asm("{ .reg .u64 t; cvta.to.shared.u64 t, %1; cvt.u32.u64 %0, t; }"
        : "=r"(a) : "l"(p));
    return a;
}

#define CP16(dst, src) \
    asm volatile("cp.async.cg.shared.global [%0], [%1], 16;" :: "r"(dst), "l"(src))
#define CP_COMMIT() asm volatile("cp.async.commit_group;" ::: "memory")
#define CP_WAIT0() asm volatile("cp.async.wait_group 0;" ::: "memory")
#define CP_WAIT1() asm volatile("cp.async.wait_group 1;" ::: "memory")

__device__ __forceinline__ void ldm4(uint32_t* r, uint32_t addr) {
    asm volatile("ldmatrix.sync.aligned.m8n8.x4.shared.b16 {%0,%1,%2,%3}, [%4];"
        : "=r"(r[0]), "=r"(r[1]), "=r"(r[2]), "=r"(r[3]) : "r"(addr));
}

__device__ __forceinline__ void mma_bf16(float* d, const uint32_t* a, const uint32_t* b) {
    asm volatile("mma.sync.aligned.m16n8k16.row.col.f32.bf16.bf16.f32 "
        "{%0,%1,%2,%3}, {%4,%5,%6,%7}, {%8,%9}, {%0,%1,%2,%3};"
        : "+f"(d[0]), "+f"(d[1]), "+f"(d[2]), "+f"(d[3])
        : "r"(a[0]), "r"(a[1]), "r"(a[2]), "r"(a[3]), "r"(b[0]), "r"(b[1]));
}

__device__ __forceinline__ void mma_f16(float* d, const uint32_t* a, const uint32_t* b) {
    asm volatile("mma.sync.aligned.m16n8k16.row.col.f32.f16.f16.f32 "
        "{%0,%1,%2,%3}, {%4,%5,%6,%7}, {%8,%9}, {%0,%1,%2,%3};"
        : "+f"(d[0]), "+f"(d[1]), "+f"(d[2]), "+f"(d[3])
        : "r"(a[0]), "r"(a[1]), "r"(a[2]), "r"(a[3]), "r"(b[0]), "r"(b[1]));
}

__device__ __forceinline__ uint32_t swz(uint32_t bo) { return bo ^ ((bo >> 3) & 0x70); }

// ================= tensor-core big matmul =================
// H16=true : fp16 mma, single A plane x single B plane (attention)
// H16=false: bf16 mma, pair-split (AhBh + AhBl + AlBh) (tail)
#define O_AH 0
#define O_AL 16384
#define O_BH 32768
#define O_BL 40960
#define STG  49152
#define MMSMEM (2 * STG)

template<bool H16>
__global__ void __launch_bounds__(256, 2) mm_mma(
        const uint16_t* __restrict__ Ahi, const uint16_t* __restrict__ Alo,
        const uint16_t* __restrict__ Bhi, const uint16_t* __restrict__ Blo,
        float* __restrict__ part, size_t aStr, size_t bStr) {
    extern __shared__ char smem[];
    uint32_t sb = smem_u32(smem);
    int tid = threadIdx.x, wid = tid >> 5, lane = tid & 31;
    int m0 = blockIdx.x * 128;
    int klen = NN / gridDim.y;
    int kbeg = blockIdx.y * klen;
    int nch = klen / 64;
    int wm = wid >> 1, wn = wid & 1;
    size_t zo = (size_t)blockIdx.z;
    const uint16_t* AhiZ = Ahi + zo * aStr;
    const uint16_t* AloZ = Alo ? Alo + zo * aStr : nullptr;
    const uint16_t* BhiZ = Bhi + zo * bStr;
    const uint16_t* BloZ = Blo ? Blo + zo * bStr : nullptr;

    auto load_chunk = [&](int ch) {
        uint32_t base = sb + (uint32_t)(ch & 1) * STG;
        int kc = kbeg + ch * 64;
        int r = tid >> 3, c = tid & 7;
        uint32_t sw = swz((uint32_t)(r * 128 + c * 16));
        #pragma unroll
        for (int i = 0; i < 4; i++)
            CP16(base + O_AH + sw + (uint32_t)i * 4096,
                 AhiZ + (size_t)(m0 + r + i * 32) * NN + kc + c * 8);
        if (!H16) {
            #pragma unroll
            for (int i = 0; i < 4; i++)
                CP16(base + O_AL + sw + (uint32_t)i * 4096,
                     AloZ + (size_t)(m0 + r + i * 32) * NN + kc + c * 8);
        }
        #pragma unroll
        for (int i = 0; i < 2; i++)
            CP16(base + O_BH + sw + (uint32_t)i * 4096,
                 BhiZ + (size_t)(r + i * 32) * NN + kc + c * 8);
        if (!H16) {
            #pragma unroll
            for (int i = 0; i < 2; i++)
                CP16(base + O_BL + sw + (uint32_t)i * 4096,
                     BloZ + (size_t)(r + i * 32) * NN + kc + c * 8);
        }
        CP_COMMIT();
    };

    float acc[2][4][4] = {};
    load_chunk(0);
    for (int ch = 0; ch < nch; ch++) {
        if (ch + 1 < nch) { load_chunk(ch + 1); CP_WAIT1(); }
        else               { CP_WAIT0(); }
        __syncthreads();
        uint32_t base = sb + (uint32_t)(ch & 1) * STG;
        #pragma unroll
        for (int ks = 0; ks < 4; ks++) {
            uint32_t ah[2][4], al[2][4], bh[8], bl[8];
            #pragma unroll
            for (int mt = 0; mt < 2; mt++) {
                int row = wm * 32 + mt * 16 + (lane & 7) + ((lane >> 3) & 1) * 8;
                int koff = ks * 32 + (lane >> 4) * 16;
                uint32_t sw = swz((uint32_t)(row * 128 + koff));
                ldm4(ah[mt], base + O_AH + sw);
                if (!H16) ldm4(al[mt], base + O_AL + sw);
            }
            #pragma unroll
            for (int half = 0; half < 2; half++) {
                int g = lane >> 3;
                int n = wn * 32 + half * 16 + (g >> 1) * 8 + (lane & 7);
                int koff = ks * 32 + (g & 1) * 16;
                uint32_t sw = swz((uint32_t)(n * 128 + koff));
                ldm4(bh + half * 4, base + O_BH + sw);
                if (!H16) ldm4(bl + half * 4, base + O_BL + sw);
            }
            #pragma unroll
            for (int mt = 0; mt < 2; mt++)
                #pragma unroll
                for (int nt = 0; nt < 4; nt++) {
                    if (H16) {
                        mma_f16(acc[mt][nt], ah[mt], bh + nt * 2);
                    } else {
                        mma_bf16(acc[mt][nt], ah[mt], bh + nt * 2);
                        mma_bf16(acc[mt][nt], ah[mt], bl + nt * 2);
                        mma_bf16(acc[mt][nt], al[mt], bh + nt * 2);
                    }
                }
        }
        __syncthreads();
    }

    float* cp = part + ((size_t)blockIdx.z * gridDim.y + blockIdx.y) * (NN * 64);
    #pragma unroll
    for (int mt = 0; mt < 2; mt++)
        #pragma unroll
        for (int nt = 0; nt < 4; nt++) {
            int row = m0 + wm * 32 + mt * 16 + (lane >> 2);
            int col = wn * 32 + nt * 8 + (lane & 3) * 2;
            *(float2*)&cp[(size_t)row * 64 + col] =
                make_float2(acc[mt][nt][0], acc[mt][nt][1]);
            *(float2*)&cp[(size_t)(row + 8) * 64 + col] =
                make_float2(acc[mt][nt][2], acc[mt][nt][3]);
        }
}

// ---------------- fp32 -> bf16 pair planes (big matrices) ----------------
__global__ void cpair(const float4* __restrict__ in, __nv_bfloat16* __restrict__ hi,
                      __nv_bfloat16* __restrict__ lo) {
    size_t n4 = (size_t)NN * NN / 4;
    for (size_t i = (size_t)blockIdx.x * 256 + threadIdx.x; i < n4;
         i += (size_t)gridDim.x * 256) {
        float4 v = in[i];
        __nv_bfloat16 h0 = __float2bfloat16_rn(v.x);
        __nv_bfloat16 h1 = __float2bfloat16_rn(v.y);
        __nv_bfloat16 h2 = __float2bfloat16_rn(v.z);
        __nv_bfloat16 h3 = __float2bfloat16_rn(v.w);
        __nv_bfloat162* H = (__nv_bfloat162*)hi;
        __nv_bfloat162* L = (__nv_bfloat162*)lo;
        H[2 * i]     = __nv_bfloat162(h0, h1);
        H[2 * i + 1] = __nv_bfloat162(h2, h3);
        L[2 * i]     = __nv_bfloat162(__float2bfloat16_rn(v.x - __bfloat162float(h0)),
                                      __float2bfloat16_rn(v.y - __bfloat162float(h1)));
        L[2 * i + 1] = __nv_bfloat162(__float2bfloat16_rn(v.z - __bfloat162float(h2)),
                                      __float2bfloat16_rn(v.w - __bfloat162float(h3)));
    }
}

// ---------------- prep: h = A@B, f1/f2, coalesced transposed planes ----------------
// H16=true: single fp16 plane (attention h); H16=false: bf16 pair planes (tail u)
template<int K, int NC, bool FV, bool H16>
__global__ void prep(const float* __restrict__ A, const float* __restrict__ B, int bStr,
                     const float* __restrict__ av, int aStr,
                     void* __restrict__ phiV, void* __restrict__ ploV,
                     float* __restrict__ f1, float* __restrict__ f2) {
    constexpr int NOUT = 16 * NC / 256;
    __shared__ float As[16 * 64];
    __shared__ float Bs[64 * NC];
    __shared__ float to[16 * 68];
    size_t z = blockIdx.y;
    const float* Bh = B + z * (size_t)bStr;
    int tid = threadIdx.x;
    int col = tid % NC, rgrp = tid / NC;
    int row0 = blockIdx.x * 16;
    float acc[NOUT];
    #pragma unroll
    for (int i = 0; i < NOUT; i++) acc[i] = 0.f;

    for (int kc = 0; kc < K; kc += 64) {
        for (int e = tid; e < 64 * NC; e += 256)
            Bs[e] = Bh[(size_t)(kc + e / NC) * NC + (e % NC)];
        for (int e = tid; e < 16 * 64; e += 256)
            As[e] = A[(size_t)(row0 + (e >> 6)) * K + kc + (e & 63)];
        __syncthreads();
        #pragma unroll 16
        for (int k = 0; k < 64; k++) {
            float bv = Bs[k * NC + col];
            #pragma unroll
            for (int i = 0; i < NOUT; i++)
                acc[i] += As[(rgrp * NOUT + i) * 64 + k] * bv;
        }
        __syncthreads();
    }
    #pragma unroll
    for (int i = 0; i < NOUT; i++)
        to[(rgrp * NOUT + i) * 68 + col] = acc[i];
    __syncthreads();

    {
        int pcol = tid >> 2, q = tid & 3;
        size_t off = z * (size_t)64 * NN + (size_t)pcol * NN + row0 + q * 4;
        if (H16) {
            __half* phi = (__half*)phiV;
            __half hv[4];
            #pragma unroll
            for (int i = 0; i < 4; i++) {
                float v = (pcol < NC) ? to[(q * 4 + i) * 68 + pcol] : 0.f;
                hv[i] = __float2half_rn(v);
            }
            *(__half2*)&phi[off]     = __halves2half2(hv[0], hv[1]);
            *(__half2*)&phi[off + 2] = __halves2half2(hv[2], hv[3]);
        } else {
            __nv_bfloat16* phi = (__nv_bfloat16*)phiV;
            __nv_bfloat16* plo = (__nv_bfloat16*)ploV;
            __nv_bfloat16 hv[4], lv[4];
            #pragma unroll
            for (int i = 0; i < 4; i++) {
                float v = (pcol < NC) ? to[(q * 4 + i) * 68 + pcol] : 0.f;
                hv[i] = __float2bfloat16_rn(v);
                lv[i] = __float2bfloat16_rn(v - __bfloat162float(hv[i]));
            }
            *(__nv_bfloat162*)&phi[off]     = __nv_bfloat162(hv[0], hv[1]);
            *(__nv_bfloat162*)&phi[off + 2] = __nv_bfloat162(hv[2], hv[3]);
            *(__nv_bfloat162*)&plo[off]     = __nv_bfloat162(lv[0], lv[1]);
            *(__nv_bfloat162*)&plo[off + 2] = __nv_bfloat162(lv[2], lv[3]);
        }
    }

    if (FV) {
        const float* az = av + z * (size_t)aStr;
        int w = tid >> 5, lane = tid & 31;
        #pragma unroll
        for (int rr = 0; rr < 2; rr++) {
            int r = w * 2 + rr;
            float h0 = to[r * 68 + lane], h1 = to[r * 68 + lane + 32];
            float v1 = h0 * az[lane] + h1 * az[lane + 32];
            float v2 = h0 * az[64 + lane] + h1 * az[96 + lane];
            #pragma unroll
            for (int o = 16; o; o >>= 1) {
                v1 += __shfl_down_sync(0xffffffffu, v1, o);
                v2 += __shfl_down_sync(0xffffffffu, v2, o);
            }
            if (lane == 0) {
                f1[z * NN + row0 + r] = v1;
                f2[z * NN + row0 + r] = v2;
            }
        }
    }
}

// ---------------- radix sort: 3x8-bit passes over top-24 key bits + fused search ----------------
#define RDXS (16384 + 16384 + 8192 + 8192 + 65536 + 4096 + 1024)

__global__ void __launch_bounds__(1024, 1) sortk(
        const float* __restrict__ f1, const float* __restrict__ f2g,
        float* __restrict__ f1s, int* __restrict__ piout, float2* __restrict__ pk) {
    extern __shared__ char rs[];
    uint32_t* keyA = (uint32_t*)rs;
    uint32_t* keyB = (uint32_t*)(rs + 16384);
    uint16_t* valA = (uint16_t*)(rs + 32768);
    uint16_t* valB = (uint16_t*)(rs + 40960);
    uint16_t* cnt  = (uint16_t*)(rs + 49152);
    uint32_t* psum = (uint32_t*)(rs + 49152 + 65536);
    uint32_t* ebase = psum + 1024;
    __shared__ uint32_t wsum[8];

    int tid = threadIdx.x;
    int lane = tid & 31, wid = tid >> 5;
    size_t hz = blockIdx.x;
    const float* src = f1 + hz * NN;

    for (int i = tid; i < NN; i += 1024) {
        uint32_t b = __float_as_uint(src[i]);
        keyA[i] = b ^ ((b & 0x80000000u) ? 0xFFFFFFFFu : 0x80000000u);
        valA[i] = (uint16_t)i;
    }
    __syncthreads();

    uint32_t* KA = keyA; uint32_t* KB = keyB;
    uint16_t* VA = valA; uint16_t* VB = valB;
    int dg = tid & 255, q = tid >> 8;

    #pragma unroll
    for (int shift = 8; shift < 32; shift += 8) {
        uint32_t k[4], d[4]; uint16_t v[4];
        #pragma unroll
        for (int s = 0; s < 4; s++) {
            k[s] = KA[s * 1024 + tid];
            v[s] = VA[s * 1024 + tid];
            d[s] = (k[s] >> shift) & 255u;
        }
        uint32_t* cz = (uint32_t*)cnt;
        #pragma unroll
        for (int i = 0; i < 16; i++) cz[i * 1024 + tid] = 0;
        __syncthreads();
        #pragma unroll
        for (int s = 0; s < 4; s++) {
            uint32_t mask = __match_any_sync(0xffffffffu, d[s]);
            if ((mask & ((1u << lane) - 1)) == 0)
                cnt[(s * 32 + wid) * 256 + d[s]] = (uint16_t)__popc(mask);
        }
        __syncthreads();
        {
            uint32_t part_ = 0;
            #pragma unroll
            for (int g = 0; g < 32; g++)
                part_ += (uint32_t)cnt[(q * 32 + g) * 256 + dg];
            psum[q * 256 + dg] = part_;
        }
        __syncthreads();
        uint32_t tot = 0, inc = 0;
        if (tid < 256) {
            tot = psum[tid] + psum[256 + tid] + psum[512 + tid] + psum[768 + tid];
            inc = tot;
            #pragma unroll
            for (int o = 1; o < 32; o <<= 1) {
                uint32_t t = __shfl_up_sync(0xffffffffu, inc, o);
                if (lane >= o) inc += t;
            }
            if (lane == 31) wsum[wid] = inc;
        }
        __syncthreads();
        if (tid < 256) {
            uint32_t off = 0;
            #pragma unroll
            for (int w = 0; w < 8; w++) if (w < wid) off += wsum[w];
            ebase[tid] = off + inc - tot;
        }
        __syncthreads();
        {
            uint32_t run = ebase[dg];
            #pragma unroll
            for (int qq = 0; qq < 3; qq++) if (qq < q) run += psum[qq * 256 + dg];
            #pragma unroll
            for (int b8 = 0; b8 < 4; b8++) {
                uint32_t c[8];
                #pragma unroll
                for (int g = 0; g < 8; g++)
                    c[g] = cnt[(q * 32 + b8 * 8 + g) * 256 + dg];
                #pragma unroll
                for (int g = 0; g < 8; g++) {
                    cnt[(q * 32 + b8 * 8 + g) * 256 + dg] = (uint16_t)run;
                    run += c[g];
                }
            }
        }
        __syncthreads();
        #pragma unroll
        for (int s = 0; s < 4; s++) {
            uint32_t mask = __match_any_sync(0xffffffffu, d[s]);
            uint32_t rank = __popc(mask & ((1u << lane) - 1));
            uint32_t pos = (uint32_t)cnt[(s * 32 + wid) * 256 + d[s]] + rank;
            KB[pos] = k[s];
            VB[pos] = v[s];
        }
        __syncthreads();
        uint32_t* tk = KA; KA = KB; KB = tk;
        uint16_t* tv = VA; VA = VB; VB = tv;
    }
    float* dk = f1s + hz * NN;
    int* di = piout + hz * NN;
    for (int i = tid; i < NN; i += 1024) {
        uint32_t u = KA[i];
        uint32_t b = (u & 0x80000000u) ? (u ^ 0x80000000u) : ~u;
        dk[i] = __uint_as_float(b);
        di[i] = (int)VA[i];
    }
    for (int j = tid; j < NN; j += 1024) {
        float f2j = f2g[hz * NN + j];
        uint32_t tb = __float_as_uint(-f2j);
        uint32_t tk24 = (tb ^ ((tb & 0x80000000u) ? 0xFFFFFFFFu : 0x80000000u)) >> 8;
        int lo = 0, hi = NN;
        while (lo < hi) {
            int mid = (lo + hi) >> 1;
            if ((KA[mid] >> 8) <= tk24) lo = mid + 1; else hi = mid;
        }
        int pidx = 16;
        if (lo > 0) pidx = ((lo - 1) >> 4) * 17 + ((lo - 1) & 15);
        pk[hz * NN + j] = make_float2(f2j, __int_as_float(pidx));
    }
}

// ---------------- phase A: all heads per block (internal loop), fp16 W ----------------
#define PASMEM (16896 * 4)

__global__ void phaseA(const float* __restrict__ adj, const int* __restrict__ pi,
                       const float* __restrict__ f1s, const float2* __restrict__ pk,
                       __half* __restrict__ Whi,
                       float* __restrict__ rinv, int nheads) {
    extern __shared__ float sm[];
    float* arow = sm;
    float* sP = sm + 4096;
    float* sQ = sP + 4352;
    float* sS = sQ + 4352;
    __shared__ float wsp[8], wsq[8];

    int i = blockIdx.x, tid = threadIdx.x;
    unsigned lane = tid & 31, wid = tid >> 5;

    const float* Arow = adj + (size_t)i * NN;
    for (int r = tid; r < NN; r += 256) arow[r] = Arow[r];
    if (tid == 0) { sP[16] = 0.f; sQ[16] = 0.f; }
    __syncthreads();

    for (int hz = 0; hz < nheads; hz++) {
        const int* piz = pi + (size_t)hz * NN;
        const float* f1z = f1s + (size_t)hz * NN;
        const float2* pkz = pk + (size_t)hz * NN;

        for (int r = tid; r < NN; r += 256) {
            float a = arow[piz[r]];
            int pr = ((r >> 4) * 17) + (r & 15);
            sP[pr] = a;
            sQ[pr] = a * f1z[r];
        }
        __syncthreads();
        int base = tid * 17;
        float p = 0.f, q = 0.f;
        #pragma unroll
        for (int u = 0; u < 16; u++) {
            p += sP[base + u]; sP[base + u] = p;
            q += sQ[base + u]; sQ[base + u] = q;
        }
        float ip = p, iq = q;
        #pragma unroll
        for (int o = 1; o < 32; o <<= 1) {
            float tp = __shfl_up_sync(0xffffffffu, ip, o);
            float tq = __shfl_up_sync(0xffffffffu, iq, o);
            if (lane >= o) { ip += tp; iq += tq; }
        }
        if (lane == 31) { wsp[wid] = ip; wsq[wid] = iq; }
        __syncthreads();
        float offp = 0.f, offq = 0.f;
        for (int w = 0; w < 8; w++)
            if (w < (int)wid) { offp += wsp[w]; offq += wsq[w]; }
        float ep = offp + ip - p;
        float eq = offq + iq - q;
        #pragma unroll
        for (int u = 0; u < 16; u++) { sP[base + u] += ep; sQ[base + u] += eq; }
        __syncthreads();
        float A0 = sP[255 * 17 + 15];
        float A1 = sQ[255 * 17 + 15];

        float m = -3.0e38f;
        for (int j = tid; j < NN; j += 256) {
            float2 pj = pkz[j];
            float f2j = pj.x;
            int pidx = __float_as_int(pj.y);
            float S = A1 + A0 * f2j - OMA * (sQ[pidx] + f2j * sP[pidx]);
            sS[j] = S;
            m = fmaxf(m, S);
        }
        #pragma unroll
        for (int o = 16; o; o >>= 1) m = fmaxf(m, __shfl_xor_sync(0xffffffffu, m, o));
        __syncthreads();
        if (lane == 0) wsp[wid] = m;
        __syncthreads();
        float mall = wsp[0];
        #pragma unroll
        for (int w = 1; w < 8; w++) mall = fmaxf(mall, wsp[w]);

        float z = 0.f;
        __half2* Wh = (__half2*)(Whi + (size_t)hz * NN * NN + (size_t)i * NN);
        for (int j0 = tid * 2; j0 < NN; j0 += 512) {
            float w0 = __expf(sS[j0] - mall);
            float w1 = __expf(sS[j0 + 1] - mall);
            z += w0 + w1;
            Wh[j0 >> 1] = __halves2half2(__float2half_rn(w0), __float2half_rn(w1));
        }
        #pragma unroll
        for (int o = 16; o; o >>= 1) z += __shfl_xor_sync(0xffffffffu, z, o);
        __syncthreads();
        if (lane == 0) wsq[wid] = z;
        __syncthreads();
        if (tid == 0) {
            float zt = 0.f;
            #pragma unroll
            for (int w = 0; w < 8; w++) zt += wsq[w];
            rinv[(size_t)hz * NN + i] = 1.0f / zt;
        }
        __syncthreads();
    }
}

// ---------------- epilogue: 16-row tiles, coalesced optional bf16 plane emission ----------------
__global__ void epilogue_k(const float* __restrict__ part, int splits,
                           const float* __restrict__ rinv, float* __restrict__ dst,
                           int ldc, int dstHeadOff, int mode,
                           __nv_bfloat16* __restrict__ phi, __nv_bfloat16* __restrict__ plo) {
    __shared__ float to[16 * 68];
    size_t z = blockIdx.y;
    const float* pz = part + z * (size_t)splits * NN * 64;
    int tid = threadIdx.x;
    int col = tid & 63, rg = tid >> 6;
    int row0 = blockIdx.x * 16;
    #pragma unroll
    for (int i = 0; i < 4; i++) {
        int rl = rg * 4 + i;
        int row = row0 + rl;
        int idx = row * 64 + col;
        float v = 0.f;
        for (int s = 0; s < splits; s++) v += pz[(size_t)s * NN * 64 + idx];
        if (rinv) v *= rinv[z * NN + row];
        if (mode == 1) v = fmaxf(v, 0.f);
        else if (mode == 2) v = (v > 0.f) ? v : expm1f(v);
        dst[(size_t)row * ldc + z * dstHeadOff + col] = v;
        to[rl * 68 + col] = v;
    }
    if (phi) {
        __syncthreads();
        int pcol = tid >> 2, q = tid & 3;
        __nv_bfloat16 hv[4], lv[4];
        #pragma unroll
        for (int i = 0; i < 4; i++) {
            float v = to[(q * 4 + i) * 68 + pcol];
            hv[i] = __float2bfloat16_rn(v);
            lv[i] = __float2bfloat16_rn(v - __bfloat162float(hv[i]));
        }
        size_t off = (size_t)pcol * NN + row0 + q * 4;
        *(__nv_bfloat162*)&phi[off]     = __nv_bfloat162(hv[0], hv[1]);
        *(__nv_bfloat162*)&phi[off + 2] = __nv_bfloat162(hv[2], hv[3]);
        *(__nv_bfloat162*)&plo[off]     = __nv_bfloat162(lv[0], lv[1]);
        *(__nv_bfloat162*)&plo[off + 2] = __nv_bfloat162(lv[2], lv[3]);
    }
}

__global__ void epi32(const float* __restrict__ part, float* __restrict__ dst) {
    int idx = blockIdx.x * 256 + threadIdx.x;
    int row = idx >> 5, col = idx & 31;
    float v = 0.f;
    for (int s = 0; s < 8; s++) v += part[(size_t)s * NN * 64 + (size_t)row * 64 + col];
    dst[idx] = v;
}

// ---------------- host orchestration ----------------
struct Bufs {
    uint16_t *Whi, *ahi, *alo, *xhi, *xlo, *bh16, *bhi, *blo;
    float *cat, *x1, *tb, *h1, *part, *f1, *f2, *f1s, *rinv;
    int *pi;
    float2 *pk;
};

static void run_gat_single(const float* adjc, const float* F,
                           const float* Hm, const float* av,
                           float* dst, const Bufs& b, bool planes) {
    prep<256, 64, true, true><<<dim3(NN / 16, 1), 256>>>(F, Hm, 0, av, 0,
                                                         b.bh16, nullptr, b.f1, b.f2);
    sortk<<<1, 1024, RDXS>>>(b.f1, b.f2, b.f1s, b.pi, b.pk);
    phaseA<<<NN, 256, PASMEM>>>(adjc, b.pi, b.f1s, b.pk, (__half*)b.Whi, b.rinv, 1);
    mm_mma<true><<<dim3(32, 8, 1), 256, MMSMEM>>>(b.Whi, nullptr, b.bh16, nullptr,
                                                  b.part, 0, 0);
    epilogue_k<<<dim3(NN / 16, 1), 256>>>(b.part, 8, b.rinv, dst, 64, 0, 2,
                                          planes ? (__nv_bfloat16*)b.bhi : nullptr,
                                          planes ? (__nv_bfloat16*)b.blo : nullptr);
}

static void run_heads(const float* adjc, const float* prev,
                      const float* HmBase, const float* avBase, const Bufs& b) {
    prep<64, 64, true, true><<<dim3(NN / 16, NH), 256>>>(prev, HmBase, 64 * 64,
                                                         avBase, 128,
                                                         b.bh16, nullptr, b.f1, b.f2);
    sortk<<<NH, 1024, RDXS>>>(b.f1, b.f2, b.f1s, b.pi, b.pk);
    phaseA<<<NN, 256, PASMEM>>>(adjc, b.pi, b.f1s, b.pk, (__half*)b.Whi, b.rinv, NH);
    mm_mma<true><<<dim3(32, 2, NH), 256, MMSMEM>>>(b.Whi, nullptr, b.bh16, nullptr,
                                                   b.part, (size_t)NN * NN,
                                                   (size_t)64 * NN);
    epilogue_k<<<dim3(NN / 16, NH), 256>>>(b.part, 2, b.rinv, b.cat, 256, 64, 2,
                                           nullptr, nullptr);
}

extern "C" void kernel_launch(void* const* d_in, const int* in_sizes, int n_in,
                              void* d_out, int out_size) {
    const float* x      = (const float*)d_in[0];
    const float* adj    = (const float*)d_in[1];
    const float* w_init = (const float*)d_in[2];
    const float* head_H = (const float*)d_in[3];
    const float* head_a = (const float*)d_in[4];
    const float* out_H  = (const float*)d_in[5];
    const float* out_a  = (const float*)d_in[6];
    const float* l2_w   = (const float*)d_in[7];
    float* out = (float*)d_out;

    cudaFuncSetAttribute(phaseA, cudaFuncAttributeMaxDynamicSharedMemorySize, PASMEM);
    cudaFuncSetAttribute(mm_mma<true>, cudaFuncAttributeMaxDynamicSharedMemorySize, MMSMEM);
    cudaFuncSetAttribute(mm_mma<false>, cudaFuncAttributeMaxDynamicSharedMemorySize, MMSMEM);
    cudaFuncSetAttribute(sortk, cudaFuncAttributeMaxDynamicSharedMemorySize, RDXS);

    static cudaStream_t s2 = nullptr;
    static cudaEvent_t evF = nullptr, evJ = nullptr;
    if (!s2) {
        cudaStreamCreateWithFlags(&s2, cudaStreamNonBlocking);
        cudaEventCreateWithFlags(&evF, cudaEventDisableTiming);
        cudaEventCreateWithFlags(&evJ, cudaEventDisableTiming);
    }

    Bufs b;
    cudaGetSymbolAddress((void**)&b.Whi, g_Whi);
    cudaGetSymbolAddress((void**)&b.ahi, g_ahi);
    cudaGetSymbolAddress((void**)&b.alo, g_alo);
    cudaGetSymbolAddress((void**)&b.xhi, g_xhi);
    cudaGetSymbolAddress((void**)&b.xlo, g_xlo);
    cudaGetSymbolAddress((void**)&b.bh16, g_bh16);
    cudaGetSymbolAddress((void**)&b.bhi, g_bhi);
    cudaGetSymbolAddress((void**)&b.blo, g_blo);
    cudaGetSymbolAddress((void**)&b.cat, g_cat);
    cudaGetSymbolAddress((void**)&b.x1, g_x1);
    cudaGetSymbolAddress((void**)&b.tb, g_tb);
    cudaGetSymbolAddress((void**)&b.h1, g_h1);
    cudaGetSymbolAddress((void**)&b.part, g_part);
    cudaGetSymbolAddress((void**)&b.f1, g_f1);
    cudaGetSymbolAddress((void**)&b.f2, g_f2);
    cudaGetSymbolAddress((void**)&b.f1s, g_f1s);
    cudaGetSymbolAddress((void**)&b.rinv, g_rinv);
    cudaGetSymbolAddress((void**)&b.pi, g_pi);
    cudaGetSymbolAddress((void**)&b.pk, g_pk);

    // fork: input-only pair conversions overlap with cell-0/1 GAT chain
    cudaEventRecord(evF, 0);
    cudaStreamWaitEvent(s2, evF, 0);
    cpair<<<4096, 256, 0, s2>>>((const float4*)(x + (size_t)NN * NN),
                                (__nv_bfloat16*)b.xhi, (__nv_bfloat16*)b.xlo);
    cpair<<<4096, 256, 0, s2>>>((const float4*)(adj + (size_t)NN * NN),
                                (__nv_bfloat16*)b.ahi, (__nv_bfloat16*)b.alo);
    cudaEventRecord(evJ, s2);

    const float* prev = w_init;
    for (int i = 0; i < 2; i++) {
        const float* adjc = adj + (size_t)i * NN * NN;
        run_heads(adjc, prev, head_H + (size_t)i * NH * 64 * 64,
                  head_a + (size_t)i * NH * 128, b);
        run_gat_single(adjc, b.cat, out_H + (size_t)i * 256 * 64,
                       out_a + (size_t)i * 128, b.x1, b, i == 1);
        prev = b.x1;

        if (i == 1) {
            cudaStreamWaitEvent(0, evJ, 0);
            // tb = x @ x1 (x1 bf16 planes already in bhi/blo); emit tb planes
            mm_mma<false><<<dim3(32, 8, 1), 256, MMSMEM>>>(b.xhi, b.xlo, b.bhi, b.blo,
                                                           b.part, 0, 0);
            epilogue_k<<<dim3(NN / 16, 1), 256>>>(b.part, 8, nullptr, b.tb, 64, 0, 0,
                                                  (__nv_bfloat16*)b.bhi,
                                                  (__nv_bfloat16*)b.blo);
            // h1 = relu(adj @ tb)
            mm_mma<false><<<dim3(32, 8, 1), 256, MMSMEM>>>(b.ahi, b.alo, b.bhi, b.blo,
                                                           b.part, 0, 0);
            epilogue_k<<<dim3(NN / 16, 1), 256>>>(b.part, 8, nullptr, b.h1, 64, 0, 1,
                                                  nullptr, nullptr);
            // u = h1 @ l2_w -> bf16 pair planes (zero-padded to 64)
            prep<64, 32, false, false><<<dim3(NN / 16, 1), 256>>>(
                b.h1, l2_w + (size_t)i * 64 * 32, 0, nullptr, 0,
                b.bhi, b.blo, nullptr, nullptr);
            // out = adj @ u
            mm_mma<false><<<dim3(32, 8, 1), 256, MMSMEM>>>(b.ahi, b.alo, b.bhi, b.blo,
                                                           b.part, 0, 0);
            epi32<<<NN * 32 / 256, 256>>>(b.part, out);
        }
    }
}

// round 14
// speedup vs baseline: 1.3270x; 1.0234x over previous
#include <cuda_runtime.h>
#include <cuda_bf16.h>
#include <cuda_fp16.h>
#include <math.h>
#include <stdint.h>

#define NN 4096
#define DD 64
#define OMA 0.8f   // 1 - alpha(0.2)
#define NH 4

// ---------------- scratch (device globals; allocation-free) ----------------
__device__ __half g_Whi[(size_t)NH * NN * NN];          // attention weights (fp16)
__device__ __nv_bfloat16 g_ahi[(size_t)NN * NN];
__device__ __nv_bfloat16 g_alo[(size_t)NN * NN];
__device__ __nv_bfloat16 g_xhi[(size_t)NN * NN];
__device__ __nv_bfloat16 g_xlo[(size_t)NN * NN];
__device__ __half g_bh16[NH * 64 * NN];                 // h planes (fp16, attention B)
__device__ __nv_bfloat16 g_bhi[64 * NN];                // tail B planes (bf16 pair)
__device__ __nv_bfloat16 g_blo[64 * NN];
__device__ float g_cat[NN * NH * DD];
__device__ float g_x1[NN * DD];
__device__ float g_tb[NN * DD];
__device__ float g_h1[NN * DD];
__device__ float g_part[8 * NN * DD];
__device__ float g_f1[NH * NN], g_f2[NH * NN], g_f1s[NH * NN], g_rinv[NH * NN];
__device__ int   g_pi[NH * NN];
__device__ float2 g_pk[NH * NN];

// ================= portable (sm_80+) PTX helpers =================
__device__ __forceinline__ uint32_t smem_u32(const void* p) {
    uint32_t a;
    asm("{ .reg .u64 t; cvta.to.shared.u64 t, %1; cvt.u32.u64 %0, t; }"
        : "=r"(a) : "l"(p));
    return a;
}

#define CP16(dst, src) \
    asm volatile("cp.async.cg.shared.global [%0], [%1], 16;" :: "r"(dst), "l"(src))
#define CP_COMMIT() asm volatile("cp.async.commit_group;" ::: "memory")
#define CP_WAIT0() asm volatile("cp.async.wait_group 0;" ::: "memory")
#define CP_WAIT1() asm volatile("cp.async.wait_group 1;" ::: "memory")

__device__ __forceinline__ void ldm4(uint32_t* r, uint32_t addr) {
    asm volatile("ldmatrix.sync.aligned.m8n8.x4.shared.b16 {%0,%1,%2,%3}, [%4];"
        : "=r"(r[0]), "=r"(r[1]), "=r"(r[2]), "=r"(r[3]) : "r"(addr));
}

__device__ __forceinline__ void mma_bf16(float* d, const uint32_t* a, const uint32_t* b) {
    asm volatile("mma.sync.aligned.m16n8k16.row.col.f32.bf16.bf16.f32 "
        "{%0,%1,%2,%3}, {%4,%5,%6,%7}, {%8,%9}, {%0,%1,%2,%3};"
        : "+f"(d[0]), "+f"(d[1]), "+f"(d[2]), "+f"(d[3])
        : "r"(a[0]), "r"(a[1]), "r"(a[2]), "r"(a[3]), "r"(b[0]), "r"(b[1]));
}

__device__ __forceinline__ void mma_f16(float* d, const uint32_t* a, const uint32_t* b) {
    asm volatile("mma.sync.aligned.m16n8k16.row.col.f32.f16.f16.f32 "
        "{%0,%1,%2,%3}, {%4,%5,%6,%7}, {%8,%9}, {%0,%1,%2,%3};"
        : "+f"(d[0]), "+f"(d[1]), "+f"(d[2]), "+f"(d[3])
        : "r"(a[0]), "r"(a[1]), "r"(a[2]), "r"(a[3]), "r"(b[0]), "r"(b[1]));
}

__device__ __forceinline__ uint32_t swz(uint32_t bo) { return bo ^ ((bo >> 3) & 0x70); }

// ================= tensor-core big matmul =================
// H16=true : fp16 mma, single A plane x single B plane (attention)
// H16=false: bf16 mma, pair-split (AhBh + AhBl + AlBh) (tail)
#define O_AH 0
#define O_AL 16384
#define O_BH 32768
#define O_BL 40960
#define STG  49152
#define MMSMEM (2 * STG)

template<bool H16>
__global__ void __launch_bounds__(256, 2) mm_mma(
        const uint16_t* __restrict__ Ahi, const uint16_t* __restrict__ Alo,
        const uint16_t* __restrict__ Bhi, const uint16_t* __restrict__ Blo,
        float* __restrict__ part, size_t aStr, size_t bStr) {
    extern __shared__ char smem[];
    uint32_t sb = smem_u32(smem);
    int tid = threadIdx.x, wid = tid >> 5, lane = tid & 31;
    int m0 = blockIdx.x * 128;
    int klen = NN / gridDim.y;
    int kbeg = blockIdx.y * klen;
    int nch = klen / 64;
    int wm = wid >> 1, wn = wid & 1;
    size_t zo = (size_t)blockIdx.z;
    const uint16_t* AhiZ = Ahi + zo * aStr;
    const uint16_t* AloZ = Alo ? Alo + zo * aStr : nullptr;
    const uint16_t* BhiZ = Bhi + zo * bStr;
    const uint16_t* BloZ = Blo ? Blo + zo * bStr : nullptr;

    auto load_chunk = [&](int ch) {
        uint32_t base = sb + (uint32_t)(ch & 1) * STG;
        int kc = kbeg + ch * 64;
        int r = tid >> 3, c = tid & 7;
        uint32_t sw = swz((uint32_t)(r * 128 + c * 16));
        #pragma unroll
        for (int i = 0; i < 4; i++)
            CP16(base + O_AH + sw + (uint32_t)i * 4096,
                 AhiZ + (size_t)(m0 + r + i * 32) * NN + kc + c * 8);
        if (!H16) {
            #pragma unroll
            for (int i = 0; i < 4; i++)
                CP16(base + O_AL + sw + (uint32_t)i * 4096,
                     AloZ + (size_t)(m0 + r + i * 32) * NN + kc + c * 8);
        }
        #pragma unroll
        for (int i = 0; i < 2; i++)
            CP16(base + O_BH + sw + (uint32_t)i * 4096,
                 BhiZ + (size_t)(r + i * 32) * NN + kc + c * 8);
        if (!H16) {
            #pragma unroll
            for (int i = 0; i < 2; i++)
                CP16(base + O_BL + sw + (uint32_t)i * 4096,
                     BloZ + (size_t)(r + i * 32) * NN + kc + c * 8);
        }
        CP_COMMIT();
    };

    float acc[2][4][4] = {};
    load_chunk(0);
    for (int ch = 0; ch < nch; ch++) {
        if (ch + 1 < nch) { load_chunk(ch + 1); CP_WAIT1(); }
        else               { CP_WAIT0(); }
        __syncthreads();
        uint32_t base = sb + (uint32_t)(ch & 1) * STG;
        #pragma unroll
        for (int ks = 0; ks < 4; ks++) {
            uint32_t ah[2][4], al[2][4], bh[8], bl[8];
            #pragma unroll
            for (int mt = 0; mt < 2; mt++) {
                int row = wm * 32 + mt * 16 + (lane & 7) + ((lane >> 3) & 1) * 8;
                int koff = ks * 32 + (lane >> 4) * 16;
                uint32_t sw = swz((uint32_t)(row * 128 + koff));
                ldm4(ah[mt], base + O_AH + sw);
                if (!H16) ldm4(al[mt], base + O_AL + sw);
            }
            #pragma unroll
            for (int half = 0; half < 2; half++) {
                int g = lane >> 3;
                int n = wn * 32 + half * 16 + (g >> 1) * 8 + (lane & 7);
                int koff = ks * 32 + (g & 1) * 16;
                uint32_t sw = swz((uint32_t)(n * 128 + koff));
                ldm4(bh + half * 4, base + O_BH + sw);
                if (!H16) ldm4(bl + half * 4, base + O_BL + sw);
            }
            #pragma unroll
            for (int mt = 0; mt < 2; mt++)
                #pragma unroll
                for (int nt = 0; nt < 4; nt++) {
                    if (H16) {
                        mma_f16(acc[mt][nt], ah[mt], bh + nt * 2);
                    } else {
                        mma_bf16(acc[mt][nt], ah[mt], bh + nt * 2);
                        mma_bf16(acc[mt][nt], ah[mt], bl + nt * 2);
                        mma_bf16(acc[mt][nt], al[mt], bh + nt * 2);
                    }
                }
        }
        __syncthreads();
    }

    float* cp = part + ((size_t)blockIdx.z * gridDim.y + blockIdx.y) * (NN * 64);
    #pragma unroll
    for (int mt = 0; mt < 2; mt++)
        #pragma unroll
        for (int nt = 0; nt < 4; nt++) {
            int row = m0 + wm * 32 + mt * 16 + (lane >> 2);
            int col = wn * 32 + nt * 8 + (lane & 3) * 2;
            *(float2*)&cp[(size_t)row * 64 + col] =
                make_float2(acc[mt][nt][0], acc[mt][nt][1]);
            *(float2*)&cp[(size_t)(row + 8) * 64 + col] =
                make_float2(acc[mt][nt][2], acc[mt][nt][3]);
        }
}

// ---------------- fp32 -> bf16 pair planes (big matrices) ----------------
__global__ void cpair(const float4* __restrict__ in, __nv_bfloat16* __restrict__ hi,
                      __nv_bfloat16* __restrict__ lo) {
    size_t n4 = (size_t)NN * NN / 4;
    for (size_t i = (size_t)blockIdx.x * 256 + threadIdx.x; i < n4;
         i += (size_t)gridDim.x * 256) {
        float4 v = in[i];
        __nv_bfloat16 h0 = __float2bfloat16_rn(v.x);
        __nv_bfloat16 h1 = __float2bfloat16_rn(v.y);
        __nv_bfloat16 h2 = __float2bfloat16_rn(v.z);
        __nv_bfloat16 h3 = __float2bfloat16_rn(v.w);
        __nv_bfloat162* H = (__nv_bfloat162*)hi;
        __nv_bfloat162* L = (__nv_bfloat162*)lo;
        H[2 * i]     = __nv_bfloat162(h0, h1);
        H[2 * i + 1] = __nv_bfloat162(h2, h3);
        L[2 * i]     = __nv_bfloat162(__float2bfloat16_rn(v.x - __bfloat162float(h0)),
                                      __float2bfloat16_rn(v.y - __bfloat162float(h1)));
        L[2 * i + 1] = __nv_bfloat162(__float2bfloat16_rn(v.z - __bfloat162float(h2)),
                                      __float2bfloat16_rn(v.w - __bfloat162float(h3)));
    }
}

// ---------------- prep: h = A@B, f1/f2, coalesced transposed planes ----------------
// H16=true: single fp16 plane (attention h); H16=false: bf16 pair planes (tail u)
template<int K, int NC, bool FV, bool H16>
__global__ void prep(const float* __restrict__ A, const float* __restrict__ B, int bStr,
                     const float* __restrict__ av, int aStr,
                     void* __restrict__ phiV, void* __restrict__ ploV,
                     float* __restrict__ f1, float* __restrict__ f2) {
    constexpr int NOUT = 16 * NC / 256;
    __shared__ float As[16 * 64];
    __shared__ float Bs[64 * NC];
    __shared__ float to[16 * 68];
    size_t z = blockIdx.y;
    const float* Bh = B + z * (size_t)bStr;
    int tid = threadIdx.x;
    int col = tid % NC, rgrp = tid / NC;
    int row0 = blockIdx.x * 16;
    float acc[NOUT];
    #pragma unroll
    for (int i = 0; i < NOUT; i++) acc[i] = 0.f;

    for (int kc = 0; kc < K; kc += 64) {
        for (int e = tid; e < 64 * NC; e += 256)
            Bs[e] = Bh[(size_t)(kc + e / NC) * NC + (e % NC)];
        for (int e = tid; e < 16 * 64; e += 256)
            As[e] = A[(size_t)(row0 + (e >> 6)) * K + kc + (e & 63)];
        __syncthreads();
        #pragma unroll 16
        for (int k = 0; k < 64; k++) {
            float bv = Bs[k * NC + col];
            #pragma unroll
            for (int i = 0; i < NOUT; i++)
                acc[i] += As[(rgrp * NOUT + i) * 64 + k] * bv;
        }
        __syncthreads();
    }
    #pragma unroll
    for (int i = 0; i < NOUT; i++)
        to[(rgrp * NOUT + i) * 68 + col] = acc[i];
    __syncthreads();

    {
        int pcol = tid >> 2, q = tid & 3;
        size_t off = z * (size_t)64 * NN + (size_t)pcol * NN + row0 + q * 4;
        if (H16) {
            __half* phi = (__half*)phiV;
            __half hv[4];
            #pragma unroll
            for (int i = 0; i < 4; i++) {
                float v = (pcol < NC) ? to[(q * 4 + i) * 68 + pcol] : 0.f;
                hv[i] = __float2half_rn(v);
            }
            *(__half2*)&phi[off]     = __halves2half2(hv[0], hv[1]);
            *(__half2*)&phi[off + 2] = __halves2half2(hv[2], hv[3]);
        } else {
            __nv_bfloat16* phi = (__nv_bfloat16*)phiV;
            __nv_bfloat16* plo = (__nv_bfloat16*)ploV;
            __nv_bfloat16 hv[4], lv[4];
            #pragma unroll
            for (int i = 0; i < 4; i++) {
                float v = (pcol < NC) ? to[(q * 4 + i) * 68 + pcol] : 0.f;
                hv[i] = __float2bfloat16_rn(v);
                lv[i] = __float2bfloat16_rn(v - __bfloat162float(hv[i]));
            }
            *(__nv_bfloat162*)&phi[off]     = __nv_bfloat162(hv[0], hv[1]);
            *(__nv_bfloat162*)&phi[off + 2] = __nv_bfloat162(hv[2], hv[3]);
            *(__nv_bfloat162*)&plo[off]     = __nv_bfloat162(lv[0], lv[1]);
            *(__nv_bfloat162*)&plo[off + 2] = __nv_bfloat162(lv[2], lv[3]);
        }
    }

    if (FV) {
        const float* az = av + z * (size_t)aStr;
        int w = tid >> 5, lane = tid & 31;
        #pragma unroll
        for (int rr = 0; rr < 2; rr++) {
            int r = w * 2 + rr;
            float h0 = to[r * 68 + lane], h1 = to[r * 68 + lane + 32];
            float v1 = h0 * az[lane] + h1 * az[lane + 32];
            float v2 = h0 * az[64 + lane] + h1 * az[96 + lane];
            #pragma unroll
            for (int o = 16; o; o >>= 1) {
                v1 += __shfl_down_sync(0xffffffffu, v1, o);
                v2 += __shfl_down_sync(0xffffffffu, v2, o);
            }
            if (lane == 0) {
                f1[z * NN + row0 + r] = v1;
                f2[z * NN + row0 + r] = v2;
            }
        }
    }
}

// ---------------- radix sort: 2x8-bit passes over top-16 key bits + fused search ----------------
// keys equal in top 16 bits stay unordered; boundary error ~1e-5 in S — negligible.
#define RDXS (16384 + 16384 + 8192 + 8192 + 65536 + 4096 + 1024)

__global__ void __launch_bounds__(1024, 1) sortk(
        const float* __restrict__ f1, const float* __restrict__ f2g,
        float* __restrict__ f1s, int* __restrict__ piout, float2* __restrict__ pk) {
    extern __shared__ char rs[];
    uint32_t* keyA = (uint32_t*)rs;
    uint32_t* keyB = (uint32_t*)(rs + 16384);
    uint16_t* valA = (uint16_t*)(rs + 32768);
    uint16_t* valB = (uint16_t*)(rs + 40960);
    uint16_t* cnt  = (uint16_t*)(rs + 49152);
    uint32_t* psum = (uint32_t*)(rs + 49152 + 65536);
    uint32_t* ebase = psum + 1024;
    __shared__ uint32_t wsum[8];

    int tid = threadIdx.x;
    int lane = tid & 31, wid = tid >> 5;
    size_t hz = blockIdx.x;
    const float* src = f1 + hz * NN;

    for (int i = tid; i < NN; i += 1024) {
        uint32_t b = __float_as_uint(src[i]);
        keyA[i] = b ^ ((b & 0x80000000u) ? 0xFFFFFFFFu : 0x80000000u);
        valA[i] = (uint16_t)i;
    }
    __syncthreads();

    uint32_t* KA = keyA; uint32_t* KB = keyB;
    uint16_t* VA = valA; uint16_t* VB = valB;
    int dg = tid & 255, q = tid >> 8;

    #pragma unroll
    for (int shift = 16; shift < 32; shift += 8) {
        uint32_t k[4], d[4]; uint16_t v[4];
        #pragma unroll
        for (int s = 0; s < 4; s++) {
            k[s] = KA[s * 1024 + tid];
            v[s] = VA[s * 1024 + tid];
            d[s] = (k[s] >> shift) & 255u;
        }
        uint32_t* cz = (uint32_t*)cnt;
        #pragma unroll
        for (int i = 0; i < 16; i++) cz[i * 1024 + tid] = 0;
        __syncthreads();
        #pragma unroll
        for (int s = 0; s < 4; s++) {
            uint32_t mask = __match_any_sync(0xffffffffu, d[s]);
            if ((mask & ((1u << lane) - 1)) == 0)
                cnt[(s * 32 + wid) * 256 + d[s]] = (uint16_t)__popc(mask);
        }
        __syncthreads();
        {
            uint32_t part_ = 0;
            #pragma unroll
            for (int g = 0; g < 32; g++)
                part_ += (uint32_t)cnt[(q * 32 + g) * 256 + dg];
            psum[q * 256 + dg] = part_;
        }
        __syncthreads();
        uint32_t tot = 0, inc = 0;
        if (tid < 256) {
            tot = psum[tid] + psum[256 + tid] + psum[512 + tid] + psum[768 + tid];
            inc = tot;
            #pragma unroll
            for (int o = 1; o < 32; o <<= 1) {
                uint32_t t = __shfl_up_sync(0xffffffffu, inc, o);
                if (lane >= o) inc += t;
            }
            if (lane == 31) wsum[wid] = inc;
        }
        __syncthreads();
        if (tid < 256) {
            uint32_t off = 0;
            #pragma unroll
            for (int w = 0; w < 8; w++) if (w < wid) off += wsum[w];
            ebase[tid] = off + inc - tot;
        }
        __syncthreads();
        {
            uint32_t run = ebase[dg];
            #pragma unroll
            for (int qq = 0; qq < 3; qq++) if (qq < q) run += psum[qq * 256 + dg];
            #pragma unroll
            for (int b8 = 0; b8 < 4; b8++) {
                uint32_t c[8];
                #pragma unroll
                for (int g = 0; g < 8; g++)
                    c[g] = cnt[(q * 32 + b8 * 8 + g) * 256 + dg];
                #pragma unroll
                for (int g = 0; g < 8; g++) {
                    cnt[(q * 32 + b8 * 8 + g) * 256 + dg] = (uint16_t)run;
                    run += c[g];
                }
            }
        }
        __syncthreads();
        #pragma unroll
        for (int s = 0; s < 4; s++) {
            uint32_t mask = __match_any_sync(0xffffffffu, d[s]);
            uint32_t rank = __popc(mask & ((1u << lane) - 1));
            uint32_t pos = (uint32_t)cnt[(s * 32 + wid) * 256 + d[s]] + rank;
            KB[pos] = k[s];
            VB[pos] = v[s];
        }
        __syncthreads();
        uint32_t* tk = KA; KA = KB; KB = tk;
        uint16_t* tv = VA; VA = VB; VB = tv;
    }
    float* dk = f1s + hz * NN;
    int* di = piout + hz * NN;
    for (int i = tid; i < NN; i += 1024) {
        uint32_t u = KA[i];
        uint32_t b = (u & 0x80000000u) ? (u ^ 0x80000000u) : ~u;
        dk[i] = __uint_as_float(b);
        di[i] = (int)VA[i];
    }
    // fused tvec: truncated-comparison binary search (consistent with sort order)
    for (int j = tid; j < NN; j += 1024) {
        float f2j = f2g[hz * NN + j];
        uint32_t tb = __float_as_uint(-f2j);
        uint32_t tk16 = (tb ^ ((tb & 0x80000000u) ? 0xFFFFFFFFu : 0x80000000u)) >> 16;
        int lo = 0, hi = NN;
        while (lo < hi) {
            int mid = (lo + hi) >> 1;
            if ((KA[mid] >> 16) <= tk16) lo = mid + 1; else hi = mid;
        }
        int pidx = 16;
        if (lo > 0) pidx = ((lo - 1) >> 4) * 17 + ((lo - 1) & 15);
        pk[hz * NN + j] = make_float2(f2j, __int_as_float(pidx));
    }
}

// ---------------- phase A: all heads per block (internal loop), fp16 W ----------------
#define PASMEM (16896 * 4)

__global__ void phaseA(const float* __restrict__ adj, const int* __restrict__ pi,
                       const float* __restrict__ f1s, const float2* __restrict__ pk,
                       __half* __restrict__ Whi,
                       float* __restrict__ rinv, int nheads) {
    extern __shared__ float sm[];
    float* arow = sm;
    float* sP = sm + 4096;
    float* sQ = sP + 4352;
    float* sS = sQ + 4352;
    __shared__ float wsp[8], wsq[8];

    int i = blockIdx.x, tid = threadIdx.x;
    unsigned lane = tid & 31, wid = tid >> 5;

    const float* Arow = adj + (size_t)i * NN;
    for (int r = tid; r < NN; r += 256) arow[r] = Arow[r];
    if (tid == 0) { sP[16] = 0.f; sQ[16] = 0.f; }
    __syncthreads();

    for (int hz = 0; hz < nheads; hz++) {
        const int* piz = pi + (size_t)hz * NN;
        const float* f1z = f1s + (size_t)hz * NN;
        const float2* pkz = pk + (size_t)hz * NN;

        for (int r = tid; r < NN; r += 256) {
            float a = arow[piz[r]];
            int pr = ((r >> 4) * 17) + (r & 15);
            sP[pr] = a;
            sQ[pr] = a * f1z[r];
        }
        __syncthreads();
        int base = tid * 17;
        float p = 0.f, q = 0.f;
        #pragma unroll
        for (int u = 0; u < 16; u++) {
            p += sP[base + u]; sP[base + u] = p;
            q += sQ[base + u]; sQ[base + u] = q;
        }
        float ip = p, iq = q;
        #pragma unroll
        for (int o = 1; o < 32; o <<= 1) {
            float tp = __shfl_up_sync(0xffffffffu, ip, o);
            float tq = __shfl_up_sync(0xffffffffu, iq, o);
            if (lane >= o) { ip += tp; iq += tq; }
        }
        if (lane == 31) { wsp[wid] = ip; wsq[wid] = iq; }
        __syncthreads();
        float offp = 0.f, offq = 0.f;
        for (int w = 0; w < 8; w++)
            if (w < (int)wid) { offp += wsp[w]; offq += wsq[w]; }
        float ep = offp + ip - p;
        float eq = offq + iq - q;
        #pragma unroll
        for (int u = 0; u < 16; u++) { sP[base + u] += ep; sQ[base + u] += eq; }
        __syncthreads();
        float A0 = sP[255 * 17 + 15];
        float A1 = sQ[255 * 17 + 15];

        float m = -3.0e38f;
        for (int j = tid; j < NN; j += 256) {
            float2 pj = pkz[j];
            float f2j = pj.x;
            int pidx = __float_as_int(pj.y);
            float S = A1 + A0 * f2j - OMA * (sQ[pidx] + f2j * sP[pidx]);
            sS[j] = S;
            m = fmaxf(m, S);
        }
        #pragma unroll
        for (int o = 16; o; o >>= 1) m = fmaxf(m, __shfl_xor_sync(0xffffffffu, m, o));
        __syncthreads();
        if (lane == 0) wsp[wid] = m;
        __syncthreads();
        float mall = wsp[0];
        #pragma unroll
        for (int w = 1; w < 8; w++) mall = fmaxf(mall, wsp[w]);

        float z = 0.f;
        __half2* Wh = (__half2*)(Whi + (size_t)hz * NN * NN + (size_t)i * NN);
        for (int j0 = tid * 2; j0 < NN; j0 += 512) {
            float w0 = __expf(sS[j0] - mall);
            float w1 = __expf(sS[j0 + 1] - mall);
            z += w0 + w1;
            Wh[j0 >> 1] = __halves2half2(__float2half_rn(w0), __float2half_rn(w1));
        }
        #pragma unroll
        for (int o = 16; o; o >>= 1) z += __shfl_xor_sync(0xffffffffu, z, o);
        __syncthreads();
        if (lane == 0) wsq[wid] = z;
        __syncthreads();
        if (tid == 0) {
            float zt = 0.f;
            #pragma unroll
            for (int w = 0; w < 8; w++) zt += wsq[w];
            rinv[(size_t)hz * NN + i] = 1.0f / zt;
        }
        __syncthreads();
    }
}

// ---------------- epilogue: 16-row tiles, coalesced optional bf16 plane emission ----------------
__global__ void epilogue_k(const float* __restrict__ part, int splits,
                           const float* __restrict__ rinv, float* __restrict__ dst,
                           int ldc, int dstHeadOff, int mode,
                           __nv_bfloat16* __restrict__ phi, __nv_bfloat16* __restrict__ plo) {
    __shared__ float to[16 * 68];
    size_t z = blockIdx.y;
    const float* pz = part + z * (size_t)splits * NN * 64;
    int tid = threadIdx.x;
    int col = tid & 63, rg = tid >> 6;
    int row0 = blockIdx.x * 16;
    #pragma unroll
    for (int i = 0; i < 4; i++) {
        int rl = rg * 4 + i;
        int row = row0 + rl;
        int idx = row * 64 + col;
        float v = 0.f;
        for (int s = 0; s < splits; s++) v += pz[(size_t)s * NN * 64 + idx];
        if (rinv) v *= rinv[z * NN + row];
        if (mode == 1) v = fmaxf(v, 0.f);
        else if (mode == 2) v = (v > 0.f) ? v : expm1f(v);
        dst[(size_t)row * ldc + z * dstHeadOff + col] = v;
        to[rl * 68 + col] = v;
    }
    if (phi) {
        __syncthreads();
        int pcol = tid >> 2, q = tid & 3;
        __nv_bfloat16 hv[4], lv[4];
        #pragma unroll
        for (int i = 0; i < 4; i++) {
            float v = to[(q * 4 + i) * 68 + pcol];
            hv[i] = __float2bfloat16_rn(v);
            lv[i] = __float2bfloat16_rn(v - __bfloat162float(hv[i]));
        }
        size_t off = (size_t)pcol * NN + row0 + q * 4;
        *(__nv_bfloat162*)&phi[off]     = __nv_bfloat162(hv[0], hv[1]);
        *(__nv_bfloat162*)&phi[off + 2] = __nv_bfloat162(hv[2], hv[3]);
        *(__nv_bfloat162*)&plo[off]     = __nv_bfloat162(lv[0], lv[1]);
        *(__nv_bfloat162*)&plo[off + 2] = __nv_bfloat162(lv[2], lv[3]);
    }
}

__global__ void epi32(const float* __restrict__ part, float* __restrict__ dst) {
    int idx = blockIdx.x * 256 + threadIdx.x;
    int row = idx >> 5, col = idx & 31;
    float v = 0.f;
    for (int s = 0; s < 8; s++) v += part[(size_t)s * NN * 64 + (size_t)row * 64 + col];
    dst[idx] = v;
}

// ---------------- host orchestration ----------------
struct Bufs {
    uint16_t *Whi, *ahi, *alo, *xhi, *xlo, *bh16, *bhi, *blo;
    float *cat, *x1, *tb, *h1, *part, *f1, *f2, *f1s, *rinv;
    int *pi;
    float2 *pk;
};

static void run_gat_single(const float* adjc, const float* F,
                           const float* Hm, const float* av,
                           float* dst, const Bufs& b, bool planes) {
    prep<256, 64, true, true><<<dim3(NN / 16, 1), 256>>>(F, Hm, 0, av, 0,
                                                         b.bh16, nullptr, b.f1, b.f2);
    sortk<<<1, 1024, RDXS>>>(b.f1, b.f2, b.f1s, b.pi, b.pk);
    phaseA<<<NN, 256, PASMEM>>>(adjc, b.pi, b.f1s, b.pk, (__half*)b.Whi, b.rinv, 1);
    mm_mma<true><<<dim3(32, 8, 1), 256, MMSMEM>>>(b.Whi, nullptr, b.bh16, nullptr,
                                                  b.part, 0, 0);
    epilogue_k<<<dim3(NN / 16, 1), 256>>>(b.part, 8, b.rinv, dst, 64, 0, 2,
                                          planes ? (__nv_bfloat16*)b.bhi : nullptr,
                                          planes ? (__nv_bfloat16*)b.blo : nullptr);
}

static void run_heads(const float* adjc, const float* prev,
                      const float* HmBase, const float* avBase, const Bufs& b) {
    prep<64, 64, true, true><<<dim3(NN / 16, NH), 256>>>(prev, HmBase, 64 * 64,
                                                         avBase, 128,
                                                         b.bh16, nullptr, b.f1, b.f2);
    sortk<<<NH, 1024, RDXS>>>(b.f1, b.f2, b.f1s, b.pi, b.pk);
    phaseA<<<NN, 256, PASMEM>>>(adjc, b.pi, b.f1s, b.pk, (__half*)b.Whi, b.rinv, NH);
    mm_mma<true><<<dim3(32, 2, NH), 256, MMSMEM>>>(b.Whi, nullptr, b.bh16, nullptr,
                                                   b.part, (size_t)NN * NN,
                                                   (size_t)64 * NN);
    epilogue_k<<<dim3(NN / 16, NH), 256>>>(b.part, 2, b.rinv, b.cat, 256, 64, 2,
                                           nullptr, nullptr);
}

extern "C" void kernel_launch(void* const* d_in, const int* in_sizes, int n_in,
                              void* d_out, int out_size) {
    const float* x      = (const float*)d_in[0];
    const float* adj    = (const float*)d_in[1];
    const float* w_init = (const float*)d_in[2];
    const float* head_H = (const float*)d_in[3];
    const float* head_a = (const float*)d_in[4];
    const float* out_H  = (const float*)d_in[5];
    const float* out_a  = (const float*)d_in[6];
    const float* l2_w   = (const float*)d_in[7];
    float* out = (float*)d_out;

    cudaFuncSetAttribute(phaseA, cudaFuncAttributeMaxDynamicSharedMemorySize, PASMEM);
    cudaFuncSetAttribute(mm_mma<true>, cudaFuncAttributeMaxDynamicSharedMemorySize, MMSMEM);
    cudaFuncSetAttribute(mm_mma<false>, cudaFuncAttributeMaxDynamicSharedMemorySize, MMSMEM);
    cudaFuncSetAttribute(sortk, cudaFuncAttributeMaxDynamicSharedMemorySize, RDXS);

    static cudaStream_t s2 = nullptr;
    static cudaEvent_t evF = nullptr, evJ = nullptr;
    if (!s2) {
        cudaStreamCreateWithFlags(&s2, cudaStreamNonBlocking);
        cudaEventCreateWithFlags(&evF, cudaEventDisableTiming);
        cudaEventCreateWithFlags(&evJ, cudaEventDisableTiming);
    }

    Bufs b;
    cudaGetSymbolAddress((void**)&b.Whi, g_Whi);
    cudaGetSymbolAddress((void**)&b.ahi, g_ahi);
    cudaGetSymbolAddress((void**)&b.alo, g_alo);
    cudaGetSymbolAddress((void**)&b.xhi, g_xhi);
    cudaGetSymbolAddress((void**)&b.xlo, g_xlo);
    cudaGetSymbolAddress((void**)&b.bh16, g_bh16);
    cudaGetSymbolAddress((void**)&b.bhi, g_bhi);
    cudaGetSymbolAddress((void**)&b.blo, g_blo);
    cudaGetSymbolAddress((void**)&b.cat, g_cat);
    cudaGetSymbolAddress((void**)&b.x1, g_x1);
    cudaGetSymbolAddress((void**)&b.tb, g_tb);
    cudaGetSymbolAddress((void**)&b.h1, g_h1);
    cudaGetSymbolAddress((void**)&b.part, g_part);
    cudaGetSymbolAddress((void**)&b.f1, g_f1);
    cudaGetSymbolAddress((void**)&b.f2, g_f2);
    cudaGetSymbolAddress((void**)&b.f1s, g_f1s);
    cudaGetSymbolAddress((void**)&b.rinv, g_rinv);
    cudaGetSymbolAddress((void**)&b.pi, g_pi);
    cudaGetSymbolAddress((void**)&b.pk, g_pk);

    // fork: input-only pair conversions overlap with cell-0/1 GAT chain
    cudaEventRecord(evF, 0);
    cudaStreamWaitEvent(s2, evF, 0);
    cpair<<<4096, 256, 0, s2>>>((const float4*)(x + (size_t)NN * NN),
                                (__nv_bfloat16*)b.xhi, (__nv_bfloat16*)b.xlo);
    cpair<<<4096, 256, 0, s2>>>((const float4*)(adj + (size_t)NN * NN),
                                (__nv_bfloat16*)b.ahi, (__nv_bfloat16*)b.alo);
    cudaEventRecord(evJ, s2);

    const float* prev = w_init;
    for (int i = 0; i < 2; i++) {
        const float* adjc = adj + (size_t)i * NN * NN;
        run_heads(adjc, prev, head_H + (size_t)i * NH * 64 * 64,
                  head_a + (size_t)i * NH * 128, b);
        run_gat_single(adjc, b.cat, out_H + (size_t)i * 256 * 64,
                       out_a + (size_t)i * 128, b.x1, b, i == 1);
        prev = b.x1;

        if (i == 1) {
            cudaStreamWaitEvent(0, evJ, 0);
            // tb = x @ x1 (x1 bf16 planes already in bhi/blo); emit tb planes
            mm_mma<false><<<dim3(32, 8, 1), 256, MMSMEM>>>(b.xhi, b.xlo, b.bhi, b.blo,
                                                           b.part, 0, 0);
            epilogue_k<<<dim3(NN / 16, 1), 256>>>(b.part, 8, nullptr, b.tb, 64, 0, 0,
                                                  (__nv_bfloat16*)b.bhi,
                                                  (__nv_bfloat16*)b.blo);
            // h1 = relu(adj @ tb)
            mm_mma<false><<<dim3(32, 8, 1), 256, MMSMEM>>>(b.ahi, b.alo, b.bhi, b.blo,
                                                           b.part, 0, 0);
            epilogue_k<<<dim3(NN / 16, 1), 256>>>(b.part, 8, nullptr, b.h1, 64, 0, 1,
                                                  nullptr, nullptr);
            // u = h1 @ l2_w -> bf16 pair planes (zero-padded to 64)
            prep<64, 32, false, false><<<dim3(NN / 16, 1), 256>>>(
                b.h1, l2_w + (size_t)i * 64 * 32, 0, nullptr, 0,
                b.bhi, b.blo, nullptr, nullptr);
            // out = adj @ u
            mm_mma<false><<<dim3(32, 8, 1), 256, MMSMEM>>>(b.ahi, b.alo, b.bhi, b.blo,
                                                           b.part, 0, 0);
            epi32<<<NN * 32 / 256, 256>>>(b.part, out);
        }
    }
}

// round 15
// speedup vs baseline: 1.3775x; 1.0380x over previous
#include <cuda_runtime.h>
#include <cuda_bf16.h>
#include <cuda_fp16.h>
#include <math.h>
#include <stdint.h>

#define NN 4096
#define DD 64
#define OMA 0.8f   // 1 - alpha(0.2)
#define NH 4

// ---------------- scratch (device globals; allocation-free) ----------------
__device__ __half g_Whi[(size_t)NH * NN * NN];          // attention weights (fp16)
__device__ __nv_bfloat16 g_ahi[(size_t)NN * NN];
__device__ __nv_bfloat16 g_alo[(size_t)NN * NN];
__device__ __nv_bfloat16 g_xhi[(size_t)NN * NN];
__device__ __nv_bfloat16 g_xlo[(size_t)NN * NN];
__device__ __half g_bh16[NH * 64 * NN];                 // h planes (fp16, attention B)
__device__ __nv_bfloat16 g_bhi[64 * NN];                // tail B planes (bf16 pair)
__device__ __nv_bfloat16 g_blo[64 * NN];
__device__ float g_cat[NN * NH * DD];
__device__ float g_x1[NN * DD];
__device__ float g_tb[NN * DD];
__device__ float g_h1[NN * DD];
__device__ float g_part[8 * NN * DD];
__device__ float g_f1[NH * NN], g_f2[NH * NN], g_f1s[NH * NN], g_rinv[NH * NN];
__device__ uint16_t g_pi[NH * NN];    // sorted permutation (fits u16)
__device__ uint16_t g_pidx[NH * NN];  // padded prefix index per j (max 4350)

// ================= portable (sm_80+) PTX helpers =================
__device__ __forceinline__ uint32_t smem_u32(const void* p) {
    uint32_t a;
    asm("{ .reg .u64 t; cvta.to.shared.u64 t, %1; cvt.u32.u64 %0, t; }"
        : "=r"(a) : "l"(p));
    return a;
}

#define CP16(dst, src) \
    asm volatile("cp.async.cg.shared.global [%0], [%1], 16;" :: "r"(dst), "l"(src))
#define CP_COMMIT() asm volatile("cp.async.commit_group;" ::: "memory")
#define CP_WAIT0() asm volatile("cp.async.wait_group 0;" ::: "memory")
#define CP_WAIT1() asm volatile("cp.async.wait_group 1;" ::: "memory")

__device__ __forceinline__ void ldm4(uint32_t* r, uint32_t addr) {
    asm volatile("ldmatrix.sync.aligned.m8n8.x4.shared.b16 {%0,%1,%2,%3}, [%4];"
        : "=r"(r[0]), "=r"(r[1]), "=r"(r[2]), "=r"(r[3]) : "r"(addr));
}

__device__ __forceinline__ void mma_bf16(float* d, const uint32_t* a, const uint32_t* b) {
    asm volatile("mma.sync.aligned.m16n8k16.row.col.f32.bf16.bf16.f32 "
        "{%0,%1,%2,%3}, {%4,%5,%6,%7}, {%8,%9}, {%0,%1,%2,%3};"
        : "+f"(d[0]), "+f"(d[1]), "+f"(d[2]), "+f"(d[3])
        : "r"(a[0]), "r"(a[1]), "r"(a[2]), "r"(a[3]), "r"(b[0]), "r"(b[1]));
}

__device__ __forceinline__ void mma_f16(float* d, const uint32_t* a, const uint32_t* b) {
    asm volatile("mma.sync.aligned.m16n8k16.row.col.f32.f16.f16.f32 "
        "{%0,%1,%2,%3}, {%4,%5,%6,%7}, {%8,%9}, {%0,%1,%2,%3};"
        : "+f"(d[0]), "+f"(d[1]), "+f"(d[2]), "+f"(d[3])
        : "r"(a[0]), "r"(a[1]), "r"(a[2]), "r"(a[3]), "r"(b[0]), "r"(b[1]));
}

__device__ __forceinline__ uint32_t swz(uint32_t bo) { return bo ^ ((bo >> 3) & 0x70); }

// ================= tensor-core big matmul =================
// H16=true : fp16 mma, single A plane x single B plane (attention)
// H16=false: bf16 mma, pair-split (AhBh + AhBl + AlBh) (tail)
#define O_AH 0
#define O_AL 16384
#define O_BH 32768
#define O_BL 40960
#define STG  49152
#define MMSMEM (2 * STG)

template<bool H16>
__global__ void __launch_bounds__(256, 2) mm_mma(
        const uint16_t* __restrict__ Ahi, const uint16_t* __restrict__ Alo,
        const uint16_t* __restrict__ Bhi, const uint16_t* __restrict__ Blo,
        float* __restrict__ part, size_t aStr, size_t bStr) {
    extern __shared__ char smem[];
    uint32_t sb = smem_u32(smem);
    int tid = threadIdx.x, wid = tid >> 5, lane = tid & 31;
    int m0 = blockIdx.x * 128;
    int klen = NN / gridDim.y;
    int kbeg = blockIdx.y * klen;
    int nch = klen / 64;
    int wm = wid >> 1, wn = wid & 1;
    size_t zo = (size_t)blockIdx.z;
    const uint16_t* AhiZ = Ahi + zo * aStr;
    const uint16_t* AloZ = Alo ? Alo + zo * aStr : nullptr;
    const uint16_t* BhiZ = Bhi + zo * bStr;
    const uint16_t* BloZ = Blo ? Blo + zo * bStr : nullptr;

    auto load_chunk = [&](int ch) {
        uint32_t base = sb + (uint32_t)(ch & 1) * STG;
        int kc = kbeg + ch * 64;
        int r = tid >> 3, c = tid & 7;
        uint32_t sw = swz((uint32_t)(r * 128 + c * 16));
        #pragma unroll
        for (int i = 0; i < 4; i++)
            CP16(base + O_AH + sw + (uint32_t)i * 4096,
                 AhiZ + (size_t)(m0 + r + i * 32) * NN + kc + c * 8);
        if (!H16) {
            #pragma unroll
            for (int i = 0; i < 4; i++)
                CP16(base + O_AL + sw + (uint32_t)i * 4096,
                     AloZ + (size_t)(m0 + r + i * 32) * NN + kc + c * 8);
        }
        #pragma unroll
        for (int i = 0; i < 2; i++)
            CP16(base + O_BH + sw + (uint32_t)i * 4096,
                 BhiZ + (size_t)(r + i * 32) * NN + kc + c * 8);
        if (!H16) {
            #pragma unroll
            for (int i = 0; i < 2; i++)
                CP16(base + O_BL + sw + (uint32_t)i * 4096,
                     BloZ + (size_t)(r + i * 32) * NN + kc + c * 8);
        }
        CP_COMMIT();
    };

    float acc[2][4][4] = {};
    load_chunk(0);
    for (int ch = 0; ch < nch; ch++) {
        if (ch + 1 < nch) { load_chunk(ch + 1); CP_WAIT1(); }
        else               { CP_WAIT0(); }
        __syncthreads();
        uint32_t base = sb + (uint32_t)(ch & 1) * STG;
        #pragma unroll
        for (int ks = 0; ks < 4; ks++) {
            uint32_t ah[2][4], al[2][4], bh[8], bl[8];
            #pragma unroll
            for (int mt = 0; mt < 2; mt++) {
                int row = wm * 32 + mt * 16 + (lane & 7) + ((lane >> 3) & 1) * 8;
                int koff = ks * 32 + (lane >> 4) * 16;
                uint32_t sw = swz((uint32_t)(row * 128 + koff));
                ldm4(ah[mt], base + O_AH + sw);
                if (!H16) ldm4(al[mt], base + O_AL + sw);
            }
            #pragma unroll
            for (int half = 0; half < 2; half++) {
                int g = lane >> 3;
                int n = wn * 32 + half * 16 + (g >> 1) * 8 + (lane & 7);
                int koff = ks * 32 + (g & 1) * 16;
                uint32_t sw = swz((uint32_t)(n * 128 + koff));
                ldm4(bh + half * 4, base + O_BH + sw);
                if (!H16) ldm4(bl + half * 4, base + O_BL + sw);
            }
            #pragma unroll
            for (int mt = 0; mt < 2; mt++)
                #pragma unroll
                for (int nt = 0; nt < 4; nt++) {
                    if (H16) {
                        mma_f16(acc[mt][nt], ah[mt], bh + nt * 2);
                    } else {
                        mma_bf16(acc[mt][nt], ah[mt], bh + nt * 2);
                        mma_bf16(acc[mt][nt], ah[mt], bl + nt * 2);
                        mma_bf16(acc[mt][nt], al[mt], bh + nt * 2);
                    }
                }
        }
        __syncthreads();
    }

    float* cp = part + ((size_t)blockIdx.z * gridDim.y + blockIdx.y) * (NN * 64);
    #pragma unroll
    for (int mt = 0; mt < 2; mt++)
        #pragma unroll
        for (int nt = 0; nt < 4; nt++) {
            int row = m0 + wm * 32 + mt * 16 + (lane >> 2);
            int col = wn * 32 + nt * 8 + (lane & 3) * 2;
            *(float2*)&cp[(size_t)row * 64 + col] =
                make_float2(acc[mt][nt][0], acc[mt][nt][1]);
            *(float2*)&cp[(size_t)(row + 8) * 64 + col] =
                make_float2(acc[mt][nt][2], acc[mt][nt][3]);
        }
}

// ---------------- fp32 -> bf16 pair planes (big matrices) ----------------
__global__ void cpair(const float4* __restrict__ in, __nv_bfloat16* __restrict__ hi,
                      __nv_bfloat16* __restrict__ lo) {
    size_t n4 = (size_t)NN * NN / 4;
    for (size_t i = (size_t)blockIdx.x * 256 + threadIdx.x; i < n4;
         i += (size_t)gridDim.x * 256) {
        float4 v = in[i];
        __nv_bfloat16 h0 = __float2bfloat16_rn(v.x);
        __nv_bfloat16 h1 = __float2bfloat16_rn(v.y);
        __nv_bfloat16 h2 = __float2bfloat16_rn(v.z);
        __nv_bfloat16 h3 = __float2bfloat16_rn(v.w);
        __nv_bfloat162* H = (__nv_bfloat162*)hi;
        __nv_bfloat162* L = (__nv_bfloat162*)lo;
        H[2 * i]     = __nv_bfloat162(h0, h1);
        H[2 * i + 1] = __nv_bfloat162(h2, h3);
        L[2 * i]     = __nv_bfloat162(__float2bfloat16_rn(v.x - __bfloat162float(h0)),
                                      __float2bfloat16_rn(v.y - __bfloat162float(h1)));
        L[2 * i + 1] = __nv_bfloat162(__float2bfloat16_rn(v.z - __bfloat162float(h2)),
                                      __float2bfloat16_rn(v.w - __bfloat162float(h3)));
    }
}

// ---------------- prep: h = A@B, f1/f2, coalesced transposed planes ----------------
template<int K, int NC, bool FV, bool H16>
__global__ void prep(const float* __restrict__ A, const float* __restrict__ B, int bStr,
                     const float* __restrict__ av, int aStr,
                     void* __restrict__ phiV, void* __restrict__ ploV,
                     float* __restrict__ f1, float* __restrict__ f2) {
    constexpr int NOUT = 16 * NC / 256;
    __shared__ float As[16 * 64];
    __shared__ float Bs[64 * NC];
    __shared__ float to[16 * 68];
    size_t z = blockIdx.y;
    const float* Bh = B + z * (size_t)bStr;
    int tid = threadIdx.x;
    int col = tid % NC, rgrp = tid / NC;
    int row0 = blockIdx.x * 16;
    float acc[NOUT];
    #pragma unroll
    for (int i = 0; i < NOUT; i++) acc[i] = 0.f;

    for (int kc = 0; kc < K; kc += 64) {
        for (int e = tid; e < 64 * NC; e += 256)
            Bs[e] = Bh[(size_t)(kc + e / NC) * NC + (e % NC)];
        for (int e = tid; e < 16 * 64; e += 256)
            As[e] = A[(size_t)(row0 + (e >> 6)) * K + kc + (e & 63)];
        __syncthreads();
        #pragma unroll 16
        for (int k = 0; k < 64; k++) {
            float bv = Bs[k * NC + col];
            #pragma unroll
            for (int i = 0; i < NOUT; i++)
                acc[i] += As[(rgrp * NOUT + i) * 64 + k] * bv;
        }
        __syncthreads();
    }
    #pragma unroll
    for (int i = 0; i < NOUT; i++)
        to[(rgrp * NOUT + i) * 68 + col] = acc[i];
    __syncthreads();

    {
        int pcol = tid >> 2, q = tid & 3;
        size_t off = z * (size_t)64 * NN + (size_t)pcol * NN + row0 + q * 4;
        if (H16) {
            __half* phi = (__half*)phiV;
            __half hv[4];
            #pragma unroll
            for (int i = 0; i < 4; i++) {
                float v = (pcol < NC) ? to[(q * 4 + i) * 68 + pcol] : 0.f;
                hv[i] = __float2half_rn(v);
            }
            *(__half2*)&phi[off]     = __halves2half2(hv[0], hv[1]);
            *(__half2*)&phi[off + 2] = __halves2half2(hv[2], hv[3]);
        } else {
            __nv_bfloat16* phi = (__nv_bfloat16*)phiV;
            __nv_bfloat16* plo = (__nv_bfloat16*)ploV;
            __nv_bfloat16 hv[4], lv[4];
            #pragma unroll
            for (int i = 0; i < 4; i++) {
                float v = (pcol < NC) ? to[(q * 4 + i) * 68 + pcol] : 0.f;
                hv[i] = __float2bfloat16_rn(v);
                lv[i] = __float2bfloat16_rn(v - __bfloat162float(hv[i]));
            }
            *(__nv_bfloat162*)&phi[off]     = __nv_bfloat162(hv[0], hv[1]);
            *(__nv_bfloat162*)&phi[off + 2] = __nv_bfloat162(hv[2], hv[3]);
            *(__nv_bfloat162*)&plo[off]     = __nv_bfloat162(lv[0], lv[1]);
            *(__nv_bfloat162*)&plo[off + 2] = __nv_bfloat162(lv[2], lv[3]);
        }
    }

    if (FV) {
        const float* az = av + z * (size_t)aStr;
        int w = tid >> 5, lane = tid & 31;
        #pragma unroll
        for (int rr = 0; rr < 2; rr++) {
            int r = w * 2 + rr;
            float h0 = to[r * 68 + lane], h1 = to[r * 68 + lane + 32];
            float v1 = h0 * az[lane] + h1 * az[lane + 32];
            float v2 = h0 * az[64 + lane] + h1 * az[96 + lane];
            #pragma unroll
            for (int o = 16; o; o >>= 1) {
                v1 += __shfl_down_sync(0xffffffffu, v1, o);
                v2 += __shfl_down_sync(0xffffffffu, v2, o);
            }
            if (lane == 0) {
                f1[z * NN + row0 + r] = v1;
                f2[z * NN + row0 + r] = v2;
            }
        }
    }
}

// ---------------- radix sort: 2x8-bit passes over top-16 key bits + fused search ----------------
#define RDXS (16384 + 16384 + 8192 + 8192 + 65536 + 4096 + 1024)

__global__ void __launch_bounds__(1024, 1) sortk(
        const float* __restrict__ f1, const float* __restrict__ f2g,
        float* __restrict__ f1s, uint16_t* __restrict__ piout,
        uint16_t* __restrict__ pidxout) {
    extern __shared__ char rs[];
    uint32_t* keyA = (uint32_t*)rs;
    uint32_t* keyB = (uint32_t*)(rs + 16384);
    uint16_t* valA = (uint16_t*)(rs + 32768);
    uint16_t* valB = (uint16_t*)(rs + 40960);
    uint16_t* cnt  = (uint16_t*)(rs + 49152);
    uint32_t* psum = (uint32_t*)(rs + 49152 + 65536);
    uint32_t* ebase = psum + 1024;
    __shared__ uint32_t wsum[8];

    int tid = threadIdx.x;
    int lane = tid & 31, wid = tid >> 5;
    size_t hz = blockIdx.x;
    const float* src = f1 + hz * NN;

    for (int i = tid; i < NN; i += 1024) {
        uint32_t b = __float_as_uint(src[i]);
        keyA[i] = b ^ ((b & 0x80000000u) ? 0xFFFFFFFFu : 0x80000000u);
        valA[i] = (uint16_t)i;
    }
    __syncthreads();

    uint32_t* KA = keyA; uint32_t* KB = keyB;
    uint16_t* VA = valA; uint16_t* VB = valB;
    int dg = tid & 255, q = tid >> 8;

    #pragma unroll
    for (int shift = 16; shift < 32; shift += 8) {
        uint32_t k[4], d[4]; uint16_t v[4];
        #pragma unroll
        for (int s = 0; s < 4; s++) {
            k[s] = KA[s * 1024 + tid];
            v[s] = VA[s * 1024 + tid];
            d[s] = (k[s] >> shift) & 255u;
        }
        uint32_t* cz = (uint32_t*)cnt;
        #pragma unroll
        for (int i = 0; i < 16; i++) cz[i * 1024 + tid] = 0;
        __syncthreads();
        #pragma unroll
        for (int s = 0; s < 4; s++) {
            uint32_t mask = __match_any_sync(0xffffffffu, d[s]);
            if ((mask & ((1u << lane) - 1)) == 0)
                cnt[(s * 32 + wid) * 256 + d[s]] = (uint16_t)__popc(mask);
        }
        __syncthreads();
        {
            uint32_t part_ = 0;
            #pragma unroll
            for (int g = 0; g < 32; g++)
                part_ += (uint32_t)cnt[(q * 32 + g) * 256 + dg];
            psum[q * 256 + dg] = part_;
        }
        __syncthreads();
        uint32_t tot = 0, inc = 0;
        if (tid < 256) {
            tot = psum[tid] + psum[256 + tid] + psum[512 + tid] + psum[768 + tid];
            inc = tot;
            #pragma unroll
            for (int o = 1; o < 32; o <<= 1) {
                uint32_t t = __shfl_up_sync(0xffffffffu, inc, o);
                if (lane >= o) inc += t;
            }
            if (lane == 31) wsum[wid] = inc;
        }
        __syncthreads();
        if (tid < 256) {
            uint32_t off = 0;
            #pragma unroll
            for (int w = 0; w < 8; w++) if (w < wid) off += wsum[w];
            ebase[tid] = off + inc - tot;
        }
        __syncthreads();
        {
            uint32_t run = ebase[dg];
            #pragma unroll
            for (int qq = 0; qq < 3; qq++) if (qq < q) run += psum[qq * 256 + dg];
            #pragma unroll
            for (int b8 = 0; b8 < 4; b8++) {
                uint32_t c[8];
                #pragma unroll
                for (int g = 0; g < 8; g++)
                    c[g] = cnt[(q * 32 + b8 * 8 + g) * 256 + dg];
                #pragma unroll
                for (int g = 0; g < 8; g++) {
                    cnt[(q * 32 + b8 * 8 + g) * 256 + dg] = (uint16_t)run;
                    run += c[g];
                }
            }
        }
        __syncthreads();
        #pragma unroll
        for (int s = 0; s < 4; s++) {
            uint32_t mask = __match_any_sync(0xffffffffu, d[s]);
            uint32_t rank = __popc(mask & ((1u << lane) - 1));
            uint32_t pos = (uint32_t)cnt[(s * 32 + wid) * 256 + d[s]] + rank;
            KB[pos] = k[s];
            VB[pos] = v[s];
        }
        __syncthreads();
        uint32_t* tk = KA; KA = KB; KB = tk;
        uint16_t* tv = VA; VA = VB; VB = tv;
    }
    float* dk = f1s + hz * NN;
    uint16_t* di = piout + hz * NN;
    for (int i = tid; i < NN; i += 1024) {
        uint32_t u = KA[i];
        uint32_t b = (u & 0x80000000u) ? (u ^ 0x80000000u) : ~u;
        dk[i] = __uint_as_float(b);
        di[i] = VA[i];
    }
    // fused tvec: truncated-comparison binary search (consistent with sort order)
    uint16_t* dp = pidxout + hz * NN;
    for (int j = tid; j < NN; j += 1024) {
        float f2j = f2g[hz * NN + j];
        uint32_t tb = __float_as_uint(-f2j);
        uint32_t tk16 = (tb ^ ((tb & 0x80000000u) ? 0xFFFFFFFFu : 0x80000000u)) >> 16;
        int lo = 0, hi = NN;
        while (lo < hi) {
            int mid = (lo + hi) >> 1;
            if ((KA[mid] >> 16) <= tk16) lo = mid + 1; else hi = mid;
        }
        int pidx = 16;
        if (lo > 0) pidx = ((lo - 1) >> 4) * 17 + ((lo - 1) & 15);
        dp[j] = (uint16_t)pidx;
    }
}

// ---------------- phase A: all heads per block (internal loop), fp16 W ----------------
#define PASMEM (16896 * 4)

__global__ void __launch_bounds__(256, 2) phaseA(
        const float* __restrict__ adj, const uint16_t* __restrict__ pi,
        const float* __restrict__ f1s, const float* __restrict__ f2,
        const uint16_t* __restrict__ pidxg,
        __half* __restrict__ Whi, float* __restrict__ rinv, int nheads) {
    extern __shared__ float sm[];
    float* arow = sm;
    float* sP = sm + 4096;
    float* sQ = sP + 4352;
    float* sS = sQ + 4352;
    __shared__ float wsp[8], wsq[8];

    int i = blockIdx.x, tid = threadIdx.x;
    unsigned lane = tid & 31, wid = tid >> 5;

    const float* Arow = adj + (size_t)i * NN;
    for (int r = tid; r < NN; r += 256) arow[r] = Arow[r];
    if (tid == 0) { sP[16] = 0.f; sQ[16] = 0.f; }
    __syncthreads();

    for (int hz = 0; hz < nheads; hz++) {
        const uint16_t* piz = pi + (size_t)hz * NN;
        const float* f1z = f1s + (size_t)hz * NN;
        const float* f2z = f2 + (size_t)hz * NN;
        const uint16_t* pidxz = pidxg + (size_t)hz * NN;

        for (int r = tid; r < NN; r += 256) {
            float a = arow[piz[r]];
            int pr = ((r >> 4) * 17) + (r & 15);
            sP[pr] = a;
            sQ[pr] = a * f1z[r];
        }
        __syncthreads();
        int base = tid * 17;
        float p = 0.f, q = 0.f;
        #pragma unroll
        for (int u = 0; u < 16; u++) {
            p += sP[base + u]; sP[base + u] = p;
            q += sQ[base + u]; sQ[base + u] = q;
        }
        float ip = p, iq = q;
        #pragma unroll
        for (int o = 1; o < 32; o <<= 1) {
            float tp = __shfl_up_sync(0xffffffffu, ip, o);
            float tq = __shfl_up_sync(0xffffffffu, iq, o);
            if (lane >= o) { ip += tp; iq += tq; }
        }
        if (lane == 31) { wsp[wid] = ip; wsq[wid] = iq; }
        __syncthreads();
        float offp = 0.f, offq = 0.f;
        for (int w = 0; w < 8; w++)
            if (w < (int)wid) { offp += wsp[w]; offq += wsq[w]; }
        float ep = offp + ip - p;
        float eq = offq + iq - q;
        #pragma unroll
        for (int u = 0; u < 16; u++) { sP[base + u] += ep; sQ[base + u] += eq; }
        __syncthreads();
        float A0 = sP[255 * 17 + 15];
        float A1 = sQ[255 * 17 + 15];

        float m = -3.0e38f;
        for (int j = tid; j < NN; j += 256) {
            float f2j = f2z[j];
            int pidx = (int)pidxz[j];
            float S = A1 + A0 * f2j - OMA * (sQ[pidx] + f2j * sP[pidx]);
            sS[j] = S;
            m = fmaxf(m, S);
        }
        #pragma unroll
        for (int o = 16; o; o >>= 1) m = fmaxf(m, __shfl_xor_sync(0xffffffffu, m, o));
        __syncthreads();
        if (lane == 0) wsp[wid] = m;
        __syncthreads();
        float mall = wsp[0];
        #pragma unroll
        for (int w = 1; w < 8; w++) mall = fmaxf(mall, wsp[w]);

        float z = 0.f;
        __half2* Wh = (__half2*)(Whi + (size_t)hz * NN * NN + (size_t)i * NN);
        for (int j0 = tid * 2; j0 < NN; j0 += 512) {
            float w0 = __expf(sS[j0] - mall);
            float w1 = __expf(sS[j0 + 1] - mall);
            z += w0 + w1;
            Wh[j0 >> 1] = __halves2half2(__float2half_rn(w0), __float2half_rn(w1));
        }
        #pragma unroll
        for (int o = 16; o; o >>= 1) z += __shfl_xor_sync(0xffffffffu, z, o);
        __syncthreads();
        if (lane == 0) wsq[wid] = z;
        __syncthreads();
        if (tid == 0) {
            float zt = 0.f;
            #pragma unroll
            for (int w = 0; w < 8; w++) zt += wsq[w];
            rinv[(size_t)hz * NN + i] = 1.0f / zt;
        }
        __syncthreads();
    }
}

// ---------------- epilogue: 16-row tiles, coalesced optional bf16 plane emission ----------------
__global__ void epilogue_k(const float* __restrict__ part, int splits,
                           const float* __restrict__ rinv, float* __restrict__ dst,
                           int ldc, int dstHeadOff, int mode,
                           __nv_bfloat16* __restrict__ phi, __nv_bfloat16* __restrict__ plo) {
    __shared__ float to[16 * 68];
    size_t z = blockIdx.y;
    const float* pz = part + z * (size_t)splits * NN * 64;
    int tid = threadIdx.x;
    int col = tid & 63, rg = tid >> 6;
    int row0 = blockIdx.x * 16;
    #pragma unroll
    for (int i = 0; i < 4; i++) {
        int rl = rg * 4 + i;
        int row = row0 + rl;
        int idx = row * 64 + col;
        float v = 0.f;
        for (int s = 0; s < splits; s++) v += pz[(size_t)s * NN * 64 + idx];
        if (rinv) v *= rinv[z * NN + row];
        if (mode == 1) v = fmaxf(v, 0.f);
        else if (mode == 2) v = (v > 0.f) ? v : expm1f(v);
        dst[(size_t)row * ldc + z * dstHeadOff + col] = v;
        to[rl * 68 + col] = v;
    }
    if (phi) {
        __syncthreads();
        int pcol = tid >> 2, q = tid & 3;
        __nv_bfloat16 hv[4], lv[4];
        #pragma unroll
        for (int i = 0; i < 4; i++) {
            float v = to[(q * 4 + i) * 68 + pcol];
            hv[i] = __float2bfloat16_rn(v);
            lv[i] = __float2bfloat16_rn(v - __bfloat162float(hv[i]));
        }
        size_t off = (size_t)pcol * NN + row0 + q * 4;
        *(__nv_bfloat162*)&phi[off]     = __nv_bfloat162(hv[0], hv[1]);
        *(__nv_bfloat162*)&phi[off + 2] = __nv_bfloat162(hv[2], hv[3]);
        *(__nv_bfloat162*)&plo[off]     = __nv_bfloat162(lv[0], lv[1]);
        *(__nv_bfloat162*)&plo[off + 2] = __nv_bfloat162(lv[2], lv[3]);
    }
}

__global__ void epi32(const float* __restrict__ part, float* __restrict__ dst) {
    int idx = blockIdx.x * 256 + threadIdx.x;
    int row = idx >> 5, col = idx & 31;
    float v = 0.f;
    for (int s = 0; s < 8; s++) v += part[(size_t)s * NN * 64 + (size_t)row * 64 + col];
    dst[idx] = v;
}

// ---------------- host orchestration ----------------
struct Bufs {
    uint16_t *Whi, *ahi, *alo, *xhi, *xlo, *bh16, *bhi, *blo;
    float *cat, *x1, *tb, *h1, *part, *f1, *f2, *f1s, *rinv;
    uint16_t *pi, *pidx;
};

static void run_gat_single(const float* adjc, const float* F,
                           const float* Hm, const float* av,
                           float* dst, const Bufs& b, bool planes) {
    prep<256, 64, true, true><<<dim3(NN / 16, 1), 256>>>(F, Hm, 0, av, 0,
                                                         b.bh16, nullptr, b.f1, b.f2);
    sortk<<<1, 1024, RDXS>>>(b.f1, b.f2, b.f1s, b.pi, b.pidx);
    phaseA<<<NN, 256, PASMEM>>>(adjc, b.pi, b.f1s, b.f2, b.pidx,
                                (__half*)b.Whi, b.rinv, 1);
    mm_mma<true><<<dim3(32, 8, 1), 256, MMSMEM>>>(b.Whi, nullptr, b.bh16, nullptr,
                                                  b.part, 0, 0);
    epilogue_k<<<dim3(NN / 16, 1), 256>>>(b.part, 8, b.rinv, dst, 64, 0, 2,
                                          planes ? (__nv_bfloat16*)b.bhi : nullptr,
                                          planes ? (__nv_bfloat16*)b.blo : nullptr);
}

static void run_heads(const float* adjc, const float* prev,
                      const float* HmBase, const float* avBase, const Bufs& b) {
    prep<64, 64, true, true><<<dim3(NN / 16, NH), 256>>>(prev, HmBase, 64 * 64,
                                                         avBase, 128,
                                                         b.bh16, nullptr, b.f1, b.f2);
    sortk<<<NH, 1024, RDXS>>>(b.f1, b.f2, b.f1s, b.pi, b.pidx);
    phaseA<<<NN, 256, PASMEM>>>(adjc, b.pi, b.f1s, b.f2, b.pidx,
                                (__half*)b.Whi, b.rinv, NH);
    mm_mma<true><<<dim3(32, 2, NH), 256, MMSMEM>>>(b.Whi, nullptr, b.bh16, nullptr,
                                                   b.part, (size_t)NN * NN,
                                                   (size_t)64 * NN);
    epilogue_k<<<dim3(NN / 16, NH), 256>>>(b.part, 2, b.rinv, b.cat, 256, 64, 2,
                                           nullptr, nullptr);
}

extern "C" void kernel_launch(void* const* d_in, const int* in_sizes, int n_in,
                              void* d_out, int out_size) {
    const float* x      = (const float*)d_in[0];
    const float* adj    = (const float*)d_in[1];
    const float* w_init = (const float*)d_in[2];
    const float* head_H = (const float*)d_in[3];
    const float* head_a = (const float*)d_in[4];
    const float* out_H  = (const float*)d_in[5];
    const float* out_a  = (const float*)d_in[6];
    const float* l2_w   = (const float*)d_in[7];
    float* out = (float*)d_out;

    cudaFuncSetAttribute(phaseA, cudaFuncAttributeMaxDynamicSharedMemorySize, PASMEM);
    cudaFuncSetAttribute(mm_mma<true>, cudaFuncAttributeMaxDynamicSharedMemorySize, MMSMEM);
    cudaFuncSetAttribute(mm_mma<false>, cudaFuncAttributeMaxDynamicSharedMemorySize, MMSMEM);
    cudaFuncSetAttribute(sortk, cudaFuncAttributeMaxDynamicSharedMemorySize, RDXS);

    static cudaStream_t s2 = nullptr;
    static cudaEvent_t evF = nullptr, evJ = nullptr;
    if (!s2) {
        cudaStreamCreateWithFlags(&s2, cudaStreamNonBlocking);
        cudaEventCreateWithFlags(&evF, cudaEventDisableTiming);
        cudaEventCreateWithFlags(&evJ, cudaEventDisableTiming);
    }

    Bufs b;
    cudaGetSymbolAddress((void**)&b.Whi, g_Whi);
    cudaGetSymbolAddress((void**)&b.ahi, g_ahi);
    cudaGetSymbolAddress((void**)&b.alo, g_alo);
    cudaGetSymbolAddress((void**)&b.xhi, g_xhi);
    cudaGetSymbolAddress((void**)&b.xlo, g_xlo);
    cudaGetSymbolAddress((void**)&b.bh16, g_bh16);
    cudaGetSymbolAddress((void**)&b.bhi, g_bhi);
    cudaGetSymbolAddress((void**)&b.blo, g_blo);
    cudaGetSymbolAddress((void**)&b.cat, g_cat);
    cudaGetSymbolAddress((void**)&b.x1, g_x1);
    cudaGetSymbolAddress((void**)&b.tb, g_tb);
    cudaGetSymbolAddress((void**)&b.h1, g_h1);
    cudaGetSymbolAddress((void**)&b.part, g_part);
    cudaGetSymbolAddress((void**)&b.f1, g_f1);
    cudaGetSymbolAddress((void**)&b.f2, g_f2);
    cudaGetSymbolAddress((void**)&b.f1s, g_f1s);
    cudaGetSymbolAddress((void**)&b.rinv, g_rinv);
    cudaGetSymbolAddress((void**)&b.pi, g_pi);
    cudaGetSymbolAddress((void**)&b.pidx, g_pidx);

    // fork: input-only pair conversions overlap with cell-0/1 GAT chain
    cudaEventRecord(evF, 0);
    cudaStreamWaitEvent(s2, evF, 0);
    cpair<<<4096, 256, 0, s2>>>((const float4*)(x + (size_t)NN * NN),
                                (__nv_bfloat16*)b.xhi, (__nv_bfloat16*)b.xlo);
    cpair<<<4096, 256, 0, s2>>>((const float4*)(adj + (size_t)NN * NN),
                                (__nv_bfloat16*)b.ahi, (__nv_bfloat16*)b.alo);
    cudaEventRecord(evJ, s2);

    const float* prev = w_init;
    for (int i = 0; i < 2; i++) {
        const float* adjc = adj + (size_t)i * NN * NN;
        run_heads(adjc, prev, head_H + (size_t)i * NH * 64 * 64,
                  head_a + (size_t)i * NH * 128, b);
        run_gat_single(adjc, b.cat, out_H + (size_t)i * 256 * 64,
                       out_a + (size_t)i * 128, b.x1, b, i == 1);
        prev = b.x1;

        if (i == 1) {
            cudaStreamWaitEvent(0, evJ, 0);
            // tb = x @ x1 (x1 bf16 planes already in bhi/blo); emit tb planes
            mm_mma<false><<<dim3(32, 8, 1), 256, MMSMEM>>>(b.xhi, b.xlo, b.bhi, b.blo,
                                                           b.part, 0, 0);
            epilogue_k<<<dim3(NN / 16, 1), 256>>>(b.part, 8, nullptr, b.tb, 64, 0, 0,
                                                  (__nv_bfloat16*)b.bhi,
                                                  (__nv_bfloat16*)b.blo);
            // h1 = relu(adj @ tb)
            mm_mma<false><<<dim3(32, 8, 1), 256, MMSMEM>>>(b.ahi, b.alo, b.bhi, b.blo,
                                                           b.part, 0, 0);
            epilogue_k<<<dim3(NN / 16, 1), 256>>>(b.part, 8, nullptr, b.h1, 64, 0, 1,
                                                  nullptr, nullptr);
            // u = h1 @ l2_w -> bf16 pair planes (zero-padded to 64)
            prep<64, 32, false, false><<<dim3(NN / 16, 1), 256>>>(
                b.h1, l2_w + (size_t)i * 64 * 32, 0, nullptr, 0,
                b.bhi, b.blo, nullptr, nullptr);
            // out = adj @ u
            mm_mma<false><<<dim3(32, 8, 1), 256, MMSMEM>>>(b.ahi, b.alo, b.bhi, b.blo,
                                                           b.part, 0, 0);
            epi32<<<NN * 32 / 256, 256>>>(b.part, out);
        }
    }
}

// round 16
// speedup vs baseline: 1.5320x; 1.1122x over previous
#include <cuda_runtime.h>
#include <cuda_bf16.h>
#include <cuda_fp16.h>
#include <math.h>
#include <stdint.h>

#define NN 4096
#define DD 64
#define OMA 0.8f   // 1 - alpha(0.2)
#define NH 4

// ---------------- scratch (device globals; allocation-free) ----------------
__device__ __half g_Whi[(size_t)NH * NN * NN];          // attention weights (fp16)
__device__ __nv_bfloat16 g_ahi[(size_t)NN * NN];
__device__ __nv_bfloat16 g_alo[(size_t)NN * NN];
__device__ __nv_bfloat16 g_xhi[(size_t)NN * NN];
__device__ __nv_bfloat16 g_xlo[(size_t)NN * NN];
__device__ __half g_bh16[NH * 64 * NN];                 // h planes (fp16, attention B)
__device__ __nv_bfloat16 g_bhi[64 * NN];                // tail B planes (bf16 pair)
__device__ __nv_bfloat16 g_blo[64 * NN];
__device__ float g_cat[NN * NH * DD];
__device__ float g_x1[NN * DD];
__device__ float g_tb[NN * DD];
__device__ float g_h1[NN * DD];
__device__ float g_part[8 * NN * DD];
__device__ float g_f1[NH * NN], g_f2[NH * NN], g_f1s[NH * NN], g_rinv[NH * NN];
__device__ uint16_t g_pi[NH * NN];    // sorted permutation (fits u16)
__device__ uint16_t g_pidx[NH * NN];  // padded prefix index per j
__device__ float4 g_ends[NH];         // (f2min, pidxmin, f2max, pidxmax) per head

// ================= portable (sm_80+) PTX helpers =================
__device__ __forceinline__ uint32_t smem_u32(const void* p) {
    uint32_t a;
    asm("{ .reg .u64 t; cvta.to.shared.u64 t, %1; cvt.u32.u64 %0, t; }"
        : "=r"(a) : "l"(p));
    return a;
}

#define CP16(dst, src) \
    asm volatile("cp.async.cg.shared.global [%0], [%1], 16;" :: "r"(dst), "l"(src))
#define CP_COMMIT() asm volatile("cp.async.commit_group;" ::: "memory")
#define CP_WAIT0() asm volatile("cp.async.wait_group 0;" ::: "memory")
#define CP_WAIT1() asm volatile("cp.async.wait_group 1;" ::: "memory")

__device__ __forceinline__ void ldm4(uint32_t* r, uint32_t addr) {
    asm volatile("ldmatrix.sync.aligned.m8n8.x4.shared.b16 {%0,%1,%2,%3}, [%4];"
        : "=r"(r[0]), "=r"(r[1]), "=r"(r[2]), "=r"(r[3]) : "r"(addr));
}

__device__ __forceinline__ void mma_bf16(float* d, const uint32_t* a, const uint32_t* b) {
    asm volatile("mma.sync.aligned.m16n8k16.row.col.f32.bf16.bf16.f32 "
        "{%0,%1,%2,%3}, {%4,%5,%6,%7}, {%8,%9}, {%0,%1,%2,%3};"
        : "+f"(d[0]), "+f"(d[1]), "+f"(d[2]), "+f"(d[3])
        : "r"(a[0]), "r"(a[1]), "r"(a[2]), "r"(a[3]), "r"(b[0]), "r"(b[1]));
}

__device__ __forceinline__ void mma_f16(float* d, const uint32_t* a, const uint32_t* b) {
    asm volatile("mma.sync.aligned.m16n8k16.row.col.f32.f16.f16.f32 "
        "{%0,%1,%2,%3}, {%4,%5,%6,%7}, {%8,%9}, {%0,%1,%2,%3};"
        : "+f"(d[0]), "+f"(d[1]), "+f"(d[2]), "+f"(d[3])
        : "r"(a[0]), "r"(a[1]), "r"(a[2]), "r"(a[3]), "r"(b[0]), "r"(b[1]));
}

__device__ __forceinline__ uint32_t swz(uint32_t bo) { return bo ^ ((bo >> 3) & 0x70); }

// ================= tensor-core big matmul =================
#define O_AH 0
#define O_AL 16384
#define O_BH 32768
#define O_BL 40960
#define STG  49152
#define MMSMEM (2 * STG)

template<bool H16>
__global__ void __launch_bounds__(256, 2) mm_mma(
        const uint16_t* __restrict__ Ahi, const uint16_t* __restrict__ Alo,
        const uint16_t* __restrict__ Bhi, const uint16_t* __restrict__ Blo,
        float* __restrict__ part, size_t aStr, size_t bStr) {
    extern __shared__ char smem[];
    uint32_t sb = smem_u32(smem);
    int tid = threadIdx.x, wid = tid >> 5, lane = tid & 31;
    int m0 = blockIdx.x * 128;
    int klen = NN / gridDim.y;
    int kbeg = blockIdx.y * klen;
    int nch = klen / 64;
    int wm = wid >> 1, wn = wid & 1;
    size_t zo = (size_t)blockIdx.z;
    const uint16_t* AhiZ = Ahi + zo * aStr;
    const uint16_t* AloZ = Alo ? Alo + zo * aStr : nullptr;
    const uint16_t* BhiZ = Bhi + zo * bStr;
    const uint16_t* BloZ = Blo ? Blo + zo * bStr : nullptr;

    auto load_chunk = [&](int ch) {
        uint32_t base = sb + (uint32_t)(ch & 1) * STG;
        int kc = kbeg + ch * 64;
        int r = tid >> 3, c = tid & 7;
        uint32_t sw = swz((uint32_t)(r * 128 + c * 16));
        #pragma unroll
        for (int i = 0; i < 4; i++)
            CP16(base + O_AH + sw + (uint32_t)i * 4096,
                 AhiZ + (size_t)(m0 + r + i * 32) * NN + kc + c * 8);
        if (!H16) {
            #pragma unroll
            for (int i = 0; i < 4; i++)
                CP16(base + O_AL + sw + (uint32_t)i * 4096,
                     AloZ + (size_t)(m0 + r + i * 32) * NN + kc + c * 8);
        }
        #pragma unroll
        for (int i = 0; i < 2; i++)
            CP16(base + O_BH + sw + (uint32_t)i * 4096,
                 BhiZ + (size_t)(r + i * 32) * NN + kc + c * 8);
        if (!H16) {
            #pragma unroll
            for (int i = 0; i < 2; i++)
                CP16(base + O_BL + sw + (uint32_t)i * 4096,
                     BloZ + (size_t)(r + i * 32) * NN + kc + c * 8);
        }
        CP_COMMIT();
    };

    float acc[2][4][4] = {};
    load_chunk(0);
    for (int ch = 0; ch < nch; ch++) {
        if (ch + 1 < nch) { load_chunk(ch + 1); CP_WAIT1(); }
        else               { CP_WAIT0(); }
        __syncthreads();
        uint32_t base = sb + (uint32_t)(ch & 1) * STG;
        #pragma unroll
        for (int ks = 0; ks < 4; ks++) {
            uint32_t ah[2][4], al[2][4], bh[8], bl[8];
            #pragma unroll
            for (int mt = 0; mt < 2; mt++) {
                int row = wm * 32 + mt * 16 + (lane & 7) + ((lane >> 3) & 1) * 8;
                int koff = ks * 32 + (lane >> 4) * 16;
                uint32_t sw = swz((uint32_t)(row * 128 + koff));
                ldm4(ah[mt], base + O_AH + sw);
                if (!H16) ldm4(al[mt], base + O_AL + sw);
            }
            #pragma unroll
            for (int half = 0; half < 2; half++) {
                int g = lane >> 3;
                int n = wn * 32 + half * 16 + (g >> 1) * 8 + (lane & 7);
                int koff = ks * 32 + (g & 1) * 16;
                uint32_t sw = swz((uint32_t)(n * 128 + koff));
                ldm4(bh + half * 4, base + O_BH + sw);
                if (!H16) ldm4(bl + half * 4, base + O_BL + sw);
            }
            #pragma unroll
            for (int mt = 0; mt < 2; mt++)
                #pragma unroll
                for (int nt = 0; nt < 4; nt++) {
                    if (H16) {
                        mma_f16(acc[mt][nt], ah[mt], bh + nt * 2);
                    } else {
                        mma_bf16(acc[mt][nt], ah[mt], bh + nt * 2);
                        mma_bf16(acc[mt][nt], ah[mt], bl + nt * 2);
                        mma_bf16(acc[mt][nt], al[mt], bh + nt * 2);
                    }
                }
        }
        __syncthreads();
    }

    float* cp = part + ((size_t)blockIdx.z * gridDim.y + blockIdx.y) * (NN * 64);
    #pragma unroll
    for (int mt = 0; mt < 2; mt++)
        #pragma unroll
        for (int nt = 0; nt < 4; nt++) {
            int row = m0 + wm * 32 + mt * 16 + (lane >> 2);
            int col = wn * 32 + nt * 8 + (lane & 3) * 2;
            *(float2*)&cp[(size_t)row * 64 + col] =
                make_float2(acc[mt][nt][0], acc[mt][nt][1]);
            *(float2*)&cp[(size_t)(row + 8) * 64 + col] =
                make_float2(acc[mt][nt][2], acc[mt][nt][3]);
        }
}

// ---------------- fp32 -> bf16 pair planes (big matrices) ----------------
__global__ void cpair(const float4* __restrict__ in, __nv_bfloat16* __restrict__ hi,
                      __nv_bfloat16* __restrict__ lo) {
    size_t n4 = (size_t)NN * NN / 4;
    for (size_t i = (size_t)blockIdx.x * 256 + threadIdx.x; i < n4;
         i += (size_t)gridDim.x * 256) {
        float4 v = in[i];
        __nv_bfloat16 h0 = __float2bfloat16_rn(v.x);
        __nv_bfloat16 h1 = __float2bfloat16_rn(v.y);
        __nv_bfloat16 h2 = __float2bfloat16_rn(v.z);
        __nv_bfloat16 h3 = __float2bfloat16_rn(v.w);
        __nv_bfloat162* H = (__nv_bfloat162*)hi;
        __nv_bfloat162* L = (__nv_bfloat162*)lo;
        H[2 * i]     = __nv_bfloat162(h0, h1);
        H[2 * i + 1] = __nv_bfloat162(h2, h3);
        L[2 * i]     = __nv_bfloat162(__float2bfloat16_rn(v.x - __bfloat162float(h0)),
                                      __float2bfloat16_rn(v.y - __bfloat162float(h1)));
        L[2 * i + 1] = __nv_bfloat162(__float2bfloat16_rn(v.z - __bfloat162float(h2)),
                                      __float2bfloat16_rn(v.w - __bfloat162float(h3)));
    }
}

// ---------------- prep: h = A@B, f1/f2, coalesced transposed planes ----------------
template<int K, int NC, bool FV, bool H16>
__global__ void prep(const float* __restrict__ A, const float* __restrict__ B, int bStr,
                     const float* __restrict__ av, int aStr,
                     void* __restrict__ phiV, void* __restrict__ ploV,
                     float* __restrict__ f1, float* __restrict__ f2) {
    constexpr int NOUT = 16 * NC / 256;
    __shared__ float As[16 * 64];
    __shared__ float Bs[64 * NC];
    __shared__ float to[16 * 68];
    size_t z = blockIdx.y;
    const float* Bh = B + z * (size_t)bStr;
    int tid = threadIdx.x;
    int col = tid % NC, rgrp = tid / NC;
    int row0 = blockIdx.x * 16;
    float acc[NOUT];
    #pragma unroll
    for (int i = 0; i < NOUT; i++) acc[i] = 0.f;

    for (int kc = 0; kc < K; kc += 64) {
        for (int e = tid; e < 64 * NC; e += 256)
            Bs[e] = Bh[(size_t)(kc + e / NC) * NC + (e % NC)];
        for (int e = tid; e < 16 * 64; e += 256)
            As[e] = A[(size_t)(row0 + (e >> 6)) * K + kc + (e & 63)];
        __syncthreads();
        #pragma unroll 16
        for (int k = 0; k < 64; k++) {
            float bv = Bs[k * NC + col];
            #pragma unroll
            for (int i = 0; i < NOUT; i++)
                acc[i] += As[(rgrp * NOUT + i) * 64 + k] * bv;
        }
        __syncthreads();
    }
    #pragma unroll
    for (int i = 0; i < NOUT; i++)
        to[(rgrp * NOUT + i) * 68 + col] = acc[i];
    __syncthreads();

    {
        int pcol = tid >> 2, q = tid & 3;
        size_t off = z * (size_t)64 * NN + (size_t)pcol * NN + row0 + q * 4;
        if (H16) {
            __half* phi = (__half*)phiV;
            __half hv[4];
            #pragma unroll
            for (int i = 0; i < 4; i++) {
                float v = (pcol < NC) ? to[(q * 4 + i) * 68 + pcol] : 0.f;
                hv[i] = __float2half_rn(v);
            }
            *(__half2*)&phi[off]     = __halves2half2(hv[0], hv[1]);
            *(__half2*)&phi[off + 2] = __halves2half2(hv[2], hv[3]);
        } else {
            __nv_bfloat16* phi = (__nv_bfloat16*)phiV;
            __nv_bfloat16* plo = (__nv_bfloat16*)ploV;
            __nv_bfloat16 hv[4], lv[4];
            #pragma unroll
            for (int i = 0; i < 4; i++) {
                float v = (pcol < NC) ? to[(q * 4 + i) * 68 + pcol] : 0.f;
                hv[i] = __float2bfloat16_rn(v);
                lv[i] = __float2bfloat16_rn(v - __bfloat162float(hv[i]));
            }
            *(__nv_bfloat162*)&phi[off]     = __nv_bfloat162(hv[0], hv[1]);
            *(__nv_bfloat162*)&phi[off + 2] = __nv_bfloat162(hv[2], hv[3]);
            *(__nv_bfloat162*)&plo[off]     = __nv_bfloat162(lv[0], lv[1]);
            *(__nv_bfloat162*)&plo[off + 2] = __nv_bfloat162(lv[2], lv[3]);
        }
    }

    if (FV) {
        const float* az = av + z * (size_t)aStr;
        int w = tid >> 5, lane = tid & 31;
        #pragma unroll
        for (int rr = 0; rr < 2; rr++) {
            int r = w * 2 + rr;
            float h0 = to[r * 68 + lane], h1 = to[r * 68 + lane + 32];
            float v1 = h0 * az[lane] + h1 * az[lane + 32];
            float v2 = h0 * az[64 + lane] + h1 * az[96 + lane];
            #pragma unroll
            for (int o = 16; o; o >>= 1) {
                v1 += __shfl_down_sync(0xffffffffu, v1, o);
                v2 += __shfl_down_sync(0xffffffffu, v2, o);
            }
            if (lane == 0) {
                f1[z * NN + row0 + r] = v1;
                f2[z * NN + row0 + r] = v2;
            }
        }
    }
}

// ---------------- radix sort: 2x8-bit passes + fused search + f2 extrema ----------------
#define RDXS (16384 + 16384 + 8192 + 8192 + 65536 + 4096 + 1024)

__global__ void __launch_bounds__(1024, 1) sortk(
        const float* __restrict__ f1, const float* __restrict__ f2g,
        float* __restrict__ f1s, uint16_t* __restrict__ piout,
        uint16_t* __restrict__ pidxout, float4* __restrict__ ends) {
    extern __shared__ char rs[];
    uint32_t* keyA = (uint32_t*)rs;
    uint32_t* keyB = (uint32_t*)(rs + 16384);
    uint16_t* valA = (uint16_t*)(rs + 32768);
    uint16_t* valB = (uint16_t*)(rs + 40960);
    uint16_t* cnt  = (uint16_t*)(rs + 49152);
    uint32_t* psum = (uint32_t*)(rs + 49152 + 65536);
    uint32_t* ebase = psum + 1024;
    __shared__ uint32_t wsum[8];
    __shared__ float rmn[32], rmx[32];
    __shared__ int rmnp[32], rmxp[32];

    int tid = threadIdx.x;
    int lane = tid & 31, wid = tid >> 5;
    size_t hz = blockIdx.x;
    const float* src = f1 + hz * NN;

    for (int i = tid; i < NN; i += 1024) {
        uint32_t b = __float_as_uint(src[i]);
        keyA[i] = b ^ ((b & 0x80000000u) ? 0xFFFFFFFFu : 0x80000000u);
        valA[i] = (uint16_t)i;
    }
    __syncthreads();

    uint32_t* KA = keyA; uint32_t* KB = keyB;
    uint16_t* VA = valA; uint16_t* VB = valB;
    int dg = tid & 255, q = tid >> 8;

    #pragma unroll
    for (int shift = 16; shift < 32; shift += 8) {
        uint32_t k[4], d[4]; uint16_t v[4];
        #pragma unroll
        for (int s = 0; s < 4; s++) {
            k[s] = KA[s * 1024 + tid];
            v[s] = VA[s * 1024 + tid];
            d[s] = (k[s] >> shift) & 255u;
        }
        uint32_t* cz = (uint32_t*)cnt;
        #pragma unroll
        for (int i = 0; i < 16; i++) cz[i * 1024 + tid] = 0;
        __syncthreads();
        #pragma unroll
        for (int s = 0; s < 4; s++) {
            uint32_t mask = __match_any_sync(0xffffffffu, d[s]);
            if ((mask & ((1u << lane) - 1)) == 0)
                cnt[(s * 32 + wid) * 256 + d[s]] = (uint16_t)__popc(mask);
        }
        __syncthreads();
        {
            uint32_t part_ = 0;
            #pragma unroll
            for (int g = 0; g < 32; g++)
                part_ += (uint32_t)cnt[(q * 32 + g) * 256 + dg];
            psum[q * 256 + dg] = part_;
        }
        __syncthreads();
        uint32_t tot = 0, inc = 0;
        if (tid < 256) {
            tot = psum[tid] + psum[256 + tid] + psum[512 + tid] + psum[768 + tid];
            inc = tot;
            #pragma unroll
            for (int o = 1; o < 32; o <<= 1) {
                uint32_t t = __shfl_up_sync(0xffffffffu, inc, o);
                if (lane >= o) inc += t;
            }
            if (lane == 31) wsum[wid] = inc;
        }
        __syncthreads();
        if (tid < 256) {
            uint32_t off = 0;
            #pragma unroll
            for (int w = 0; w < 8; w++) if (w < wid) off += wsum[w];
            ebase[tid] = off + inc - tot;
        }
        __syncthreads();
        {
            uint32_t run = ebase[dg];
            #pragma unroll
            for (int qq = 0; qq < 3; qq++) if (qq < q) run += psum[qq * 256 + dg];
            #pragma unroll
            for (int b8 = 0; b8 < 4; b8++) {
                uint32_t c[8];
                #pragma unroll
                for (int g = 0; g < 8; g++)
                    c[g] = cnt[(q * 32 + b8 * 8 + g) * 256 + dg];
                #pragma unroll
                for (int g = 0; g < 8; g++) {
                    cnt[(q * 32 + b8 * 8 + g) * 256 + dg] = (uint16_t)run;
                    run += c[g];
                }
            }
        }
        __syncthreads();
        #pragma unroll
        for (int s = 0; s < 4; s++) {
            uint32_t mask = __match_any_sync(0xffffffffu, d[s]);
            uint32_t rank = __popc(mask & ((1u << lane) - 1));
            uint32_t pos = (uint32_t)cnt[(s * 32 + wid) * 256 + d[s]] + rank;
            KB[pos] = k[s];
            VB[pos] = v[s];
        }
        __syncthreads();
        uint32_t* tk = KA; KA = KB; KB = tk;
        uint16_t* tv = VA; VA = VB; VB = tv;
    }
    float* dk = f1s + hz * NN;
    uint16_t* di = piout + hz * NN;
    for (int i = tid; i < NN; i += 1024) {
        uint32_t u = KA[i];
        uint32_t b = (u & 0x80000000u) ? (u ^ 0x80000000u) : ~u;
        dk[i] = __uint_as_float(b);
        di[i] = VA[i];
    }
    // fused tvec + f2 extrema tracking
    uint16_t* dp = pidxout + hz * NN;
    float mnv = 3.0e38f, mxv = -3.0e38f;
    int mnp = 16, mxp = 16;
    for (int j = tid; j < NN; j += 1024) {
        float f2j = f2g[hz * NN + j];
        uint32_t tb = __float_as_uint(-f2j);
        uint32_t tk16 = (tb ^ ((tb & 0x80000000u) ? 0xFFFFFFFFu : 0x80000000u)) >> 16;
        int lo = 0, hi = NN;
        while (lo < hi) {
            int mid = (lo + hi) >> 1;
            if ((KA[mid] >> 16) <= tk16) lo = mid + 1; else hi = mid;
        }
        int pidx = 16;
        if (lo > 0) pidx = ((lo - 1) >> 4) * 17 + ((lo - 1) & 15);
        dp[j] = (uint16_t)pidx;
        if (f2j < mnv) { mnv = f2j; mnp = pidx; }
        if (f2j > mxv) { mxv = f2j; mxp = pidx; }
    }
    #pragma unroll
    for (int o = 16; o; o >>= 1) {
        float tv_ = __shfl_down_sync(0xffffffffu, mnv, o);
        int tp_ = __shfl_down_sync(0xffffffffu, mnp, o);
        if (tv_ < mnv) { mnv = tv_; mnp = tp_; }
        float tv2 = __shfl_down_sync(0xffffffffu, mxv, o);
        int tp2 = __shfl_down_sync(0xffffffffu, mxp, o);
        if (tv2 > mxv) { mxv = tv2; mxp = tp2; }
    }
    if (lane == 0) { rmn[wid] = mnv; rmnp[wid] = mnp; rmx[wid] = mxv; rmxp[wid] = mxp; }
    __syncthreads();
    if (tid == 0) {
        float a = rmn[0], c = rmx[0];
        int ap = rmnp[0], cp_ = rmxp[0];
        #pragma unroll
        for (int w = 1; w < 32; w++) {
            if (rmn[w] < a) { a = rmn[w]; ap = rmnp[w]; }
            if (rmx[w] > c) { c = rmx[w]; cp_ = rmxp[w]; }
        }
        ends[hz] = make_float4(a, __int_as_float(ap), c, __int_as_float(cp_));
    }
}

// ---------------- phase A: single j-pass (convexity rowmax), fp16 W ----------------
#define PASMEM ((4096 + 4352 + 4352) * 4)

__global__ void __launch_bounds__(256, 3) phaseA(
        const float* __restrict__ adj, const uint16_t* __restrict__ pi,
        const float* __restrict__ f1s, const float* __restrict__ f2,
        const uint16_t* __restrict__ pidxg, const float4* __restrict__ ends,
        __half* __restrict__ Whi, float* __restrict__ rinv, int nheads) {
    extern __shared__ float sm[];
    float* arow = sm;
    float* sP = sm + 4096;
    float* sQ = sP + 4352;
    __shared__ float wsp[8], wsq[8];

    int i = blockIdx.x, tid = threadIdx.x;
    unsigned lane = tid & 31, wid = tid >> 5;

    const float* Arow = adj + (size_t)i * NN;
    for (int r = tid; r < NN; r += 256) arow[r] = Arow[r];
    if (tid == 0) { sP[16] = 0.f; sQ[16] = 0.f; }
    __syncthreads();

    for (int hz = 0; hz < nheads; hz++) {
        const uint16_t* piz = pi + (size_t)hz * NN;
        const float* f1z = f1s + (size_t)hz * NN;
        const float* f2z = f2 + (size_t)hz * NN;
        const uint16_t* pidxz = pidxg + (size_t)hz * NN;

        for (int r = tid; r < NN; r += 256) {
            float a = arow[piz[r]];
            int pr = ((r >> 4) * 17) + (r & 15);
            sP[pr] = a;
            sQ[pr] = a * f1z[r];
        }
        __syncthreads();
        int base = tid * 17;
        float p = 0.f, q = 0.f;
        #pragma unroll
        for (int u = 0; u < 16; u++) {
            p += sP[base + u]; sP[base + u] = p;
            q += sQ[base + u]; sQ[base + u] = q;
        }
        float ip = p, iq = q;
        #pragma unroll
        for (int o = 1; o < 32; o <<= 1) {
            float tp = __shfl_up_sync(0xffffffffu, ip, o);
            float tq = __shfl_up_sync(0xffffffffu, iq, o);
            if (lane >= o) { ip += tp; iq += tq; }
        }
        if (lane == 31) { wsp[wid] = ip; wsq[wid] = iq; }
        __syncthreads();
        float offp = 0.f, offq = 0.f;
        for (int w = 0; w < 8; w++)
            if (w < (int)wid) { offp += wsp[w]; offq += wsq[w]; }
        float ep = offp + ip - p;
        float eq = offq + iq - q;
        #pragma unroll
        for (int u = 0; u < 16; u++) { sP[base + u] += ep; sQ[base + u] += eq; }
        __syncthreads();
        float A0 = sP[255 * 17 + 15];
        float A1 = sQ[255 * 17 + 15];

        // row max from endpoints (S convex piecewise-linear in f2)
        float4 e = ends[hz];
        float f2lo = e.x; int plo = __float_as_int(e.y);
        float f2hi = e.z; int phi_ = __float_as_int(e.w);
        float Slo = A1 + A0 * f2lo - OMA * (sQ[plo] + f2lo * sP[plo]);
        float Shi = A1 + A0 * f2hi - OMA * (sQ[phi_] + f2hi * sP[phi_]);
        float mall = fmaxf(Slo, Shi);

        // single fused pass: S -> exp -> z -> W
        float z = 0.f;
        __half2* Wh = (__half2*)(Whi + (size_t)hz * NN * NN + (size_t)i * NN);
        for (int j0 = tid * 2; j0 < NN; j0 += 512) {
            float f20 = f2z[j0], f21 = f2z[j0 + 1];
            int p0 = (int)pidxz[j0], p1 = (int)pidxz[j0 + 1];
            float S0 = A1 + A0 * f20 - OMA * (sQ[p0] + f20 * sP[p0]);
            float S1 = A1 + A0 * f21 - OMA * (sQ[p1] + f21 * sP[p1]);
            float w0 = __expf(S0 - mall);
            float w1 = __expf(S1 - mall);
            z += w0 + w1;
            Wh[j0 >> 1] = __halves2half2(__float2half_rn(w0), __float2half_rn(w1));
        }
        #pragma unroll
        for (int o = 16; o; o >>= 1) z += __shfl_xor_sync(0xffffffffu, z, o);
        __syncthreads();
        if (lane == 0) wsq[wid] = z;
        __syncthreads();
        if (tid == 0) {
            float zt = 0.f;
            #pragma unroll
            for (int w = 0; w < 8; w++) zt += wsq[w];
            rinv[(size_t)hz * NN + i] = 1.0f / zt;
        }
        __syncthreads();
    }
}

// ---------------- epilogue: 16-row tiles, coalesced optional bf16 plane emission ----------------
__global__ void epilogue_k(const float* __restrict__ part, int splits,
                           const float* __restrict__ rinv, float* __restrict__ dst,
                           int ldc, int dstHeadOff, int mode,
                           __nv_bfloat16* __restrict__ phi, __nv_bfloat16* __restrict__ plo) {
    __shared__ float to[16 * 68];
    size_t z = blockIdx.y;
    const float* pz = part + z * (size_t)splits * NN * 64;
    int tid = threadIdx.x;
    int col = tid & 63, rg = tid >> 6;
    int row0 = blockIdx.x * 16;
    #pragma unroll
    for (int i = 0; i < 4; i++) {
        int rl = rg * 4 + i;
        int row = row0 + rl;
        int idx = row * 64 + col;
        float v = 0.f;
        for (int s = 0; s < splits; s++) v += pz[(size_t)s * NN * 64 + idx];
        if (rinv) v *= rinv[z * NN + row];
        if (mode == 1) v = fmaxf(v, 0.f);
        else if (mode == 2) v = (v > 0.f) ? v : expm1f(v);
        dst[(size_t)row * ldc + z * dstHeadOff + col] = v;
        to[rl * 68 + col] = v;
    }
    if (phi) {
        __syncthreads();
        int pcol = tid >> 2, q = tid & 3;
        __nv_bfloat16 hv[4], lv[4];
        #pragma unroll
        for (int i = 0; i < 4; i++) {
            float v = to[(q * 4 + i) * 68 + pcol];
            hv[i] = __float2bfloat16_rn(v);
            lv[i] = __float2bfloat16_rn(v - __bfloat162float(hv[i]));
        }
        size_t off = (size_t)pcol * NN + row0 + q * 4;
        *(__nv_bfloat162*)&phi[off]     = __nv_bfloat162(hv[0], hv[1]);
        *(__nv_bfloat162*)&phi[off + 2] = __nv_bfloat162(hv[2], hv[3]);
        *(__nv_bfloat162*)&plo[off]     = __nv_bfloat162(lv[0], lv[1]);
        *(__nv_bfloat162*)&plo[off + 2] = __nv_bfloat162(lv[2], lv[3]);
    }
}

__global__ void epi32(const float* __restrict__ part, float* __restrict__ dst) {
    int idx = blockIdx.x * 256 + threadIdx.x;
    int row = idx >> 5, col = idx & 31;
    float v = 0.f;
    for (int s = 0; s < 8; s++) v += part[(size_t)s * NN * 64 + (size_t)row * 64 + col];
    dst[idx] = v;
}

// ---------------- host orchestration ----------------
struct Bufs {
    uint16_t *Whi, *ahi, *alo, *xhi, *xlo, *bh16, *bhi, *blo;
    float *cat, *x1, *tb, *h1, *part, *f1, *f2, *f1s, *rinv;
    uint16_t *pi, *pidx;
    float4 *ends;
};

static void run_gat_single(const float* adjc, const float* F,
                           const float* Hm, const float* av,
                           float* dst, const Bufs& b, bool planes) {
    prep<256, 64, true, true><<<dim3(NN / 16, 1), 256>>>(F, Hm, 0, av, 0,
                                                         b.bh16, nullptr, b.f1, b.f2);
    sortk<<<1, 1024, RDXS>>>(b.f1, b.f2, b.f1s, b.pi, b.pidx, b.ends);
    phaseA<<<NN, 256, PASMEM>>>(adjc, b.pi, b.f1s, b.f2, b.pidx, b.ends,
                                (__half*)b.Whi, b.rinv, 1);
    mm_mma<true><<<dim3(32, 8, 1), 256, MMSMEM>>>(b.Whi, nullptr, b.bh16, nullptr,
                                                  b.part, 0, 0);
    epilogue_k<<<dim3(NN / 16, 1), 256>>>(b.part, 8, b.rinv, dst, 64, 0, 2,
                                          planes ? (__nv_bfloat16*)b.bhi : nullptr,
                                          planes ? (__nv_bfloat16*)b.blo : nullptr);
}

static void run_heads(const float* adjc, const float* prev,
                      const float* HmBase, const float* avBase, const Bufs& b) {
    prep<64, 64, true, true><<<dim3(NN / 16, NH), 256>>>(prev, HmBase, 64 * 64,
                                                         avBase, 128,
                                                         b.bh16, nullptr, b.f1, b.f2);
    sortk<<<NH, 1024, RDXS>>>(b.f1, b.f2, b.f1s, b.pi, b.pidx, b.ends);
    phaseA<<<NN, 256, PASMEM>>>(adjc, b.pi, b.f1s, b.f2, b.pidx, b.ends,
                                (__half*)b.Whi, b.rinv, NH);
    mm_mma<true><<<dim3(32, 2, NH), 256, MMSMEM>>>(b.Whi, nullptr, b.bh16, nullptr,
                                                   b.part, (size_t)NN * NN,
                                                   (size_t)64 * NN);
    epilogue_k<<<dim3(NN / 16, NH), 256>>>(b.part, 2, b.rinv, b.cat, 256, 64, 2,
                                           nullptr, nullptr);
}

extern "C" void kernel_launch(void* const* d_in, const int* in_sizes, int n_in,
                              void* d_out, int out_size) {
    const float* x      = (const float*)d_in[0];
    const float* adj    = (const float*)d_in[1];
    const float* w_init = (const float*)d_in[2];
    const float* head_H = (const float*)d_in[3];
    const float* head_a = (const float*)d_in[4];
    const float* out_H  = (const float*)d_in[5];
    const float* out_a  = (const float*)d_in[6];
    const float* l2_w   = (const float*)d_in[7];
    float* out = (float*)d_out;

    cudaFuncSetAttribute(phaseA, cudaFuncAttributeMaxDynamicSharedMemorySize, PASMEM);
    cudaFuncSetAttribute(mm_mma<true>, cudaFuncAttributeMaxDynamicSharedMemorySize, MMSMEM);
    cudaFuncSetAttribute(mm_mma<false>, cudaFuncAttributeMaxDynamicSharedMemorySize, MMSMEM);
    cudaFuncSetAttribute(sortk, cudaFuncAttributeMaxDynamicSharedMemorySize, RDXS);

    static cudaStream_t s2 = nullptr;
    static cudaEvent_t evF = nullptr, evJ = nullptr;
    if (!s2) {
        cudaStreamCreateWithFlags(&s2, cudaStreamNonBlocking);
        cudaEventCreateWithFlags(&evF, cudaEventDisableTiming);
        cudaEventCreateWithFlags(&evJ, cudaEventDisableTiming);
    }

    Bufs b;
    cudaGetSymbolAddress((void**)&b.Whi, g_Whi);
    cudaGetSymbolAddress((void**)&b.ahi, g_ahi);
    cudaGetSymbolAddress((void**)&b.alo, g_alo);
    cudaGetSymbolAddress((void**)&b.xhi, g_xhi);
    cudaGetSymbolAddress((void**)&b.xlo, g_xlo);
    cudaGetSymbolAddress((void**)&b.bh16, g_bh16);
    cudaGetSymbolAddress((void**)&b.bhi, g_bhi);
    cudaGetSymbolAddress((void**)&b.blo, g_blo);
    cudaGetSymbolAddress((void**)&b.cat, g_cat);
    cudaGetSymbolAddress((void**)&b.x1, g_x1);
    cudaGetSymbolAddress((void**)&b.tb, g_tb);
    cudaGetSymbolAddress((void**)&b.h1, g_h1);
    cudaGetSymbolAddress((void**)&b.part, g_part);
    cudaGetSymbolAddress((void**)&b.f1, g_f1);
    cudaGetSymbolAddress((void**)&b.f2, g_f2);
    cudaGetSymbolAddress((void**)&b.f1s, g_f1s);
    cudaGetSymbolAddress((void**)&b.rinv, g_rinv);
    cudaGetSymbolAddress((void**)&b.pi, g_pi);
    cudaGetSymbolAddress((void**)&b.pidx, g_pidx);
    cudaGetSymbolAddress((void**)&b.ends, g_ends);

    // fork: input-only pair conversions overlap with cell-0/1 GAT chain
    cudaEventRecord(evF, 0);
    cudaStreamWaitEvent(s2, evF, 0);
    cpair<<<4096, 256, 0, s2>>>((const float4*)(x + (size_t)NN * NN),
                                (__nv_bfloat16*)b.xhi, (__nv_bfloat16*)b.xlo);
    cpair<<<4096, 256, 0, s2>>>((const float4*)(adj + (size_t)NN * NN),
                                (__nv_bfloat16*)b.ahi, (__nv_bfloat16*)b.alo);
    cudaEventRecord(evJ, s2);

    const float* prev = w_init;
    for (int i = 0; i < 2; i++) {
        const float* adjc = adj + (size_t)i * NN * NN;
        run_heads(adjc, prev, head_H + (size_t)i * NH * 64 * 64,
                  head_a + (size_t)i * NH * 128, b);
        run_gat_single(adjc, b.cat, out_H + (size_t)i * 256 * 64,
                       out_a + (size_t)i * 128, b.x1, b, i == 1);
        prev = b.x1;

        if (i == 1) {
            cudaStreamWaitEvent(0, evJ, 0);
            // tb = x @ x1 (x1 bf16 planes already in bhi/blo); emit tb planes
            mm_mma<false><<<dim3(32, 8, 1), 256, MMSMEM>>>(b.xhi, b.xlo, b.bhi, b.blo,
                                                           b.part, 0, 0);
            epilogue_k<<<dim3(NN / 16, 1), 256>>>(b.part, 8, nullptr, b.tb, 64, 0, 0,
                                                  (__nv_bfloat16*)b.bhi,
                                                  (__nv_bfloat16*)b.blo);
            // h1 = relu(adj @ tb)
            mm_mma<false><<<dim3(32, 8, 1), 256, MMSMEM>>>(b.ahi, b.alo, b.bhi, b.blo,
                                                           b.part, 0, 0);
            epilogue_k<<<dim3(NN / 16, 1), 256>>>(b.part, 8, nullptr, b.h1, 64, 0, 1,
                                                  nullptr, nullptr);
            // u = h1 @ l2_w -> bf16 pair planes (zero-padded to 64)
            prep<64, 32, false, false><<<dim3(NN / 16, 1), 256>>>(
                b.h1, l2_w + (size_t)i * 64 * 32, 0, nullptr, 0,
                b.bhi, b.blo, nullptr, nullptr);
            // out = adj @ u
            mm_mma<false><<<dim3(32, 8, 1), 256, MMSMEM>>>(b.ahi, b.alo, b.bhi, b.blo,
                                                           b.part, 0, 0);
            epi32<<<NN * 32 / 256, 256>>>(b.part, out);
        }
    }
}

// round 17
// speedup vs baseline: 1.5770x; 1.0294x over previous
#include <cuda_runtime.h>
#include <cuda_bf16.h>
#include <cuda_fp16.h>
#include <math.h>
#include <stdint.h>

#define NN 4096
#define DD 64
#define OMA 0.8f   // 1 - alpha(0.2)
#define NH 4

// ---------------- scratch (device globals; allocation-free) ----------------
__device__ __half g_Whi[(size_t)NH * NN * NN];   // attention weights (fp16)
__device__ __half g_a16[(size_t)NN * NN];        // adj[1] * 4096 (fp16)
__device__ __half g_x16[(size_t)NN * NN];        // x[1] (fp16)
__device__ __half g_bh16[NH * 64 * NN];          // h planes (fp16, attention B)
__device__ __half g_bt16[64 * NN];               // tail B planes (fp16, scaled)
__device__ float g_cat[NN * NH * DD];
__device__ float g_x1[NN * DD];
__device__ float g_h1[NN * DD];
__device__ float g_part[8 * NN * DD];
__device__ float g_f1[NH * NN], g_f2[NH * NN], g_f1s[NH * NN], g_rinv[NH * NN];
__device__ uint16_t g_pi[NH * NN];
__device__ uint16_t g_pidx[NH * NN];
__device__ float4 g_ends[NH];

// ================= portable (sm_80+) PTX helpers =================
__device__ __forceinline__ uint32_t smem_u32(const void* p) {
    uint32_t a;
    asm("{ .reg .u64 t; cvta.to.shared.u64 t, %1; cvt.u32.u64 %0, t; }"
        : "=r"(a) : "l"(p));
    return a;
}

#define CP16(dst, src) \
    asm volatile("cp.async.cg.shared.global [%0], [%1], 16;" :: "r"(dst), "l"(src))
#define CP_COMMIT() asm volatile("cp.async.commit_group;" ::: "memory")
#define CP_WAIT0() asm volatile("cp.async.wait_group 0;" ::: "memory")
#define CP_WAIT1() asm volatile("cp.async.wait_group 1;" ::: "memory")

__device__ __forceinline__ void ldm4(uint32_t* r, uint32_t addr) {
    asm volatile("ldmatrix.sync.aligned.m8n8.x4.shared.b16 {%0,%1,%2,%3}, [%4];"
        : "=r"(r[0]), "=r"(r[1]), "=r"(r[2]), "=r"(r[3]) : "r"(addr));
}

__device__ __forceinline__ void mma_f16(float* d, const uint32_t* a, const uint32_t* b) {
    asm volatile("mma.sync.aligned.m16n8k16.row.col.f32.f16.f16.f32 "
        "{%0,%1,%2,%3}, {%4,%5,%6,%7}, {%8,%9}, {%0,%1,%2,%3};"
        : "+f"(d[0]), "+f"(d[1]), "+f"(d[2]), "+f"(d[3])
        : "r"(a[0]), "r"(a[1]), "r"(a[2]), "r"(a[3]), "r"(b[0]), "r"(b[1]));
}

__device__ __forceinline__ uint32_t swz(uint32_t bo) { return bo ^ ((bo >> 3) & 0x70); }

// ================= unified fp16 tensor-core matmul: part = A @ B^T =================
#define O_A 0
#define O_B 16384
#define STG 24576
#define MMSMEM (2 * STG)

__global__ void __launch_bounds__(256, 2) mm_mma(
        const __half* __restrict__ A, const __half* __restrict__ B,
        float* __restrict__ part, size_t aStr, size_t bStr) {
    extern __shared__ char smem[];
    uint32_t sb = smem_u32(smem);
    int tid = threadIdx.x, wid = tid >> 5, lane = tid & 31;
    int m0 = blockIdx.x * 128;
    int klen = NN / gridDim.y;
    int kbeg = blockIdx.y * klen;
    int nch = klen / 64;
    int wm = wid >> 1, wn = wid & 1;
    size_t zo = (size_t)blockIdx.z;
    const __half* AZ = A + zo * aStr;
    const __half* BZ = B + zo * bStr;

    auto load_chunk = [&](int ch) {
        uint32_t base = sb + (uint32_t)(ch & 1) * STG;
        int kc = kbeg + ch * 64;
        int r = tid >> 3, c = tid & 7;
        uint32_t sw = swz((uint32_t)(r * 128 + c * 16));
        #pragma unroll
        for (int i = 0; i < 4; i++)
            CP16(base + O_A + sw + (uint32_t)i * 4096,
                 AZ + (size_t)(m0 + r + i * 32) * NN + kc + c * 8);
        #pragma unroll
        for (int i = 0; i < 2; i++)
            CP16(base + O_B + sw + (uint32_t)i * 4096,
                 BZ + (size_t)(r + i * 32) * NN + kc + c * 8);
        CP_COMMIT();
    };

    float acc[2][4][4] = {};
    load_chunk(0);
    for (int ch = 0; ch < nch; ch++) {
        if (ch + 1 < nch) { load_chunk(ch + 1); CP_WAIT1(); }
        else               { CP_WAIT0(); }
        __syncthreads();
        uint32_t base = sb + (uint32_t)(ch & 1) * STG;
        #pragma unroll
        for (int ks = 0; ks < 4; ks++) {
            uint32_t ah[2][4], bh[8];
            #pragma unroll
            for (int mt = 0; mt < 2; mt++) {
                int row = wm * 32 + mt * 16 + (lane & 7) + ((lane >> 3) & 1) * 8;
                int koff = ks * 32 + (lane >> 4) * 16;
                uint32_t sw = swz((uint32_t)(row * 128 + koff));
                ldm4(ah[mt], base + O_A + sw);
            }
            #pragma unroll
            for (int half = 0; half < 2; half++) {
                int g = lane >> 3;
                int n = wn * 32 + half * 16 + (g >> 1) * 8 + (lane & 7);
                int koff = ks * 32 + (g & 1) * 16;
                uint32_t sw = swz((uint32_t)(n * 128 + koff));
                ldm4(bh + half * 4, base + O_B + sw);
            }
            #pragma unroll
            for (int mt = 0; mt < 2; mt++)
                #pragma unroll
                for (int nt = 0; nt < 4; nt++)
                    mma_f16(acc[mt][nt], ah[mt], bh + nt * 2);
        }
        __syncthreads();
    }

    float* cp = part + ((size_t)blockIdx.z * gridDim.y + blockIdx.y) * (NN * 64);
    #pragma unroll
    for (int mt = 0; mt < 2; mt++)
        #pragma unroll
        for (int nt = 0; nt < 4; nt++) {
            int row = m0 + wm * 32 + mt * 16 + (lane >> 2);
            int col = wn * 32 + nt * 8 + (lane & 3) * 2;
            *(float2*)&cp[(size_t)row * 64 + col] =
                make_float2(acc[mt][nt][0], acc[mt][nt][1]);
            *(float2*)&cp[(size_t)(row + 8) * 64 + col] =
                make_float2(acc[mt][nt][2], acc[mt][nt][3]);
        }
}

// ---------------- fp32 -> scaled fp16 plane (big matrices) ----------------
__global__ void cconv(const float4* __restrict__ in, __half* __restrict__ out,
                      float scale) {
    size_t n4 = (size_t)NN * NN / 4;
    for (size_t i = (size_t)blockIdx.x * 256 + threadIdx.x; i < n4;
         i += (size_t)gridDim.x * 256) {
        float4 v = in[i];
        __half2* O = (__half2*)out;
        O[2 * i]     = __halves2half2(__float2half_rn(v.x * scale),
                                      __float2half_rn(v.y * scale));
        O[2 * i + 1] = __halves2half2(__float2half_rn(v.z * scale),
                                      __float2half_rn(v.w * scale));
    }
}

// ---------------- prep: h = A@B, f1/f2, coalesced transposed fp16 plane ----------------
template<int K, int NC, bool FV>
__global__ void prep(const float* __restrict__ A, const float* __restrict__ B, int bStr,
                     const float* __restrict__ av, int aStr,
                     __half* __restrict__ phi, float planeScale,
                     float* __restrict__ f1, float* __restrict__ f2) {
    constexpr int NOUT = 16 * NC / 256;
    __shared__ float As[16 * 64];
    __shared__ float Bs[64 * NC];
    __shared__ float to[16 * 68];
    size_t z = blockIdx.y;
    const float* Bh = B + z * (size_t)bStr;
    int tid = threadIdx.x;
    int col = tid % NC, rgrp = tid / NC;
    int row0 = blockIdx.x * 16;
    float acc[NOUT];
    #pragma unroll
    for (int i = 0; i < NOUT; i++) acc[i] = 0.f;

    for (int kc = 0; kc < K; kc += 64) {
        for (int e = tid; e < 64 * NC; e += 256)
            Bs[e] = Bh[(size_t)(kc + e / NC) * NC + (e % NC)];
        for (int e = tid; e < 16 * 64; e += 256)
            As[e] = A[(size_t)(row0 + (e >> 6)) * K + kc + (e & 63)];
        __syncthreads();
        #pragma unroll 16
        for (int k = 0; k < 64; k++) {
            float bv = Bs[k * NC + col];
            #pragma unroll
            for (int i = 0; i < NOUT; i++)
                acc[i] += As[(rgrp * NOUT + i) * 64 + k] * bv;
        }
        __syncthreads();
    }
    #pragma unroll
    for (int i = 0; i < NOUT; i++)
        to[(rgrp * NOUT + i) * 68 + col] = acc[i];
    __syncthreads();

    {
        int pcol = tid >> 2, q = tid & 3;
        size_t off = z * (size_t)64 * NN + (size_t)pcol * NN + row0 + q * 4;
        __half hv[4];
        #pragma unroll
        for (int i = 0; i < 4; i++) {
            float v = (pcol < NC) ? to[(q * 4 + i) * 68 + pcol] * planeScale : 0.f;
            hv[i] = __float2half_rn(v);
        }
        *(__half2*)&phi[off]     = __halves2half2(hv[0], hv[1]);
        *(__half2*)&phi[off + 2] = __halves2half2(hv[2], hv[3]);
    }

    if (FV) {
        const float* az = av + z * (size_t)aStr;
        int w = tid >> 5, lane = tid & 31;
        #pragma unroll
        for (int rr = 0; rr < 2; rr++) {
            int r = w * 2 + rr;
            float h0 = to[r * 68 + lane], h1 = to[r * 68 + lane + 32];
            float v1 = h0 * az[lane] + h1 * az[lane + 32];
            float v2 = h0 * az[64 + lane] + h1 * az[96 + lane];
            #pragma unroll
            for (int o = 16; o; o >>= 1) {
                v1 += __shfl_down_sync(0xffffffffu, v1, o);
                v2 += __shfl_down_sync(0xffffffffu, v2, o);
            }
            if (lane == 0) {
                f1[z * NN + row0 + r] = v1;
                f2[z * NN + row0 + r] = v2;
            }
        }
    }
}

// ---------------- radix sort: 2x8-bit passes + fused search + f2 extrema ----------------
#define RDXS (16384 + 16384 + 8192 + 8192 + 65536 + 4096 + 1024)

__global__ void __launch_bounds__(1024, 1) sortk(
        const float* __restrict__ f1, const float* __restrict__ f2g,
        float* __restrict__ f1s, uint16_t* __restrict__ piout,
        uint16_t* __restrict__ pidxout, float4* __restrict__ ends) {
    extern __shared__ char rs[];
    uint32_t* keyA = (uint32_t*)rs;
    uint32_t* keyB = (uint32_t*)(rs + 16384);
    uint16_t* valA = (uint16_t*)(rs + 32768);
    uint16_t* valB = (uint16_t*)(rs + 40960);
    uint16_t* cnt  = (uint16_t*)(rs + 49152);
    uint32_t* psum = (uint32_t*)(rs + 49152 + 65536);
    uint32_t* ebase = psum + 1024;
    __shared__ uint32_t wsum[8];
    __shared__ float rmn[32], rmx[32];
    __shared__ int rmnp[32], rmxp[32];

    int tid = threadIdx.x;
    int lane = tid & 31, wid = tid >> 5;
    size_t hz = blockIdx.x;
    const float* src = f1 + hz * NN;

    for (int i = tid; i < NN; i += 1024) {
        uint32_t b = __float_as_uint(src[i]);
        keyA[i] = b ^ ((b & 0x80000000u) ? 0xFFFFFFFFu : 0x80000000u);
        valA[i] = (uint16_t)i;
    }
    __syncthreads();

    uint32_t* KA = keyA; uint32_t* KB = keyB;
    uint16_t* VA = valA; uint16_t* VB = valB;
    int dg = tid & 255, q = tid >> 8;

    #pragma unroll
    for (int shift = 16; shift < 32; shift += 8) {
        uint32_t k[4], d[4]; uint16_t v[4];
        #pragma unroll
        for (int s = 0; s < 4; s++) {
            k[s] = KA[s * 1024 + tid];
            v[s] = VA[s * 1024 + tid];
            d[s] = (k[s] >> shift) & 255u;
        }
        uint32_t* cz = (uint32_t*)cnt;
        #pragma unroll
        for (int i = 0; i < 16; i++) cz[i * 1024 + tid] = 0;
        __syncthreads();
        #pragma unroll
        for (int s = 0; s < 4; s++) {
            uint32_t mask = __match_any_sync(0xffffffffu, d[s]);
            if ((mask & ((1u << lane) - 1)) == 0)
                cnt[(s * 32 + wid) * 256 + d[s]] = (uint16_t)__popc(mask);
        }
        __syncthreads();
        {
            uint32_t part_ = 0;
            #pragma unroll
            for (int g = 0; g < 32; g++)
                part_ += (uint32_t)cnt[(q * 32 + g) * 256 + dg];
            psum[q * 256 + dg] = part_;
        }
        __syncthreads();
        uint32_t tot = 0, inc = 0;
        if (tid < 256) {
            tot = psum[tid] + psum[256 + tid] + psum[512 + tid] + psum[768 + tid];
            inc = tot;
            #pragma unroll
            for (int o = 1; o < 32; o <<= 1) {
                uint32_t t = __shfl_up_sync(0xffffffffu, inc, o);
                if (lane >= o) inc += t;
            }
            if (lane == 31) wsum[wid] = inc;
        }
        __syncthreads();
        if (tid < 256) {
            uint32_t off = 0;
            #pragma unroll
            for (int w = 0; w < 8; w++) if (w < wid) off += wsum[w];
            ebase[tid] = off + inc - tot;
        }
        __syncthreads();
        {
            uint32_t run = ebase[dg];
            #pragma unroll
            for (int qq = 0; qq < 3; qq++) if (qq < q) run += psum[qq * 256 + dg];
            #pragma unroll
            for (int b8 = 0; b8 < 4; b8++) {
                uint32_t c[8];
                #pragma unroll
                for (int g = 0; g < 8; g++)
                    c[g] = cnt[(q * 32 + b8 * 8 + g) * 256 + dg];
                #pragma unroll
                for (int g = 0; g < 8; g++) {
                    cnt[(q * 32 + b8 * 8 + g) * 256 + dg] = (uint16_t)run;
                    run += c[g];
                }
            }
        }
        __syncthreads();
        #pragma unroll
        for (int s = 0; s < 4; s++) {
            uint32_t mask = __match_any_sync(0xffffffffu, d[s]);
            uint32_t rank = __popc(mask & ((1u << lane) - 1));
            uint32_t pos = (uint32_t)cnt[(s * 32 + wid) * 256 + d[s]] + rank;
            KB[pos] = k[s];
            VB[pos] = v[s];
        }
        __syncthreads();
        uint32_t* tk = KA; KA = KB; KB = tk;
        uint16_t* tv = VA; VA = VB; VB = tv;
    }
    float* dk = f1s + hz * NN;
    uint16_t* di = piout + hz * NN;
    for (int i = tid; i < NN; i += 1024) {
        uint32_t u = KA[i];
        uint32_t b = (u & 0x80000000u) ? (u ^ 0x80000000u) : ~u;
        dk[i] = __uint_as_float(b);
        di[i] = VA[i];
    }
    uint16_t* dp = pidxout + hz * NN;
    float mnv = 3.0e38f, mxv = -3.0e38f;
    int mnp = 16, mxp = 16;
    for (int j = tid; j < NN; j += 1024) {
        float f2j = f2g[hz * NN + j];
        uint32_t tb = __float_as_uint(-f2j);
        uint32_t tk16 = (tb ^ ((tb & 0x80000000u) ? 0xFFFFFFFFu : 0x80000000u)) >> 16;
        int lo = 0, hi = NN;
        while (lo < hi) {
            int mid = (lo + hi) >> 1;
            if ((KA[mid] >> 16) <= tk16) lo = mid + 1; else hi = mid;
        }
        int pidx = 16;
        if (lo > 0) pidx = ((lo - 1) >> 4) * 17 + ((lo - 1) & 15);
        dp[j] = (uint16_t)pidx;
        if (f2j < mnv) { mnv = f2j; mnp = pidx; }
        if (f2j > mxv) { mxv = f2j; mxp = pidx; }
    }
    #pragma unroll
    for (int o = 16; o; o >>= 1) {
        float tv_ = __shfl_down_sync(0xffffffffu, mnv, o);
        int tp_ = __shfl_down_sync(0xffffffffu, mnp, o);
        if (tv_ < mnv) { mnv = tv_; mnp = tp_; }
        float tv2 = __shfl_down_sync(0xffffffffu, mxv, o);
        int tp2 = __shfl_down_sync(0xffffffffu, mxp, o);
        if (tv2 > mxv) { mxv = tv2; mxp = tp2; }
    }
    if (lane == 0) { rmn[wid] = mnv; rmnp[wid] = mnp; rmx[wid] = mxv; rmxp[wid] = mxp; }
    __syncthreads();
    if (tid == 0) {
        float a = rmn[0], c = rmx[0];
        int ap = rmnp[0], cp_ = rmxp[0];
        #pragma unroll
        for (int w = 1; w < 32; w++) {
            if (rmn[w] < a) { a = rmn[w]; ap = rmnp[w]; }
            if (rmx[w] > c) { c = rmx[w]; cp_ = rmxp[w]; }
        }
        ends[hz] = make_float4(a, __int_as_float(ap), c, __int_as_float(cp_));
    }
}

// ---------------- phase A: single j-pass (convexity rowmax), fp16 W ----------------
#define PASMEM ((4096 + 4352 + 4352) * 4)

__global__ void __launch_bounds__(256, 3) phaseA(
        const float* __restrict__ adj, const uint16_t* __restrict__ pi,
        const float* __restrict__ f1s, const float* __restrict__ f2,
        const uint16_t* __restrict__ pidxg, const float4* __restrict__ ends,
        __half* __restrict__ Whi, float* __restrict__ rinv, int nheads) {
    extern __shared__ float sm[];
    float* arow = sm;
    float* sP = sm + 4096;
    float* sQ = sP + 4352;
    __shared__ float wsp[8], wsq[8];

    int i = blockIdx.x, tid = threadIdx.x;
    unsigned lane = tid & 31, wid = tid >> 5;

    const float* Arow = adj + (size_t)i * NN;
    for (int r = tid; r < NN; r += 256) arow[r] = Arow[r];
    if (tid == 0) { sP[16] = 0.f; sQ[16] = 0.f; }
    __syncthreads();

    for (int hz = 0; hz < nheads; hz++) {
        const uint16_t* piz = pi + (size_t)hz * NN;
        const float* f1z = f1s + (size_t)hz * NN;
        const float* f2z = f2 + (size_t)hz * NN;
        const uint16_t* pidxz = pidxg + (size_t)hz * NN;

        for (int r = tid; r < NN; r += 256) {
            float a = arow[piz[r]];
            int pr = ((r >> 4) * 17) + (r & 15);
            sP[pr] = a;
            sQ[pr] = a * f1z[r];
        }
        __syncthreads();
        int base = tid * 17;
        float p = 0.f, q = 0.f;
        #pragma unroll
        for (int u = 0; u < 16; u++) {
            p += sP[base + u]; sP[base + u] = p;
            q += sQ[base + u]; sQ[base + u] = q;
        }
        float ip = p, iq = q;
        #pragma unroll
        for (int o = 1; o < 32; o <<= 1) {
            float tp = __shfl_up_sync(0xffffffffu, ip, o);
            float tq = __shfl_up_sync(0xffffffffu, iq, o);
            if (lane >= o) { ip += tp; iq += tq; }
        }
        if (lane == 31) { wsp[wid] = ip; wsq[wid] = iq; }
        __syncthreads();
        float offp = 0.f, offq = 0.f;
        for (int w = 0; w < 8; w++)
            if (w < (int)wid) { offp += wsp[w]; offq += wsq[w]; }
        float ep = offp + ip - p;
        float eq = offq + iq - q;
        #pragma unroll
        for (int u = 0; u < 16; u++) { sP[base + u] += ep; sQ[base + u] += eq; }
        __syncthreads();
        float A0 = sP[255 * 17 + 15];
        float A1 = sQ[255 * 17 + 15];

        float4 e = ends[hz];
        float f2lo = e.x; int plo = __float_as_int(e.y);
        float f2hi = e.z; int phi_ = __float_as_int(e.w);
        float Slo = A1 + A0 * f2lo - OMA * (sQ[plo] + f2lo * sP[plo]);
        float Shi = A1 + A0 * f2hi - OMA * (sQ[phi_] + f2hi * sP[phi_]);
        float mall = fmaxf(Slo, Shi);

        float z = 0.f;
        __half2* Wh = (__half2*)(Whi + (size_t)hz * NN * NN + (size_t)i * NN);
        for (int j0 = tid * 2; j0 < NN; j0 += 512) {
            float f20 = f2z[j0], f21 = f2z[j0 + 1];
            int p0 = (int)pidxz[j0], p1 = (int)pidxz[j0 + 1];
            float S0 = A1 + A0 * f20 - OMA * (sQ[p0] + f20 * sP[p0]);
            float S1 = A1 + A0 * f21 - OMA * (sQ[p1] + f21 * sP[p1]);
            float w0 = __expf(S0 - mall);
            float w1 = __expf(S1 - mall);
            z += w0 + w1;
            Wh[j0 >> 1] = __halves2half2(__float2half_rn(w0), __float2half_rn(w1));
        }
        #pragma unroll
        for (int o = 16; o; o >>= 1) z += __shfl_xor_sync(0xffffffffu, z, o);
        __syncthreads();
        if (lane == 0) wsq[wid] = z;
        __syncthreads();
        if (tid == 0) {
            float zt = 0.f;
            #pragma unroll
            for (int w = 0; w < 8; w++) zt += wsq[w];
            rinv[(size_t)hz * NN + i] = 1.0f / zt;
        }
        __syncthreads();
    }
}

// ---------------- epilogue: split-sum, scale, act, optional scaled fp16 plane ----------------
__global__ void epilogue_k(const float* __restrict__ part, int splits,
                           const float* __restrict__ rinv, float* __restrict__ dst,
                           int ldc, int dstHeadOff, int mode, float preScale,
                           __half* __restrict__ phi, float planeScale) {
    __shared__ float to[16 * 68];
    size_t z = blockIdx.y;
    const float* pz = part + z * (size_t)splits * NN * 64;
    int tid = threadIdx.x;
    int col = tid & 63, rg = tid >> 6;
    int row0 = blockIdx.x * 16;
    #pragma unroll
    for (int i = 0; i < 4; i++) {
        int rl = rg * 4 + i;
        int row = row0 + rl;
        int idx = row * 64 + col;
        float v = 0.f;
        for (int s = 0; s < splits; s++) v += pz[(size_t)s * NN * 64 + idx];
        if (rinv) v *= rinv[z * NN + row];
        v *= preScale;
        if (mode == 1) v = fmaxf(v, 0.f);
        else if (mode == 2) v = (v > 0.f) ? v : expm1f(v);
        if (dst) dst[(size_t)row * ldc + z * dstHeadOff + col] = v;
        to[rl * 68 + col] = v;
    }
    if (phi) {
        __syncthreads();
        int pcol = tid >> 2, q = tid & 3;
        __half hv[4];
        #pragma unroll
        for (int i = 0; i < 4; i++)
            hv[i] = __float2half_rn(to[(q * 4 + i) * 68 + pcol] * planeScale);
        size_t off = (size_t)pcol * NN + row0 + q * 4;
        *(__half2*)&phi[off]     = __halves2half2(hv[0], hv[1]);
        *(__half2*)&phi[off + 2] = __halves2half2(hv[2], hv[3]);
    }
}

__global__ void epi32(const float* __restrict__ part, float* __restrict__ dst,
                      float scale) {
    int idx = blockIdx.x * 256 + threadIdx.x;
    int row = idx >> 5, col = idx & 31;
    float v = 0.f;
    for (int s = 0; s < 8; s++) v += part[(size_t)s * NN * 64 + (size_t)row * 64 + col];
    dst[idx] = v * scale;
}

// ---------------- host orchestration ----------------
struct Bufs {
    __half *Whi, *a16, *x16, *bh16, *bt16;
    float *cat, *x1, *h1, *part, *f1, *f2, *f1s, *rinv;
    uint16_t *pi, *pidx;
    float4 *ends;
};

static void run_gat_single(const float* adjc, const float* F,
                           const float* Hm, const float* av,
                           float* dst, const Bufs& b, bool planes) {
    prep<256, 64, true><<<dim3(NN / 16, 1), 256>>>(F, Hm, 0, av, 0,
                                                   b.bh16, 1.f, b.f1, b.f2);
    sortk<<<1, 1024, RDXS>>>(b.f1, b.f2, b.f1s, b.pi, b.pidx, b.ends);
    phaseA<<<NN, 256, PASMEM>>>(adjc, b.pi, b.f1s, b.f2, b.pidx, b.ends,
                                b.Whi, b.rinv, 1);
    mm_mma<<<dim3(32, 8, 1), 256, MMSMEM>>>(b.Whi, b.bh16, b.part, 0, 0);
    epilogue_k<<<dim3(NN / 16, 1), 256>>>(b.part, 8, b.rinv, dst, 64, 0, 2, 1.f,
                                          planes ? b.bt16 : nullptr, 1.f / 16.f);
}

static void run_heads(const float* adjc, const float* prev,
                      const float* HmBase, const float* avBase, const Bufs& b) {
    prep<64, 64, true><<<dim3(NN / 16, NH), 256>>>(prev, HmBase, 64 * 64, avBase, 128,
                                                   b.bh16, 1.f, b.f1, b.f2);
    sortk<<<NH, 1024, RDXS>>>(b.f1, b.f2, b.f1s, b.pi, b.pidx, b.ends);
    phaseA<<<NN, 256, PASMEM>>>(adjc, b.pi, b.f1s, b.f2, b.pidx, b.ends,
                                b.Whi, b.rinv, NH);
    mm_mma<<<dim3(32, 2, NH), 256, MMSMEM>>>(b.Whi, b.bh16, b.part,
                                             (size_t)NN * NN, (size_t)64 * NN);
    epilogue_k<<<dim3(NN / 16, NH), 256>>>(b.part, 2, b.rinv, b.cat, 256, 64, 2, 1.f,
                                           nullptr, 0.f);
}

extern "C" void kernel_launch(void* const* d_in, const int* in_sizes, int n_in,
                              void* d_out, int out_size) {
    const float* x      = (const float*)d_in[0];
    const float* adj    = (const float*)d_in[1];
    const float* w_init = (const float*)d_in[2];
    const float* head_H = (const float*)d_in[3];
    const float* head_a = (const float*)d_in[4];
    const float* out_H  = (const float*)d_in[5];
    const float* out_a  = (const float*)d_in[6];
    const float* l2_w   = (const float*)d_in[7];
    float* out = (float*)d_out;

    cudaFuncSetAttribute(phaseA, cudaFuncAttributeMaxDynamicSharedMemorySize, PASMEM);
    cudaFuncSetAttribute(mm_mma, cudaFuncAttributeMaxDynamicSharedMemorySize, MMSMEM);
    cudaFuncSetAttribute(sortk, cudaFuncAttributeMaxDynamicSharedMemorySize, RDXS);

    static cudaStream_t s2 = nullptr;
    static cudaEvent_t evF = nullptr, evJ = nullptr;
    if (!s2) {
        cudaStreamCreateWithFlags(&s2, cudaStreamNonBlocking);
        cudaEventCreateWithFlags(&evF, cudaEventDisableTiming);
        cudaEventCreateWithFlags(&evJ, cudaEventDisableTiming);
    }

    Bufs b;
    cudaGetSymbolAddress((void**)&b.Whi, g_Whi);
    cudaGetSymbolAddress((void**)&b.a16, g_a16);
    cudaGetSymbolAddress((void**)&b.x16, g_x16);
    cudaGetSymbolAddress((void**)&b.bh16, g_bh16);
    cudaGetSymbolAddress((void**)&b.bt16, g_bt16);
    cudaGetSymbolAddress((void**)&b.cat, g_cat);
    cudaGetSymbolAddress((void**)&b.x1, g_x1);
    cudaGetSymbolAddress((void**)&b.h1, g_h1);
    cudaGetSymbolAddress((void**)&b.part, g_part);
    cudaGetSymbolAddress((void**)&b.f1, g_f1);
    cudaGetSymbolAddress((void**)&b.f2, g_f2);
    cudaGetSymbolAddress((void**)&b.f1s, g_f1s);
    cudaGetSymbolAddress((void**)&b.rinv, g_rinv);
    cudaGetSymbolAddress((void**)&b.pi, g_pi);
    cudaGetSymbolAddress((void**)&b.pidx, g_pidx);
    cudaGetSymbolAddress((void**)&b.ends, g_ends);

    // fork: input-only fp16 conversions overlap with cell-0/1 GAT chain
    // adj scaled by 4096 (exact) to stay in fp16 normal range.
    cudaEventRecord(evF, 0);
    cudaStreamWaitEvent(s2, evF, 0);
    cconv<<<4096, 256, 0, s2>>>((const float4*)(x + (size_t)NN * NN), b.x16, 1.f);
    cconv<<<4096, 256, 0, s2>>>((const float4*)(adj + (size_t)NN * NN), b.a16, 4096.f);
    cudaEventRecord(evJ, s2);

    const float* prev = w_init;
    for (int i = 0; i < 2; i++) {
        const float* adjc = adj + (size_t)i * NN * NN;
        run_heads(adjc, prev, head_H + (size_t)i * NH * 64 * 64,
                  head_a + (size_t)i * NH * 128, b);
        run_gat_single(adjc, b.cat, out_H + (size_t)i * 256 * 64,
                       out_a + (size_t)i * 128, b.x1, b, i == 1);
        prev = b.x1;

        if (i == 1) {
            cudaStreamWaitEvent(0, evJ, 0);
            // tb = x @ x1  (A = x fp16; B = x1/16 plane)  part = tb/16
            mm_mma<<<dim3(32, 8, 1), 256, MMSMEM>>>(b.x16, b.bt16, b.part, 0, 0);
            // v = part*16 = tb; plane = tb/256
            epilogue_k<<<dim3(NN / 16, 1), 256>>>(b.part, 8, nullptr, nullptr, 64, 0,
                                                  0, 16.f, b.bt16, 1.f / 256.f);
            // h1 = relu(adj @ tb): part = (adj*4096)@(tb/256) = (adj@tb)*16
            mm_mma<<<dim3(32, 8, 1), 256, MMSMEM>>>(b.a16, b.bt16, b.part, 0, 0);
            epilogue_k<<<dim3(NN / 16, 1), 256>>>(b.part, 8, nullptr, b.h1, 64, 0,
                                                  1, 1.f / 16.f, nullptr, 0.f);
            // u = h1 @ l2_w (fp32) -> plane = u/256 (zero-padded to 64)
            prep<64, 32, false><<<dim3(NN / 16, 1), 256>>>(
                b.h1, l2_w + (size_t)i * 64 * 32, 0, nullptr, 0,
                b.bt16, 1.f / 256.f, nullptr, nullptr);
            // out = adj @ u: part = (adj*4096)@(u/256) = out*16
            mm_mma<<<dim3(32, 8, 1), 256, MMSMEM>>>(b.a16, b.bt16, b.part, 0, 0);
            epi32<<<NN * 32 / 256, 256>>>(b.part, out, 1.f / 16.f);
        }
    }
}